// round 6
// baseline (speedup 1.0000x reference)
#include <cuda_runtime.h>
#include <math.h>
#include <stdint.h>

#define N_FFT 16000
#define PPOS  1568
#define NSPLIT 6
#define KCHUNK 2672
#define FSPLIT 8

// -------- device scratch (allocation-free rule: __device__ globals) --------
__device__ float g_twr[N_FFT];
__device__ float g_twi[N_FFT];
__device__ float g_txtp[32 * 2048];
__device__ __align__(16) float g_imgt[(size_t)PPOS * 2048];
__device__ __align__(16) float g_Z1[(size_t)PPOS * 2 * N_FFT];
__device__ __align__(16) float g_Y[(size_t)PPOS * N_FFT];
__device__ float g_Cpart[(size_t)NSPLIT * PPOS * 512];
__device__ float g_res[32 * 2048];
__device__ __align__(16) float g_Zb1[(size_t)32 * 2 * N_FFT];
__device__ __align__(16) float g_Yb[(size_t)32 * N_FFT];
__device__ float g_Fpart[(size_t)FSPLIT * 32 * 3000];

__constant__ float W5C[5] = {1.0f, 0.30901699437494742f, -0.80901699437494745f,
                             -0.80901699437494745f, 0.30901699437494742f};
__constant__ float W5S[5] = {0.0f, 0.95105651629515353f, 0.58778525229247314f,
                             -0.58778525229247314f, -0.95105651629515353f};

// -------- twiddles: W_N^k = exp(-2 pi i k / N) --------
__global__ void k_twiddle() {
    int i = blockIdx.x * blockDim.x + threadIdx.x;
    if (i < N_FFT) {
        double th = -2.0 * 3.141592653589793238462643383279502884 * (double)i / (double)N_FFT;
        g_twr[i] = (float)cos(th);
        g_twi[i] = (float)sin(th);
    }
}

// -------- txt avgpool (3,3) s(100,1) p(1,1) count_include_pad -> (32,2048) ----
__global__ void k_txtp(const float* __restrict__ txt) {
    int b = blockIdx.x;
    const float* base = txt + (size_t)b * 50 * 2048;
    for (int j = threadIdx.x; j < 2048; j += blockDim.x) {
        float sum = 0.0f;
        #pragma unroll
        for (int r = 0; r < 2; r++)
            #pragma unroll
            for (int dj = -1; dj <= 1; dj++) {
                int jj = j + dj;
                if (jj >= 0 && jj < 2048) sum += base[r * 2048 + jj];
            }
        g_txtp[b * 2048 + j] = sum * (1.0f / 9.0f);
    }
}

// -------- transpose img NCHW -> rows (b*49+q, c) for coalesced sketch --------
__global__ void k_imgt(const float* __restrict__ img) {
    int p = blockIdx.x;            // b*49+q
    int b = p / 49, q = p - 49 * b;
    const float* ib = img + (size_t)b * 2048 * 49;
    float* op = g_imgt + (size_t)p * 2048;
    for (int c = threadIdx.x; c < 2048; c += blockDim.x)
        op[c] = ib[c * 49 + q];
}

// -------- one mixed-radix stage on smem --------------------------------------
__device__ __forceinline__ void fft_stage(float* re, float* im, int L, int r, int dir,
                                          int tid, int T) {
    int m = L / r;
    int nb = N_FFT / r;
    int step = N_FFT / L;
    if (r == 2) {
        for (int i = tid; i < nb; i += T) {
            int blk = i / m, j = i - blk * m;
            int i0 = blk * L + j, i1 = i0 + m;
            float ar = re[i0], ai = im[i0], br = re[i1], bi = im[i1];
            int idx = j * step;
            float wr = g_twr[idx], wi = g_twi[idx];
            if (dir > 0) {
                float vr = ar - br, vi = ai - bi;
                re[i0] = ar + br;            im[i0] = ai + bi;
                re[i1] = vr * wr - vi * wi;  im[i1] = vr * wi + vi * wr;
            } else {
                float tr = br * wr + bi * wi;   // b * conj(w)
                float ti = bi * wr - br * wi;
                re[i0] = ar + tr; im[i0] = ai + ti;
                re[i1] = ar - tr; im[i1] = ai - ti;
            }
        }
    } else {
        for (int i = tid; i < nb; i += T) {
            int blk = i / m, j = i - blk * m;
            int base = blk * L + j;
            float ur[5], ui[5];
            if (dir > 0) {
                #pragma unroll
                for (int q = 0; q < 5; q++) { ur[q] = re[base + q * m]; ui[q] = im[base + q * m]; }
                #pragma unroll
                for (int q = 0; q < 5; q++) {
                    float vr = 0.0f, vi = 0.0f;
                    #pragma unroll
                    for (int t = 0; t < 5; t++) {
                        int e = (q * t) % 5;
                        float C = W5C[e], S = W5S[e];       // * e^{-i th}
                        vr += ur[t] * C + ui[t] * S;
                        vi += ui[t] * C - ur[t] * S;
                    }
                    if (q) {
                        int idx = j * q * step;
                        float wr = g_twr[idx], wi = g_twi[idx];
                        float t2 = vr * wr - vi * wi;
                        vi = vr * wi + vi * wr; vr = t2;
                    }
                    re[base + q * m] = vr; im[base + q * m] = vi;
                }
            } else {
                #pragma unroll
                for (int q = 0; q < 5; q++) {
                    float a = re[base + q * m], b2 = im[base + q * m];
                    if (q) {
                        int idx = j * q * step;
                        float wr = g_twr[idx], wi = g_twi[idx];  // conj twiddle
                        float t2 = a * wr + b2 * wi;
                        b2 = b2 * wr - a * wi; a = t2;
                    }
                    ur[q] = a; ui[q] = b2;
                }
                #pragma unroll
                for (int t = 0; t < 5; t++) {
                    float vr = 0.0f, vi = 0.0f;
                    #pragma unroll
                    for (int q = 0; q < 5; q++) {
                        int e = (q * t) % 5;
                        float C = W5C[e], S = W5S[e];       // * e^{+i th}
                        vr += ur[q] * C - ui[q] * S;
                        vi += ui[q] * C + ur[q] * S;
                    }
                    re[base + t * m] = vr; im[base + t * m] = vi;
                }
            }
        }
    }
}

// dir>0: DIF forward (scrambled output). dir<0: transposed network
// (consumes scrambled, emits natural order); caller scales by 1/N.
__device__ __forceinline__ void fft16000(float* re, float* im, int dir, int tid, int T) {
    const int rads[10] = {2, 2, 2, 2, 2, 2, 2, 5, 5, 5};
    if (dir > 0) {
        int L = N_FFT;
        #pragma unroll
        for (int s = 0; s < 10; s++) {
            fft_stage(re, im, L, rads[s], 1, tid, T);
            __syncthreads();
            L /= rads[s];
        }
    } else {
        int Ls[10];
        int L = N_FFT;
        #pragma unroll
        for (int s = 0; s < 10; s++) { Ls[s] = L; L /= rads[s]; }
        #pragma unroll
        for (int s = 9; s >= 0; s--) {
            fft_stage(re, im, Ls[s], rads[s], -1, tid, T);
            __syncthreads();
        }
    }
}

// -------- forward: count sketch -> FFT -> store spectrum ---------------------
// mode 0: x[c] = txt_p[b, (49c+q)&2047]  (p=b*49+q);  mode 1: x[c]=src[p*2048+c]
__global__ void k_fwd(const float* __restrict__ src, int mode,
                      const int* __restrict__ h, const int* __restrict__ sg,
                      float* __restrict__ Zout) {
    extern __shared__ float sm[];
    float* re = sm;
    float* im = sm + N_FFT;
    int tid = threadIdx.x, T = blockDim.x, p = blockIdx.x;
    for (int d = tid; d < N_FFT; d += T) { re[d] = 0.0f; im[d] = 0.0f; }
    __syncthreads();
    if (mode == 0) {
        int b = p / 49, q = p - 49 * b;
        const float* tp = src + (size_t)b * 2048;
        for (int c = tid; c < 2048; c += T) {
            float v = tp[(49 * c + q) & 2047];
            v = (sg[c] > 0) ? v : -v;
            atomicAdd(&re[h[c]], v);
        }
    } else {
        const float* x = src + (size_t)p * 2048;
        for (int c = tid; c < 2048; c += T) {
            float v = x[c];
            v = (sg[c] > 0) ? v : -v;
            atomicAdd(&re[h[c]], v);
        }
    }
    __syncthreads();
    fft16000(re, im, 1, tid, T);
    float* zo = Zout + (size_t)p * (2 * N_FFT);
    for (int d = tid; d < N_FFT; d += T) { zo[d] = re[d]; zo[N_FFT + d] = im[d]; }
}

// -------- backward: sketch2 -> FFT -> product -> inv FFT -> ssqrt+l2norm -----
__global__ void k_bwd(const float* __restrict__ src,
                      const int* __restrict__ h, const int* __restrict__ sg,
                      const float* __restrict__ Zin, float* __restrict__ Yout) {
    extern __shared__ float sm[];
    float* re = sm;
    float* im = sm + N_FFT;
    float* red = sm + 2 * N_FFT;
    int tid = threadIdx.x, T = blockDim.x, p = blockIdx.x;
    for (int d = tid; d < N_FFT; d += T) { re[d] = 0.0f; im[d] = 0.0f; }
    __syncthreads();
    const float* x = src + (size_t)p * 2048;
    for (int c = tid; c < 2048; c += T) {
        float v = x[c];
        v = (sg[c] > 0) ? v : -v;
        atomicAdd(&re[h[c]], v);
    }
    __syncthreads();
    fft16000(re, im, 1, tid, T);
    const float* zr = Zin + (size_t)p * (2 * N_FFT);
    const float* zi = zr + N_FFT;
    for (int d = tid; d < N_FFT; d += T) {
        float a = re[d], b2 = im[d], c2 = zr[d], d2 = zi[d];
        re[d] = a * c2 - b2 * d2;
        im[d] = a * d2 + b2 * c2;
    }
    __syncthreads();
    fft16000(re, im, -1, tid, T);
    const float invN = 1.0f / (float)N_FFT;
    float ss = 0.0f;
    for (int d = tid; d < N_FFT; d += T) {
        float v = re[d] * invN;
        float y = copysignf(sqrtf(fabsf(v)), v);    // signed sqrt
        re[d] = y;
        ss += y * y;
    }
    #pragma unroll
    for (int o = 16; o; o >>= 1) ss += __shfl_xor_sync(0xffffffffu, ss, o);
    if ((tid & 31) == 0) red[tid >> 5] = ss;
    __syncthreads();
    if (tid == 0) {
        float tot = 0.0f;
        int nw = T >> 5;
        for (int i = 0; i < nw; i++) tot += red[i];
        red[0] = 1.0f / fmaxf(sqrtf(tot), 1e-12f);
    }
    __syncthreads();
    float sc = red[0];
    float* yo = Yout + (size_t)p * N_FFT;
    for (int d = tid; d < N_FFT; d += T) yo[d] = re[d] * sc;
}

// -------- conv1 GEMM split-K partials: Cp[z][p][o] = sum_k Y[p,k]*W1[o,k] -----
__global__ __launch_bounds__(256, 2) void k_gemm1(const float* __restrict__ A,
                                                  const float* __restrict__ B,
                                                  float* __restrict__ Cp) {
    __shared__ __align__(16) float As[2][8][128];
    __shared__ __align__(16) float Bs[2][8][128];
    int tid = threadIdx.x;
    int p0 = blockIdx.x * 128, o0 = blockIdx.y * 128;
    int kbeg = blockIdx.z * KCHUNK;
    int kend = min(16000, kbeg + KCHUNK);
    int arow = tid >> 1;
    int ac4 = (tid & 1) * 4;
    bool aval = (p0 + arow) < PPOS;
    const float* Aptr = A + (size_t)(p0 + arow) * 16000;
    const float* Bptr = B + (size_t)(o0 + arow) * 16000;

    float4 pa = aval ? *(const float4*)(Aptr + kbeg + ac4) : make_float4(0, 0, 0, 0);
    float4 pb = *(const float4*)(Bptr + kbeg + ac4);
    As[0][ac4 + 0][arow] = pa.x; As[0][ac4 + 1][arow] = pa.y;
    As[0][ac4 + 2][arow] = pa.z; As[0][ac4 + 3][arow] = pa.w;
    Bs[0][ac4 + 0][arow] = pb.x; Bs[0][ac4 + 1][arow] = pb.y;
    Bs[0][ac4 + 2][arow] = pb.z; Bs[0][ac4 + 3][arow] = pb.w;
    __syncthreads();

    int nk = (kend - kbeg) >> 3;
    int ty = tid >> 4, tx = tid & 15;
    float acc[8][8];
    #pragma unroll
    for (int i = 0; i < 8; i++)
        #pragma unroll
        for (int j = 0; j < 8; j++) acc[i][j] = 0.0f;

    for (int it = 0; it < nk; it++) {
        int cur = it & 1;
        bool more = (it + 1) < nk;
        if (more) {
            int k = kbeg + (it + 1) * 8;
            pa = aval ? *(const float4*)(Aptr + k + ac4) : make_float4(0, 0, 0, 0);
            pb = *(const float4*)(Bptr + k + ac4);
        }
        #pragma unroll
        for (int kk = 0; kk < 8; kk++) {
            float a[8], b[8];
            *(float4*)&a[0] = *(const float4*)&As[cur][kk][ty * 8];
            *(float4*)&a[4] = *(const float4*)&As[cur][kk][ty * 8 + 4];
            *(float4*)&b[0] = *(const float4*)&Bs[cur][kk][tx * 8];
            *(float4*)&b[4] = *(const float4*)&Bs[cur][kk][tx * 8 + 4];
            #pragma unroll
            for (int i = 0; i < 8; i++)
                #pragma unroll
                for (int j = 0; j < 8; j++) acc[i][j] += a[i] * b[j];
        }
        if (more) {
            int nxt = cur ^ 1;
            As[nxt][ac4 + 0][arow] = pa.x; As[nxt][ac4 + 1][arow] = pa.y;
            As[nxt][ac4 + 2][arow] = pa.z; As[nxt][ac4 + 3][arow] = pa.w;
            Bs[nxt][ac4 + 0][arow] = pb.x; Bs[nxt][ac4 + 1][arow] = pb.y;
            Bs[nxt][ac4 + 2][arow] = pb.z; Bs[nxt][ac4 + 3][arow] = pb.w;
        }
        __syncthreads();
    }

    float* cp = Cp + (size_t)blockIdx.z * PPOS * 512;
    #pragma unroll
    for (int i = 0; i < 8; i++) {
        int p = p0 + ty * 8 + i;
        if (p < PPOS) {
            float* dst = cp + (size_t)p * 512 + o0 + tx * 8;
            #pragma unroll
            for (int j = 0; j < 8; j++) dst[j] = acc[i][j];
        }
    }
}

// -------- attention: sum partials + bias + relu, conv2, softmax(49), pooling -
__global__ void k_attn(const float* __restrict__ b1, const float* __restrict__ w2,
                       const float* __restrict__ b2, const float* __restrict__ img) {
    __shared__ float slog[49];
    __shared__ float sw[49];
    int b = blockIdx.x, tid = threadIdx.x;
    int warp = tid >> 5, lane = tid & 31;
    for (int q = warp; q < 49; q += 8) {
        float acc = 0.0f;
        const float* c0 = g_Cpart + (size_t)(b * 49 + q) * 512;
        for (int o = lane; o < 512; o += 32) {
            float z = b1[o];
            #pragma unroll
            for (int s = 0; s < NSPLIT; s++) z += c0[(size_t)s * PPOS * 512 + o];
            z = fmaxf(z, 0.0f);
            acc += z * w2[o];
        }
        #pragma unroll
        for (int o = 16; o; o >>= 1) acc += __shfl_xor_sync(0xffffffffu, acc, o);
        if (lane == 0) slog[q] = acc + b2[0];
    }
    __syncthreads();
    if (tid == 0) {
        float mx = -1e30f;
        for (int q = 0; q < 49; q++) mx = fmaxf(mx, slog[q]);
        float sum = 0.0f;
        for (int q = 0; q < 49; q++) { float e = expf(slog[q] - mx); sw[q] = e; sum += e; }
        float inv = 1.0f / sum;
        for (int q = 0; q < 49; q++) sw[q] *= inv;
    }
    __syncthreads();
    // faithful to torch .view(bs,49,-1) on NCHW-contiguous img: flat addressing
    const float* ib = img + (size_t)b * 100352;
    for (int c = tid; c < 2048; c += blockDim.x) {
        float acc = 0.0f;
        #pragma unroll
        for (int q = 0; q < 49; q++) acc += sw[q] * ib[q * 2048 + c];
        g_res[b * 2048 + c] = acc;
    }
}

// -------- final GEMM partials: Fp[z][b][o] = sum_{k-chunk} Yb[b,k]*W[o,k] -----
__global__ __launch_bounds__(256) void k_final(const float* __restrict__ W) {
    __shared__ __align__(16) float Ws[16][132];
    __shared__ __align__(16) float Ys[16][36];
    int tid = threadIdx.x;
    int o0 = blockIdx.x * 128;
    int z = blockIdx.y;
    int ty = tid >> 5, tx = tid & 31;            // ty: b-quad 0..7, tx: o-quad 0..31
    float acc[4][4];
    #pragma unroll
    for (int i = 0; i < 4; i++)
        #pragma unroll
        for (int j = 0; j < 4; j++) acc[i][j] = 0.0f;

    int kq = (tid & 3) * 4;
    int orow = tid >> 2;                          // 0..63
    int brow = tid >> 2;                          // 0..63 (use <32)

    for (int it = 0; it < 125; it++) {
        int k0 = z * 2000 + it * 16;
        if (brow < 32) {
            float4 f = *(const float4*)(g_Yb + (size_t)brow * 16000 + k0 + kq);
            Ys[kq + 0][brow] = f.x; Ys[kq + 1][brow] = f.y;
            Ys[kq + 2][brow] = f.z; Ys[kq + 3][brow] = f.w;
        }
        #pragma unroll
        for (int rr = 0; rr < 2; rr++) {
            int o = o0 + orow + rr * 64;
            float4 f = (o < 3000) ? *(const float4*)(W + (size_t)o * 16000 + k0 + kq)
                                  : make_float4(0, 0, 0, 0);
            Ws[kq + 0][orow + rr * 64] = f.x; Ws[kq + 1][orow + rr * 64] = f.y;
            Ws[kq + 2][orow + rr * 64] = f.z; Ws[kq + 3][orow + rr * 64] = f.w;
        }
        __syncthreads();
        #pragma unroll
        for (int kk = 0; kk < 16; kk++) {
            float a[4], b[4];
            *(float4*)a = *(const float4*)&Ys[kk][ty * 4];
            *(float4*)b = *(const float4*)&Ws[kk][tx * 4];
            #pragma unroll
            for (int i = 0; i < 4; i++)
                #pragma unroll
                for (int j = 0; j < 4; j++) acc[i][j] += a[i] * b[j];
        }
        __syncthreads();
    }

    float* fp = g_Fpart + (size_t)z * 32 * 3000;
    #pragma unroll
    for (int i = 0; i < 4; i++) {
        int b = ty * 4 + i;
        #pragma unroll
        for (int j = 0; j < 4; j++) {
            int o = o0 + tx * 4 + j;
            if (o < 3000) fp[(size_t)b * 3000 + o] = acc[i][j];
        }
    }
}

// -------- reduce final partials + bias -> d_out ------------------------------
__global__ void k_finred(const float* __restrict__ bias, float* __restrict__ out) {
    int i = blockIdx.x * blockDim.x + threadIdx.x;
    if (i < 32 * 3000) {
        int o = i % 3000;
        float s = bias[o];
        #pragma unroll
        for (int zz = 0; zz < FSPLIT; zz++) s += g_Fpart[(size_t)zz * 32 * 3000 + i];
        out[i] = s;
    }
}

extern "C" void kernel_launch(void* const* d_in, const int* in_sizes, int n_in,
                              void* d_out, int out_size) {
    const float* txt     = (const float*)d_in[0];
    const float* img     = (const float*)d_in[1];
    const float* conv1_w = (const float*)d_in[2];
    const float* conv1_b = (const float*)d_in[3];
    const float* conv2_w = (const float*)d_in[4];
    const float* conv2_b = (const float*)d_in[5];
    const float* lin2_w  = (const float*)d_in[6];
    const float* lin2_b  = (const float*)d_in[7];
    const int* h1a = (const int*)d_in[8];
    const int* s1a = (const int*)d_in[9];
    const int* h2a = (const int*)d_in[10];
    const int* s2a = (const int*)d_in[11];
    const int* h1b = (const int*)d_in[12];
    const int* s1b = (const int*)d_in[13];
    const int* h2b = (const int*)d_in[14];
    const int* s2b = (const int*)d_in[15];
    float* out = (float*)d_out;

    const int SMEMB = (2 * N_FFT + 32) * sizeof(float);
    cudaFuncSetAttribute(k_fwd, cudaFuncAttributeMaxDynamicSharedMemorySize, SMEMB);
    cudaFuncSetAttribute(k_bwd, cudaFuncAttributeMaxDynamicSharedMemorySize, SMEMB);

    float* zptr;  cudaGetSymbolAddress((void**)&zptr, g_Z1);
    float* yptr;  cudaGetSymbolAddress((void**)&yptr, g_Y);
    float* zbptr; cudaGetSymbolAddress((void**)&zbptr, g_Zb1);
    float* ybptr; cudaGetSymbolAddress((void**)&ybptr, g_Yb);
    float* cpptr; cudaGetSymbolAddress((void**)&cpptr, g_Cpart);
    float* tpptr; cudaGetSymbolAddress((void**)&tpptr, g_txtp);
    float* itptr; cudaGetSymbolAddress((void**)&itptr, g_imgt);
    float* rsptr; cudaGetSymbolAddress((void**)&rsptr, g_res);

    k_twiddle<<<(N_FFT + 255) / 256, 256>>>();
    k_txtp<<<32, 256>>>(txt);
    k_imgt<<<PPOS, 256>>>(img);

    // CBP layer A, per spatial position
    k_fwd<<<PPOS, 512, SMEMB>>>(tpptr, 0, h1a, s1a, zptr);
    k_bwd<<<PPOS, 512, SMEMB>>>(itptr, h2a, s2a, zptr, yptr);

    // conv1 (split-K) + attention
    dim3 g1(13, 4, NSPLIT);
    k_gemm1<<<g1, 256>>>(yptr, conv1_w, cpptr);
    k_attn<<<32, 256>>>(conv1_b, conv2_w, conv2_b, img);

    // CBP layer B, per batch
    k_fwd<<<32, 512, SMEMB>>>(tpptr, 1, h1b, s1b, zbptr);
    k_bwd<<<32, 512, SMEMB>>>(rsptr, h2b, s2b, zbptr, ybptr);

    // final linear
    dim3 gf(24, FSPLIT);
    k_final<<<gf, 256>>>(lin2_w);
    k_finred<<<(32 * 3000 + 255) / 256, 256>>>(lin2_b, out);
}

// round 7
// speedup vs baseline: 1.9496x; 1.9496x over previous
#include <cuda_runtime.h>
#include <math.h>
#include <stdint.h>

#define N_FFT 16000
#define PPOS  1568
#define NSPLIT 6
#define KCHUNK 2672
#define FSPLIT 8
#define TCBP   1024

// -------- device scratch (allocation-free rule: __device__ globals) --------
__device__ float g_txtp[32 * 2048];
__device__ __align__(16) float g_imgt[(size_t)PPOS * 2048];
__device__ __align__(16) float g_Y[(size_t)PPOS * N_FFT];
__device__ float g_Cpart[(size_t)NSPLIT * PPOS * 512];
__device__ float g_res[32 * 2048];
__device__ __align__(16) float g_Yb[(size_t)32 * N_FFT];
__device__ float g_Fpart[(size_t)FSPLIT * 32 * 3000];

__constant__ float W5C[5] = {1.0f, 0.30901699437494742f, -0.80901699437494745f,
                             -0.80901699437494745f, 0.30901699437494742f};
__constant__ float W5S[5] = {0.0f, 0.95105651629515353f, 0.58778525229247314f,
                             -0.58778525229247314f, -0.95105651629515353f};

// -------- txt avgpool (3,3) s(100,1) p(1,1) count_include_pad -> (32,2048) ----
__global__ void k_txtp(const float* __restrict__ txt) {
    int b = blockIdx.x;
    const float* base = txt + (size_t)b * 50 * 2048;
    for (int j = threadIdx.x; j < 2048; j += blockDim.x) {
        float sum = 0.0f;
        #pragma unroll
        for (int r = 0; r < 2; r++)
            #pragma unroll
            for (int dj = -1; dj <= 1; dj++) {
                int jj = j + dj;
                if (jj >= 0 && jj < 2048) sum += base[r * 2048 + jj];
            }
        g_txtp[b * 2048 + j] = sum * (1.0f / 9.0f);
    }
}

// -------- transpose img NCHW -> rows (b*49+q, c) for coalesced sketch --------
__global__ void k_imgt(const float* __restrict__ img) {
    int p = blockIdx.x;
    int b = p / 49, q = p - 49 * b;
    const float* ib = img + (size_t)b * 2048 * 49;
    float* op = g_imgt + (size_t)p * 2048;
    for (int c = threadIdx.x; c < 2048; c += blockDim.x)
        op[c] = ib[c * 49 + q];
}

// -------- one mixed-radix stage on smem (twiddles via __sincosf) -------------
// dir>0: DIF forward (butterfly then twiddle), scrambled output.
// dir<0: transposed network (conj twiddle then inverse butterfly), stages in
//        reverse order; consumes scrambled input, emits natural order.
__device__ __forceinline__ void fft_stage(float* re, float* im, int L, int r, int dir,
                                          int tid) {
    int m = L / r;
    int nb = N_FFT / r;
    float invL = 1.0f / (float)L;
    if (r == 2) {
        for (int i = tid; i < nb; i += TCBP) {
            int blk = i / m, j = i - blk * m;
            int i0 = blk * L + j, i1 = i0 + m;
            float f = (float)j * invL;
            if (f >= 0.5f) f -= 1.0f;
            float wr, wi;
            __sincosf(-6.28318530717958647692f * f, &wi, &wr);
            // note: __sincosf(x, &s, &c) -> s=sin, c=cos; we swapped names: fix
            float sr = wi; wi = 0.0f; // placeholder (overwritten below)
            (void)sr;
            __sincosf(-6.28318530717958647692f * f, &wi, &wr);
            float ar = re[i0], ai = im[i0], br = re[i1], bi = im[i1];
            if (dir > 0) {
                float vr = ar - br, vi = ai - bi;
                re[i0] = ar + br;            im[i0] = ai + bi;
                re[i1] = vr * wr - vi * wi;  im[i1] = vr * wi + vi * wr;
            } else {
                float tr = br * wr + bi * wi;   // b * conj(w)
                float ti = bi * wr - br * wi;
                re[i0] = ar + tr; im[i0] = ai + ti;
                re[i1] = ar - tr; im[i1] = ai - ti;
            }
        }
    } else if (r == 4) {
        for (int i = tid; i < nb; i += TCBP) {
            int blk = i / m, j = i - blk * m;
            int base = blk * L + j;
            float f = (float)j * invL;
            if (f >= 0.5f) f -= 1.0f;
            float c1, s1;
            __sincosf(-6.28318530717958647692f * f, &s1, &c1);
            float c2 = c1 * c1 - s1 * s1, s2 = 2.0f * c1 * s1;
            float c3 = c2 * c1 - s2 * s1, s3 = c2 * s1 + s2 * c1;
            float u0r = re[base],         u0i = im[base];
            float u1r = re[base + m],     u1i = im[base + m];
            float u2r = re[base + 2 * m], u2i = im[base + 2 * m];
            float u3r = re[base + 3 * m], u3i = im[base + 3 * m];
            if (dir > 0) {
                float t0r = u0r + u2r, t0i = u0i + u2i;
                float t1r = u0r - u2r, t1i = u0i - u2i;
                float t2r = u1r + u3r, t2i = u1i + u3i;
                float t3r = u1r - u3r, t3i = u1i - u3i;
                re[base] = t0r + t2r;  im[base] = t0i + t2i;
                float v1r = t1r + t3i, v1i = t1i - t3r;   // t1 - i t3
                float v2r = t0r - t2r, v2i = t0i - t2i;
                float v3r = t1r - t3i, v3i = t1i + t3r;   // t1 + i t3
                re[base + m]     = v1r * c1 - v1i * s1; im[base + m]     = v1r * s1 + v1i * c1;
                re[base + 2 * m] = v2r * c2 - v2i * s2; im[base + 2 * m] = v2r * s2 + v2i * c2;
                re[base + 3 * m] = v3r * c3 - v3i * s3; im[base + 3 * m] = v3r * s3 + v3i * c3;
            } else {
                // conj rotate inputs q>=1: (a + i b) * (c - i s)
                float a1r = u1r * c1 + u1i * s1, a1i = u1i * c1 - u1r * s1;
                float a2r = u2r * c2 + u2i * s2, a2i = u2i * c2 - u2r * s2;
                float a3r = u3r * c3 + u3i * s3, a3i = u3i * c3 - u3r * s3;
                float t0r = u0r + a2r, t0i = u0i + a2i;
                float t1r = u0r - a2r, t1i = u0i - a2i;
                float t2r = a1r + a3r, t2i = a1i + a3i;
                float t3r = a1r - a3r, t3i = a1i - a3i;
                re[base] = t0r + t2r;  im[base] = t0i + t2i;
                re[base + m]     = t1r - t3i; im[base + m]     = t1i + t3r;  // t1 + i t3
                re[base + 2 * m] = t0r - t2r; im[base + 2 * m] = t0i - t2i;
                re[base + 3 * m] = t1r + t3i; im[base + 3 * m] = t1i - t3r;  // t1 - i t3
            }
        }
    } else {  // r == 5
        for (int i = tid; i < nb; i += TCBP) {
            int blk = i / m, j = i - blk * m;
            int base = blk * L + j;
            float f = (float)j * invL;
            if (f >= 0.5f) f -= 1.0f;
            float w1r, w1i;
            __sincosf(-6.28318530717958647692f * f, &w1i, &w1r);
            float ur[5], ui[5];
            if (dir > 0) {
                #pragma unroll
                for (int q = 0; q < 5; q++) { ur[q] = re[base + q * m]; ui[q] = im[base + q * m]; }
                float cwr = 1.0f, cwi = 0.0f;   // running twiddle W^{jq}
                #pragma unroll
                for (int q = 0; q < 5; q++) {
                    float vr = 0.0f, vi = 0.0f;
                    #pragma unroll
                    for (int t = 0; t < 5; t++) {
                        int e = (q * t) % 5;
                        float C = W5C[e], S = W5S[e];       // * e^{-i th}
                        vr += ur[t] * C + ui[t] * S;
                        vi += ui[t] * C - ur[t] * S;
                    }
                    re[base + q * m] = vr * cwr - vi * cwi;
                    im[base + q * m] = vr * cwi + vi * cwr;
                    float nr = cwr * w1r - cwi * w1i;
                    cwi = cwr * w1i + cwi * w1r; cwr = nr;
                }
            } else {
                float cwr = 1.0f, cwi = 0.0f;
                #pragma unroll
                for (int q = 0; q < 5; q++) {
                    float a = re[base + q * m], b2 = im[base + q * m];
                    ur[q] = a * cwr + b2 * cwi;             // * conj(W^{jq})
                    ui[q] = b2 * cwr - a * cwi;
                    float nr = cwr * w1r - cwi * w1i;
                    cwi = cwr * w1i + cwi * w1r; cwr = nr;
                }
                #pragma unroll
                for (int t = 0; t < 5; t++) {
                    float vr = 0.0f, vi = 0.0f;
                    #pragma unroll
                    for (int q = 0; q < 5; q++) {
                        int e = (q * t) % 5;
                        float C = W5C[e], S = W5S[e];       // * e^{+i th}
                        vr += ur[q] * C - ui[q] * S;
                        vi += ui[q] * C + ur[q] * S;
                    }
                    re[base + t * m] = vr; im[base + t * m] = vi;
                }
            }
        }
    }
}

__device__ __forceinline__ void fft16000(float* re, float* im, int dir, int tid) {
    const int rads[7] = {4, 4, 4, 2, 5, 5, 5};
    if (dir > 0) {
        int L = N_FFT;
        #pragma unroll
        for (int s = 0; s < 7; s++) {
            fft_stage(re, im, L, rads[s], 1, tid);
            __syncthreads();
            L /= rads[s];
        }
    } else {
        int Ls[7];
        int L = N_FFT;
        #pragma unroll
        for (int s = 0; s < 7; s++) { Ls[s] = L; L /= rads[s]; }
        #pragma unroll
        for (int s = 6; s >= 0; s--) {
            fft_stage(re, im, Ls[s], rads[s], -1, tid);
            __syncthreads();
        }
    }
}

// -------- fused CBP: z = sketch1 + i*sketch2; FFT; Z^2; IFFT;
//          a(*)b = Im/(2N); signed-sqrt; l2-norm -----------------------------
// mode 0 (layer A): sketch1[c] = txt_p[b, (49c+q)&2047], sketch2 from src2 rows
// mode 1 (layer B): both from plain rows p
__global__ __launch_bounds__(TCBP, 1) void k_cbp(
    const float* __restrict__ src1, const float* __restrict__ src2, int mode,
    const int* __restrict__ h1, const int* __restrict__ s1,
    const int* __restrict__ h2, const int* __restrict__ s2,
    float* __restrict__ Yout) {
    extern __shared__ float sm[];
    float* re = sm;
    float* im = sm + N_FFT;
    float* red = sm + 2 * N_FFT;
    int tid = threadIdx.x, p = blockIdx.x;
    for (int d = tid; d < N_FFT; d += TCBP) { re[d] = 0.0f; im[d] = 0.0f; }
    __syncthreads();
    if (mode == 0) {
        int b = p / 49, q = p - 49 * b;
        const float* tp = src1 + (size_t)b * 2048;
        const float* x2 = src2 + (size_t)p * 2048;
        for (int c = tid; c < 2048; c += TCBP) {
            float v = tp[(49 * c + q) & 2047];
            v = (s1[c] > 0) ? v : -v;
            atomicAdd(&re[h1[c]], v);
            float w = x2[c];
            w = (s2[c] > 0) ? w : -w;
            atomicAdd(&im[h2[c]], w);
        }
    } else {
        const float* x1 = src1 + (size_t)p * 2048;
        const float* x2 = src2 + (size_t)p * 2048;
        for (int c = tid; c < 2048; c += TCBP) {
            float v = x1[c];
            v = (s1[c] > 0) ? v : -v;
            atomicAdd(&re[h1[c]], v);
            float w = x2[c];
            w = (s2[c] > 0) ? w : -w;
            atomicAdd(&im[h2[c]], w);
        }
    }
    __syncthreads();
    fft16000(re, im, 1, tid);          // scrambled Z
    for (int d = tid; d < N_FFT; d += TCBP) {
        float a = re[d], b2 = im[d];   // Z^2 (pointwise, order-agnostic)
        re[d] = a * a - b2 * b2;
        im[d] = 2.0f * a * b2;
    }
    __syncthreads();
    fft16000(re, im, -1, tid);         // natural-order unnormalized IDFT
    const float sc0 = 0.5f / (float)N_FFT;   // Im/(2N) = a (*) b
    float ss = 0.0f;
    for (int d = tid; d < N_FFT; d += TCBP) {
        float v = im[d] * sc0;
        float y = copysignf(sqrtf(fabsf(v)), v);
        im[d] = y;
        ss += y * y;
    }
    #pragma unroll
    for (int o = 16; o; o >>= 1) ss += __shfl_xor_sync(0xffffffffu, ss, o);
    if ((tid & 31) == 0) red[tid >> 5] = ss;
    __syncthreads();
    if (tid == 0) {
        float tot = 0.0f;
        for (int i = 0; i < TCBP / 32; i++) tot += red[i];
        red[0] = 1.0f / fmaxf(sqrtf(tot), 1e-12f);
    }
    __syncthreads();
    float sc = red[0];
    float* yo = Yout + (size_t)p * N_FFT;
    for (int d = tid; d < N_FFT; d += TCBP) yo[d] = im[d] * sc;
}

// -------- conv1 GEMM split-K partials: Cp[z][p][o] = sum_k Y[p,k]*W1[o,k] -----
__global__ __launch_bounds__(256, 2) void k_gemm1(const float* __restrict__ A,
                                                  const float* __restrict__ B,
                                                  float* __restrict__ Cp) {
    __shared__ __align__(16) float As[2][8][128];
    __shared__ __align__(16) float Bs[2][8][128];
    int tid = threadIdx.x;
    int p0 = blockIdx.x * 128, o0 = blockIdx.y * 128;
    int kbeg = blockIdx.z * KCHUNK;
    int kend = min(16000, kbeg + KCHUNK);
    int arow = tid >> 1;
    int ac4 = (tid & 1) * 4;
    bool aval = (p0 + arow) < PPOS;
    const float* Aptr = A + (size_t)(p0 + arow) * 16000;
    const float* Bptr = B + (size_t)(o0 + arow) * 16000;

    float4 pa = aval ? *(const float4*)(Aptr + kbeg + ac4) : make_float4(0, 0, 0, 0);
    float4 pb = *(const float4*)(Bptr + kbeg + ac4);
    As[0][ac4 + 0][arow] = pa.x; As[0][ac4 + 1][arow] = pa.y;
    As[0][ac4 + 2][arow] = pa.z; As[0][ac4 + 3][arow] = pa.w;
    Bs[0][ac4 + 0][arow] = pb.x; Bs[0][ac4 + 1][arow] = pb.y;
    Bs[0][ac4 + 2][arow] = pb.z; Bs[0][ac4 + 3][arow] = pb.w;
    __syncthreads();

    int nk = (kend - kbeg) >> 3;
    int ty = tid >> 4, tx = tid & 15;
    float acc[8][8];
    #pragma unroll
    for (int i = 0; i < 8; i++)
        #pragma unroll
        for (int j = 0; j < 8; j++) acc[i][j] = 0.0f;

    for (int it = 0; it < nk; it++) {
        int cur = it & 1;
        bool more = (it + 1) < nk;
        if (more) {
            int k = kbeg + (it + 1) * 8;
            pa = aval ? *(const float4*)(Aptr + k + ac4) : make_float4(0, 0, 0, 0);
            pb = *(const float4*)(Bptr + k + ac4);
        }
        #pragma unroll
        for (int kk = 0; kk < 8; kk++) {
            float a[8], b[8];
            *(float4*)&a[0] = *(const float4*)&As[cur][kk][ty * 8];
            *(float4*)&a[4] = *(const float4*)&As[cur][kk][ty * 8 + 4];
            *(float4*)&b[0] = *(const float4*)&Bs[cur][kk][tx * 8];
            *(float4*)&b[4] = *(const float4*)&Bs[cur][kk][tx * 8 + 4];
            #pragma unroll
            for (int i = 0; i < 8; i++)
                #pragma unroll
                for (int j = 0; j < 8; j++) acc[i][j] += a[i] * b[j];
        }
        if (more) {
            int nxt = cur ^ 1;
            As[nxt][ac4 + 0][arow] = pa.x; As[nxt][ac4 + 1][arow] = pa.y;
            As[nxt][ac4 + 2][arow] = pa.z; As[nxt][ac4 + 3][arow] = pa.w;
            Bs[nxt][ac4 + 0][arow] = pb.x; Bs[nxt][ac4 + 1][arow] = pb.y;
            Bs[nxt][ac4 + 2][arow] = pb.z; Bs[nxt][ac4 + 3][arow] = pb.w;
        }
        __syncthreads();
    }

    float* cp = Cp + (size_t)blockIdx.z * PPOS * 512;
    #pragma unroll
    for (int i = 0; i < 8; i++) {
        int p = p0 + ty * 8 + i;
        if (p < PPOS) {
            float* dst = cp + (size_t)p * 512 + o0 + tx * 8;
            #pragma unroll
            for (int j = 0; j < 8; j++) dst[j] = acc[i][j];
        }
    }
}

// -------- attention: sum partials + bias + relu, conv2, softmax(49), pooling -
__global__ void k_attn(const float* __restrict__ b1, const float* __restrict__ w2,
                       const float* __restrict__ b2, const float* __restrict__ img) {
    __shared__ float slog[49];
    __shared__ float sw[49];
    int b = blockIdx.x, tid = threadIdx.x;
    int warp = tid >> 5, lane = tid & 31;
    for (int q = warp; q < 49; q += 8) {
        float acc = 0.0f;
        const float* c0 = g_Cpart + (size_t)(b * 49 + q) * 512;
        for (int o = lane; o < 512; o += 32) {
            float z = b1[o];
            #pragma unroll
            for (int s = 0; s < NSPLIT; s++) z += c0[(size_t)s * PPOS * 512 + o];
            z = fmaxf(z, 0.0f);
            acc += z * w2[o];
        }
        #pragma unroll
        for (int o = 16; o; o >>= 1) acc += __shfl_xor_sync(0xffffffffu, acc, o);
        if (lane == 0) slog[q] = acc + b2[0];
    }
    __syncthreads();
    if (tid == 0) {
        float mx = -1e30f;
        for (int q = 0; q < 49; q++) mx = fmaxf(mx, slog[q]);
        float sum = 0.0f;
        for (int q = 0; q < 49; q++) { float e = expf(slog[q] - mx); sw[q] = e; sum += e; }
        float inv = 1.0f / sum;
        for (int q = 0; q < 49; q++) sw[q] *= inv;
    }
    __syncthreads();
    // faithful to torch .view(bs,49,-1) on NCHW-contiguous img: flat addressing
    const float* ib = img + (size_t)b * 100352;
    for (int c = tid; c < 2048; c += blockDim.x) {
        float acc = 0.0f;
        #pragma unroll
        for (int q = 0; q < 49; q++) acc += sw[q] * ib[q * 2048 + c];
        g_res[b * 2048 + c] = acc;
    }
}

// -------- final GEMM partials: Fp[z][b][o] = sum_{k-chunk} Yb[b,k]*W[o,k] -----
__global__ __launch_bounds__(256) void k_final(const float* __restrict__ W) {
    __shared__ __align__(16) float Ws[16][132];
    __shared__ __align__(16) float Ys[16][36];
    int tid = threadIdx.x;
    int o0 = blockIdx.x * 128;
    int z = blockIdx.y;
    int ty = tid >> 5, tx = tid & 31;
    float acc[4][4];
    #pragma unroll
    for (int i = 0; i < 4; i++)
        #pragma unroll
        for (int j = 0; j < 4; j++) acc[i][j] = 0.0f;

    int kq = (tid & 3) * 4;
    int orow = tid >> 2;
    int brow = tid >> 2;

    for (int it = 0; it < 125; it++) {
        int k0 = z * 2000 + it * 16;
        if (brow < 32) {
            float4 f = *(const float4*)(g_Yb + (size_t)brow * 16000 + k0 + kq);
            Ys[kq + 0][brow] = f.x; Ys[kq + 1][brow] = f.y;
            Ys[kq + 2][brow] = f.z; Ys[kq + 3][brow] = f.w;
        }
        #pragma unroll
        for (int rr = 0; rr < 2; rr++) {
            int o = o0 + orow + rr * 64;
            float4 f = (o < 3000) ? *(const float4*)(W + (size_t)o * 16000 + k0 + kq)
                                  : make_float4(0, 0, 0, 0);
            Ws[kq + 0][orow + rr * 64] = f.x; Ws[kq + 1][orow + rr * 64] = f.y;
            Ws[kq + 2][orow + rr * 64] = f.z; Ws[kq + 3][orow + rr * 64] = f.w;
        }
        __syncthreads();
        #pragma unroll
        for (int kk = 0; kk < 16; kk++) {
            float a[4], b[4];
            *(float4*)a = *(const float4*)&Ys[kk][ty * 4];
            *(float4*)b = *(const float4*)&Ws[kk][tx * 4];
            #pragma unroll
            for (int i = 0; i < 4; i++)
                #pragma unroll
                for (int j = 0; j < 4; j++) acc[i][j] += a[i] * b[j];
        }
        __syncthreads();
    }

    float* fp = g_Fpart + (size_t)z * 32 * 3000;
    #pragma unroll
    for (int i = 0; i < 4; i++) {
        int b = ty * 4 + i;
        #pragma unroll
        for (int j = 0; j < 4; j++) {
            int o = o0 + tx * 4 + j;
            if (o < 3000) fp[(size_t)b * 3000 + o] = acc[i][j];
        }
    }
}

// -------- reduce final partials + bias -> d_out ------------------------------
__global__ void k_finred(const float* __restrict__ bias, float* __restrict__ out) {
    int i = blockIdx.x * blockDim.x + threadIdx.x;
    if (i < 32 * 3000) {
        int o = i % 3000;
        float s = bias[o];
        #pragma unroll
        for (int zz = 0; zz < FSPLIT; zz++) s += g_Fpart[(size_t)zz * 32 * 3000 + i];
        out[i] = s;
    }
}

extern "C" void kernel_launch(void* const* d_in, const int* in_sizes, int n_in,
                              void* d_out, int out_size) {
    const float* txt     = (const float*)d_in[0];
    const float* img     = (const float*)d_in[1];
    const float* conv1_w = (const float*)d_in[2];
    const float* conv1_b = (const float*)d_in[3];
    const float* conv2_w = (const float*)d_in[4];
    const float* conv2_b = (const float*)d_in[5];
    const float* lin2_w  = (const float*)d_in[6];
    const float* lin2_b  = (const float*)d_in[7];
    const int* h1a = (const int*)d_in[8];
    const int* s1a = (const int*)d_in[9];
    const int* h2a = (const int*)d_in[10];
    const int* s2a = (const int*)d_in[11];
    const int* h1b = (const int*)d_in[12];
    const int* s1b = (const int*)d_in[13];
    const int* h2b = (const int*)d_in[14];
    const int* s2b = (const int*)d_in[15];
    float* out = (float*)d_out;

    const int SMEMB = (2 * N_FFT + 32) * sizeof(float);
    cudaFuncSetAttribute(k_cbp, cudaFuncAttributeMaxDynamicSharedMemorySize, SMEMB);

    float* yptr;  cudaGetSymbolAddress((void**)&yptr, g_Y);
    float* ybptr; cudaGetSymbolAddress((void**)&ybptr, g_Yb);
    float* cpptr; cudaGetSymbolAddress((void**)&cpptr, g_Cpart);
    float* tpptr; cudaGetSymbolAddress((void**)&tpptr, g_txtp);
    float* itptr; cudaGetSymbolAddress((void**)&itptr, g_imgt);
    float* rsptr; cudaGetSymbolAddress((void**)&rsptr, g_res);

    k_txtp<<<32, 256>>>(txt);
    k_imgt<<<PPOS, 256>>>(img);

    // CBP layer A: one fused kernel per spatial position (2 FFTs via Z^2 trick)
    k_cbp<<<PPOS, TCBP, SMEMB>>>(tpptr, itptr, 0, h1a, s1a, h2a, s2a, yptr);

    // conv1 (split-K) + attention
    dim3 g1(13, 4, NSPLIT);
    k_gemm1<<<g1, 256>>>(yptr, conv1_w, cpptr);
    k_attn<<<32, 256>>>(conv1_b, conv2_w, conv2_b, img);

    // CBP layer B, per batch
    k_cbp<<<32, TCBP, SMEMB>>>(tpptr, rsptr, 1, h1b, s1b, h2b, s2b, ybptr);

    // final linear
    dim3 gf(24, FSPLIT);
    k_final<<<gf, 256>>>(lin2_w);
    k_finred<<<(32 * 3000 + 255) / 256, 256>>>(lin2_b, out);
}

// round 9
// speedup vs baseline: 3.0903x; 1.5851x over previous
#include <cuda_runtime.h>
#include <cuda_bf16.h>
#include <math.h>
#include <stdint.h>

#define N_FFT 16000
#define PPOS  1568
#define PPAD  1664            // 13 * 128
#define NSPLIT 6
#define KCHUNK 2688           // divisible by 32; 5*2688 + 2560 = 16000
#define FSPLIT 8
#define TCBP   1024
#define SMT    10240          // bytes per smem tile array: 128 rows * 80B

// -------- device scratch (allocation-free rule: __device__ globals) --------
__device__ float g_txtp[32 * 2048];
__device__ __align__(16) float g_imgt[(size_t)PPOS * 2048];
__device__ __align__(16) __nv_bfloat16 g_Yh[(size_t)PPAD * N_FFT];
__device__ __align__(16) __nv_bfloat16 g_Yl[(size_t)PPAD * N_FFT];
__device__ __align__(16) __nv_bfloat16 g_Wh[(size_t)512 * N_FFT];
__device__ __align__(16) __nv_bfloat16 g_Wl[(size_t)512 * N_FFT];
__device__ float g_Cpart[(size_t)NSPLIT * PPOS * 512];
__device__ float g_res[32 * 2048];
__device__ __align__(16) float g_Yb[(size_t)32 * N_FFT];
__device__ float g_Fpart[(size_t)FSPLIT * 32 * 3000];

__constant__ float W5C[5] = {1.0f, 0.30901699437494742f, -0.80901699437494745f,
                             -0.80901699437494745f, 0.30901699437494742f};
__constant__ float W5S[5] = {0.0f, 0.95105651629515353f, 0.58778525229247314f,
                             -0.58778525229247314f, -0.95105651629515353f};

// -------- txt avgpool (3,3) s(100,1) p(1,1) count_include_pad -> (32,2048) ----
__global__ void k_txtp(const float* __restrict__ txt) {
    int b = blockIdx.x;
    const float* base = txt + (size_t)b * 50 * 2048;
    for (int j = threadIdx.x; j < 2048; j += blockDim.x) {
        float sum = 0.0f;
        #pragma unroll
        for (int r = 0; r < 2; r++)
            #pragma unroll
            for (int dj = -1; dj <= 1; dj++) {
                int jj = j + dj;
                if (jj >= 0 && jj < 2048) sum += base[r * 2048 + jj];
            }
        g_txtp[b * 2048 + j] = sum * (1.0f / 9.0f);
    }
}

// -------- transpose img NCHW -> rows (b*49+q, c) for coalesced sketch --------
__global__ void k_imgt(const float* __restrict__ img) {
    int p = blockIdx.x;
    int b = p / 49, q = p - 49 * b;
    const float* ib = img + (size_t)b * 2048 * 49;
    float* op = g_imgt + (size_t)p * 2048;
    for (int c = threadIdx.x; c < 2048; c += blockDim.x)
        op[c] = ib[c * 49 + q];
}

// -------- split conv1_w into bf16 hi/lo -------------------------------------
__global__ void k_wsplit(const float* __restrict__ W) {
    size_t i = (size_t)blockIdx.x * blockDim.x + threadIdx.x;
    if (i < (size_t)512 * N_FFT) {
        float w = W[i];
        __nv_bfloat16 h = __float2bfloat16(w);
        g_Wh[i] = h;
        g_Wl[i] = __float2bfloat16(w - __bfloat162float(h));
    }
}

// -------- zero padded Y rows [PPOS, PPAD) -----------------------------------
__global__ void k_padY() {
    size_t n = (size_t)(PPAD - PPOS) * N_FFT;
    size_t i = (size_t)blockIdx.x * blockDim.x + threadIdx.x;
    if (i < n) {
        g_Yh[(size_t)PPOS * N_FFT + i] = __float2bfloat16(0.0f);
        g_Yl[(size_t)PPOS * N_FFT + i] = __float2bfloat16(0.0f);
    }
}

// -------- one mixed-radix stage on smem, compile-time L/R/DIR ----------------
// DIR>0: DIF forward (butterfly then twiddle), scrambled output.
// DIR<0: transposed network (conj twiddle then inverse butterfly), reverse order.
template<int L, int R, int DIR>
__device__ __forceinline__ void fft_stage_t(float* re, float* im, int tid) {
    constexpr int m = L / R;
    constexpr int nb = N_FFT / R;
    const float invL = 1.0f / (float)L;
    for (int i = tid; i < nb; i += TCBP) {
        int blk = i / m, j = i - blk * m;          // const-divisor -> IMAD
        float f = (float)j * invL;
        if (f >= 0.5f) f -= 1.0f;
        if (R == 2) {
            int i0 = blk * L + j, i1 = i0 + m;
            float wr, wi;
            __sincosf(-6.28318530717958647692f * f, &wi, &wr);
            float ar = re[i0], ai = im[i0], br = re[i1], bi = im[i1];
            if (DIR > 0) {
                float vr = ar - br, vi = ai - bi;
                re[i0] = ar + br;            im[i0] = ai + bi;
                re[i1] = vr * wr - vi * wi;  im[i1] = vr * wi + vi * wr;
            } else {
                float tr = br * wr + bi * wi;   // b * conj(w)
                float ti = bi * wr - br * wi;
                re[i0] = ar + tr; im[i0] = ai + ti;
                re[i1] = ar - tr; im[i1] = ai - ti;
            }
        } else if (R == 4) {
            int base = blk * L + j;
            float c1, s1;
            __sincosf(-6.28318530717958647692f * f, &s1, &c1);
            float c2 = c1 * c1 - s1 * s1, s2 = 2.0f * c1 * s1;
            float c3 = c2 * c1 - s2 * s1, s3 = c2 * s1 + s2 * c1;
            float u0r = re[base],         u0i = im[base];
            float u1r = re[base + m],     u1i = im[base + m];
            float u2r = re[base + 2 * m], u2i = im[base + 2 * m];
            float u3r = re[base + 3 * m], u3i = im[base + 3 * m];
            if (DIR > 0) {
                float t0r = u0r + u2r, t0i = u0i + u2i;
                float t1r = u0r - u2r, t1i = u0i - u2i;
                float t2r = u1r + u3r, t2i = u1i + u3i;
                float t3r = u1r - u3r, t3i = u1i - u3i;
                re[base] = t0r + t2r;  im[base] = t0i + t2i;
                float v1r = t1r + t3i, v1i = t1i - t3r;   // t1 - i t3
                float v2r = t0r - t2r, v2i = t0i - t2i;
                float v3r = t1r - t3i, v3i = t1i + t3r;   // t1 + i t3
                re[base + m]     = v1r * c1 - v1i * s1; im[base + m]     = v1r * s1 + v1i * c1;
                re[base + 2 * m] = v2r * c2 - v2i * s2; im[base + 2 * m] = v2r * s2 + v2i * c2;
                re[base + 3 * m] = v3r * c3 - v3i * s3; im[base + 3 * m] = v3r * s3 + v3i * c3;
            } else {
                float a1r = u1r * c1 + u1i * s1, a1i = u1i * c1 - u1r * s1;
                float a2r = u2r * c2 + u2i * s2, a2i = u2i * c2 - u2r * s2;
                float a3r = u3r * c3 + u3i * s3, a3i = u3i * c3 - u3r * s3;
                float t0r = u0r + a2r, t0i = u0i + a2i;
                float t1r = u0r - a2r, t1i = u0i - a2i;
                float t2r = a1r + a3r, t2i = a1i + a3i;
                float t3r = a1r - a3r, t3i = a1i - a3i;
                re[base] = t0r + t2r;  im[base] = t0i + t2i;
                re[base + m]     = t1r - t3i; im[base + m]     = t1i + t3r;  // t1 + i t3
                re[base + 2 * m] = t0r - t2r; im[base + 2 * m] = t0i - t2i;
                re[base + 3 * m] = t1r + t3i; im[base + 3 * m] = t1i - t3r;  // t1 - i t3
            }
        } else {  // R == 5
            int base = blk * L + j;
            float w1r, w1i;
            __sincosf(-6.28318530717958647692f * f, &w1i, &w1r);
            float ur[5], ui[5];
            if (DIR > 0) {
                #pragma unroll
                for (int q = 0; q < 5; q++) { ur[q] = re[base + q * m]; ui[q] = im[base + q * m]; }
                float cwr = 1.0f, cwi = 0.0f;   // running twiddle W^{jq}
                #pragma unroll
                for (int q = 0; q < 5; q++) {
                    float vr = 0.0f, vi = 0.0f;
                    #pragma unroll
                    for (int t = 0; t < 5; t++) {
                        int e = (q * t) % 5;
                        float C = W5C[e], S = W5S[e];       // * e^{-i th}
                        vr += ur[t] * C + ui[t] * S;
                        vi += ui[t] * C - ur[t] * S;
                    }
                    re[base + q * m] = vr * cwr - vi * cwi;
                    im[base + q * m] = vr * cwi + vi * cwr;
                    float nr = cwr * w1r - cwi * w1i;
                    cwi = cwr * w1i + cwi * w1r; cwr = nr;
                }
            } else {
                float cwr = 1.0f, cwi = 0.0f;
                #pragma unroll
                for (int q = 0; q < 5; q++) {
                    float a = re[base + q * m], b2 = im[base + q * m];
                    ur[q] = a * cwr + b2 * cwi;             // * conj(W^{jq})
                    ui[q] = b2 * cwr - a * cwi;
                    float nr = cwr * w1r - cwi * w1i;
                    cwi = cwr * w1i + cwi * w1r; cwr = nr;
                }
                #pragma unroll
                for (int t = 0; t < 5; t++) {
                    float vr = 0.0f, vi = 0.0f;
                    #pragma unroll
                    for (int q = 0; q < 5; q++) {
                        int e = (q * t) % 5;
                        float C = W5C[e], S = W5S[e];       // * e^{+i th}
                        vr += ur[q] * C - ui[q] * S;
                        vi += ui[q] * C + ur[q] * S;
                    }
                    re[base + t * m] = vr; im[base + t * m] = vi;
                }
            }
        }
    }
}

__device__ __forceinline__ void fft_fwd(float* re, float* im, int tid) {
    fft_stage_t<16000, 4, 1>(re, im, tid); __syncthreads();
    fft_stage_t<4000, 4, 1>(re, im, tid);  __syncthreads();
    fft_stage_t<1000, 4, 1>(re, im, tid);  __syncthreads();
    fft_stage_t<250, 2, 1>(re, im, tid);   __syncthreads();
    fft_stage_t<125, 5, 1>(re, im, tid);   __syncthreads();
    fft_stage_t<25, 5, 1>(re, im, tid);    __syncthreads();
    fft_stage_t<5, 5, 1>(re, im, tid);     __syncthreads();
}
__device__ __forceinline__ void fft_inv(float* re, float* im, int tid) {
    fft_stage_t<5, 5, -1>(re, im, tid);     __syncthreads();
    fft_stage_t<25, 5, -1>(re, im, tid);    __syncthreads();
    fft_stage_t<125, 5, -1>(re, im, tid);   __syncthreads();
    fft_stage_t<250, 2, -1>(re, im, tid);   __syncthreads();
    fft_stage_t<1000, 4, -1>(re, im, tid);  __syncthreads();
    fft_stage_t<4000, 4, -1>(re, im, tid);  __syncthreads();
    fft_stage_t<16000, 4, -1>(re, im, tid); __syncthreads();
}

// -------- fused CBP: z = s1 + i*s2; FFT; Z^2; IFFT; Im/(2N); ssqrt; l2norm ---
// mode 0 (layer A): sketch1 from tiled txt_p, sketch2 from src2 rows;
//                   output split bf16 hi/lo (feeds tensor-core GEMM).
// mode 1 (layer B): both plain rows; output fp32 Yout.
__global__ __launch_bounds__(TCBP, 1) void k_cbp(
    const float* __restrict__ src1, const float* __restrict__ src2, int mode,
    const int* __restrict__ h1, const int* __restrict__ s1,
    const int* __restrict__ h2, const int* __restrict__ s2,
    float* __restrict__ Yout, __nv_bfloat16* __restrict__ YoutH,
    __nv_bfloat16* __restrict__ YoutL) {
    extern __shared__ float sm[];
    float* re = sm;
    float* im = sm + N_FFT;
    float* red = sm + 2 * N_FFT;
    int tid = threadIdx.x, p = blockIdx.x;
    for (int d = tid; d < N_FFT; d += TCBP) { re[d] = 0.0f; im[d] = 0.0f; }
    __syncthreads();
    if (mode == 0) {
        int b = p / 49, q = p - 49 * b;
        const float* tp = src1 + (size_t)b * 2048;
        const float* x2 = src2 + (size_t)p * 2048;
        for (int c = tid; c < 2048; c += TCBP) {
            float v = tp[(49 * c + q) & 2047];
            v = (s1[c] > 0) ? v : -v;
            atomicAdd(&re[h1[c]], v);
            float w = x2[c];
            w = (s2[c] > 0) ? w : -w;
            atomicAdd(&im[h2[c]], w);
        }
    } else {
        const float* x1 = src1 + (size_t)p * 2048;
        const float* x2 = src2 + (size_t)p * 2048;
        for (int c = tid; c < 2048; c += TCBP) {
            float v = x1[c];
            v = (s1[c] > 0) ? v : -v;
            atomicAdd(&re[h1[c]], v);
            float w = x2[c];
            w = (s2[c] > 0) ? w : -w;
            atomicAdd(&im[h2[c]], w);
        }
    }
    __syncthreads();
    fft_fwd(re, im, tid);              // scrambled Z
    for (int d = tid; d < N_FFT; d += TCBP) {
        float a = re[d], b2 = im[d];   // Z^2 (pointwise, order-agnostic)
        re[d] = a * a - b2 * b2;
        im[d] = 2.0f * a * b2;
    }
    __syncthreads();
    fft_inv(re, im, tid);              // natural-order unnormalized IDFT
    const float sc0 = 0.5f / (float)N_FFT;   // Im/(2N) = a (*) b
    float ss = 0.0f;
    for (int d = tid; d < N_FFT; d += TCBP) {
        float v = im[d] * sc0;
        float y = copysignf(sqrtf(fabsf(v)), v);
        im[d] = y;
        ss += y * y;
    }
    #pragma unroll
    for (int o = 16; o; o >>= 1) ss += __shfl_xor_sync(0xffffffffu, ss, o);
    if ((tid & 31) == 0) red[tid >> 5] = ss;
    __syncthreads();
    if (tid == 0) {
        float tot = 0.0f;
        for (int i = 0; i < TCBP / 32; i++) tot += red[i];
        red[0] = 1.0f / fmaxf(sqrtf(tot), 1e-12f);
    }
    __syncthreads();
    float sc = red[0];
    if (mode == 0) {
        __nv_bfloat16* yh = YoutH + (size_t)p * N_FFT;
        __nv_bfloat16* yl = YoutL + (size_t)p * N_FFT;
        for (int d = tid; d < N_FFT; d += TCBP) {
            float y = im[d] * sc;
            __nv_bfloat16 h = __float2bfloat16(y);
            yh[d] = h;
            yl[d] = __float2bfloat16(y - __bfloat162float(h));
        }
    } else {
        float* yo = Yout + (size_t)p * N_FFT;
        for (int d = tid; d < N_FFT; d += TCBP) yo[d] = im[d] * sc;
    }
}

// -------- conv1 GEMM on tensor cores, split-bf16 (hi*hi + hi*lo + lo*hi) -----
// Cp[z][p][o] = sum_k Y[p,k]*W1[o,k] for k in split chunk z.
__device__ __forceinline__ void ldmx4(uint32_t* r, uint32_t a) {
    asm volatile("ldmatrix.sync.aligned.m8n8.x4.shared.b16 {%0,%1,%2,%3}, [%4];"
                 : "=r"(r[0]), "=r"(r[1]), "=r"(r[2]), "=r"(r[3]) : "r"(a));
}
__device__ __forceinline__ void ldmx2(uint32_t* r, uint32_t a) {
    asm volatile("ldmatrix.sync.aligned.m8n8.x2.shared.b16 {%0,%1}, [%2];"
                 : "=r"(r[0]), "=r"(r[1]) : "r"(a));
}
__device__ __forceinline__ void mma16816(float* d, const uint32_t* a, const uint32_t* b) {
    asm volatile("mma.sync.aligned.m16n8k16.row.col.f32.bf16.bf16.f32 "
                 "{%0,%1,%2,%3}, {%4,%5,%6,%7}, {%8,%9}, {%0,%1,%2,%3};"
                 : "+f"(d[0]), "+f"(d[1]), "+f"(d[2]), "+f"(d[3])
                 : "r"(a[0]), "r"(a[1]), "r"(a[2]), "r"(a[3]), "r"(b[0]), "r"(b[1]));
}

__global__ __launch_bounds__(256) void k_gemm1t(float* __restrict__ Cp) {
    extern __shared__ __align__(16) char smraw[];   // 2 bufs * 4 arrays * SMT = 80KB
    uint32_t sbase;
    asm("{ .reg .u64 t; cvta.to.shared.u64 t, %1; cvt.u32.u64 %0, t; }"
        : "=r"(sbase) : "l"(smraw));
    int tid = threadIdx.x;
    int p0 = blockIdx.x * 128, o0 = blockIdx.y * 128;
    int kbeg = blockIdx.z * KCHUNK;
    int kend = min(16000, kbeg + KCHUNK);
    int nk = (kend - kbeg) >> 5;
    int wid = tid >> 5, lane = tid & 31;
    int wm = wid >> 2, wn = wid & 3;                // warp tile: 64x32

    // stage loader: 4 arrays (Yh,Yl,Wh,Wl), 128 rows x 4 chunks of 16B each
    auto load_stage = [&](int it, int buf) {
        int kpos = kbeg + it * 32;
        uint32_t bb = sbase + buf * (4 * SMT);
        #pragma unroll
        for (int x = 0; x < 8; x++) {
            const int arr = x >> 1;                 // compile-time per unrolled x
            int idx = tid + x * 256;
            int rem = idx & 511;
            int row = rem >> 2, ch = rem & 3;
            const __nv_bfloat16* g;
            if (arr == 0)      g = g_Yh + (size_t)(p0 + row) * 16000;
            else if (arr == 1) g = g_Yl + (size_t)(p0 + row) * 16000;
            else if (arr == 2) g = g_Wh + (size_t)(o0 + row) * 16000;
            else               g = g_Wl + (size_t)(o0 + row) * 16000;
            const void* src = (const void*)(g + kpos + ch * 8);
            uint32_t dst = bb + arr * SMT + row * 80 + ch * 16;
            asm volatile("cp.async.cg.shared.global [%0], [%1], 16;" :: "r"(dst), "l"(src));
        }
        asm volatile("cp.async.commit_group;");
    };

    float acc[4][4][4];
    #pragma unroll
    for (int i = 0; i < 4; i++)
        #pragma unroll
        for (int j = 0; j < 4; j++)
            #pragma unroll
            for (int k = 0; k < 4; k++) acc[i][j][k] = 0.0f;

    load_stage(0, 0);
    for (int it = 0; it < nk; it++) {
        bool more = (it + 1) < nk;
        if (more) {
            load_stage(it + 1, (it + 1) & 1);
            asm volatile("cp.async.wait_group 1;" ::: "memory");
        } else {
            asm volatile("cp.async.wait_group 0;" ::: "memory");
        }
        __syncthreads();
        uint32_t bb = sbase + (it & 1) * (4 * SMT);
        #pragma unroll
        for (int kk = 0; kk < 2; kk++) {           // two k16 halves of BK=32
            uint32_t ah[4][4], al[4][4], bh[4][2], bl[4][2];
            uint32_t chA = kk * 2 + (lane >> 4);
            #pragma unroll
            for (int mt = 0; mt < 4; mt++) {
                uint32_t r = wm * 64 + mt * 16 + (lane & 15);
                ldmx4(ah[mt], bb + 0 * SMT + r * 80 + chA * 16);
                ldmx4(al[mt], bb + 1 * SMT + r * 80 + chA * 16);
            }
            uint32_t chB = kk * 2 + ((lane >> 3) & 1);
            #pragma unroll
            for (int nt = 0; nt < 4; nt++) {
                uint32_t r = wn * 32 + nt * 8 + (lane & 7);
                ldmx2(bh[nt], bb + 2 * SMT + r * 80 + chB * 16);
                ldmx2(bl[nt], bb + 3 * SMT + r * 80 + chB * 16);
            }
            #pragma unroll
            for (int mt = 0; mt < 4; mt++)
                #pragma unroll
                for (int nt = 0; nt < 4; nt++) {
                    mma16816(acc[mt][nt], ah[mt], bh[nt]);
                    mma16816(acc[mt][nt], ah[mt], bl[nt]);
                    mma16816(acc[mt][nt], al[mt], bh[nt]);
                }
        }
        __syncthreads();
    }

    float* cp = Cp + (size_t)blockIdx.z * PPOS * 512;
    int tq = lane >> 2, t2 = (lane & 3) * 2;
    #pragma unroll
    for (int mt = 0; mt < 4; mt++)
        #pragma unroll
        for (int nt = 0; nt < 4; nt++) {
            int o = o0 + wn * 32 + nt * 8 + t2;
            int pA = p0 + wm * 64 + mt * 16 + tq;
            if (pA < PPOS) {
                float* d = cp + (size_t)pA * 512 + o;
                d[0] = acc[mt][nt][0]; d[1] = acc[mt][nt][1];
            }
            int pB = pA + 8;
            if (pB < PPOS) {
                float* d = cp + (size_t)pB * 512 + o;
                d[0] = acc[mt][nt][2]; d[1] = acc[mt][nt][3];
            }
        }
}

// -------- attention: sum partials + bias + relu, conv2, softmax(49), pooling -
__global__ void k_attn(const float* __restrict__ b1, const float* __restrict__ w2,
                       const float* __restrict__ b2, const float* __restrict__ img) {
    __shared__ float slog[49];
    __shared__ float sw[49];
    int b = blockIdx.x, tid = threadIdx.x;
    int warp = tid >> 5, lane = tid & 31;
    for (int q = warp; q < 49; q += 8) {
        float acc = 0.0f;
        const float* c0 = g_Cpart + (size_t)(b * 49 + q) * 512;
        for (int o = lane; o < 512; o += 32) {
            float z = b1[o];
            #pragma unroll
            for (int s = 0; s < NSPLIT; s++) z += c0[(size_t)s * PPOS * 512 + o];
            z = fmaxf(z, 0.0f);
            acc += z * w2[o];
        }
        #pragma unroll
        for (int o = 16; o; o >>= 1) acc += __shfl_xor_sync(0xffffffffu, acc, o);
        if (lane == 0) slog[q] = acc + b2[0];
    }
    __syncthreads();
    if (tid == 0) {
        float mx = -1e30f;
        for (int q = 0; q < 49; q++) mx = fmaxf(mx, slog[q]);
        float sum = 0.0f;
        for (int q = 0; q < 49; q++) { float e = expf(slog[q] - mx); sw[q] = e; sum += e; }
        float inv = 1.0f / sum;
        for (int q = 0; q < 49; q++) sw[q] *= inv;
    }
    __syncthreads();
    // faithful to torch .view(bs,49,-1) on NCHW-contiguous img: flat addressing
    const float* ib = img + (size_t)b * 100352;
    for (int c = tid; c < 2048; c += blockDim.x) {
        float acc = 0.0f;
        #pragma unroll
        for (int q = 0; q < 49; q++) acc += sw[q] * ib[q * 2048 + c];
        g_res[b * 2048 + c] = acc;
    }
}

// -------- final GEMM partials: Fp[z][b][o] = sum_{k-chunk} Yb[b,k]*W[o,k] -----
__global__ __launch_bounds__(256) void k_final(const float* __restrict__ W) {
    __shared__ __align__(16) float Ws[16][132];
    __shared__ __align__(16) float Ys[16][36];
    int tid = threadIdx.x;
    int o0 = blockIdx.x * 128;
    int z = blockIdx.y;
    int ty = tid >> 5, tx = tid & 31;
    float acc[4][4];
    #pragma unroll
    for (int i = 0; i < 4; i++)
        #pragma unroll
        for (int j = 0; j < 4; j++) acc[i][j] = 0.0f;

    int kq = (tid & 3) * 4;
    int orow = tid >> 2;
    int brow = tid >> 2;

    for (int it = 0; it < 125; it++) {
        int k0 = z * 2000 + it * 16;
        if (brow < 32) {
            float4 f = *(const float4*)(g_Yb + (size_t)brow * 16000 + k0 + kq);
            Ys[kq + 0][brow] = f.x; Ys[kq + 1][brow] = f.y;
            Ys[kq + 2][brow] = f.z; Ys[kq + 3][brow] = f.w;
        }
        #pragma unroll
        for (int rr = 0; rr < 2; rr++) {
            int o = o0 + orow + rr * 64;
            float4 f = (o < 3000) ? *(const float4*)(W + (size_t)o * 16000 + k0 + kq)
                                  : make_float4(0, 0, 0, 0);
            Ws[kq + 0][orow + rr * 64] = f.x; Ws[kq + 1][orow + rr * 64] = f.y;
            Ws[kq + 2][orow + rr * 64] = f.z; Ws[kq + 3][orow + rr * 64] = f.w;
        }
        __syncthreads();
        #pragma unroll
        for (int kk = 0; kk < 16; kk++) {
            float a[4], b[4];
            *(float4*)a = *(const float4*)&Ys[kk][ty * 4];
            *(float4*)b = *(const float4*)&Ws[kk][tx * 4];
            #pragma unroll
            for (int i = 0; i < 4; i++)
                #pragma unroll
                for (int j = 0; j < 4; j++) acc[i][j] += a[i] * b[j];
        }
        __syncthreads();
    }

    float* fp = g_Fpart + (size_t)z * 32 * 3000;
    #pragma unroll
    for (int i = 0; i < 4; i++) {
        int b = ty * 4 + i;
        #pragma unroll
        for (int j = 0; j < 4; j++) {
            int o = o0 + tx * 4 + j;
            if (o < 3000) fp[(size_t)b * 3000 + o] = acc[i][j];
        }
    }
}

// -------- reduce final partials + bias -> d_out ------------------------------
__global__ void k_finred(const float* __restrict__ bias, float* __restrict__ out) {
    int i = blockIdx.x * blockDim.x + threadIdx.x;
    if (i < 32 * 3000) {
        int o = i % 3000;
        float s = bias[o];
        #pragma unroll
        for (int zz = 0; zz < FSPLIT; zz++) s += g_Fpart[(size_t)zz * 32 * 3000 + i];
        out[i] = s;
    }
}

extern "C" void kernel_launch(void* const* d_in, const int* in_sizes, int n_in,
                              void* d_out, int out_size) {
    const float* txt     = (const float*)d_in[0];
    const float* img     = (const float*)d_in[1];
    const float* conv1_w = (const float*)d_in[2];
    const float* conv1_b = (const float*)d_in[3];
    const float* conv2_w = (const float*)d_in[4];
    const float* conv2_b = (const float*)d_in[5];
    const float* lin2_w  = (const float*)d_in[6];
    const float* lin2_b  = (const float*)d_in[7];
    const int* h1a = (const int*)d_in[8];
    const int* s1a = (const int*)d_in[9];
    const int* h2a = (const int*)d_in[10];
    const int* s2a = (const int*)d_in[11];
    const int* h1b = (const int*)d_in[12];
    const int* s1b = (const int*)d_in[13];
    const int* h2b = (const int*)d_in[14];
    const int* s2b = (const int*)d_in[15];
    float* out = (float*)d_out;

    const int SMEMB = (2 * N_FFT + 32) * sizeof(float);
    const int SMEMG = 2 * 4 * SMT;   // 80KB
    cudaFuncSetAttribute(k_cbp, cudaFuncAttributeMaxDynamicSharedMemorySize, SMEMB);
    cudaFuncSetAttribute(k_gemm1t, cudaFuncAttributeMaxDynamicSharedMemorySize, SMEMG);

    float* ybptr; cudaGetSymbolAddress((void**)&ybptr, g_Yb);
    float* cpptr; cudaGetSymbolAddress((void**)&cpptr, g_Cpart);
    float* tpptr; cudaGetSymbolAddress((void**)&tpptr, g_txtp);
    float* itptr; cudaGetSymbolAddress((void**)&itptr, g_imgt);
    float* rsptr; cudaGetSymbolAddress((void**)&rsptr, g_res);
    __nv_bfloat16* yhptr; cudaGetSymbolAddress((void**)&yhptr, g_Yh);
    __nv_bfloat16* ylptr; cudaGetSymbolAddress((void**)&ylptr, g_Yl);

    k_txtp<<<32, 256>>>(txt);
    k_imgt<<<PPOS, 256>>>(img);
    k_wsplit<<<(512 * N_FFT + 255) / 256, 256>>>(conv1_w);
    k_padY<<<((PPAD - PPOS) * N_FFT + 255) / 256, 256>>>();

    // CBP layer A: fused, per spatial position; writes split bf16 hi/lo
    k_cbp<<<PPOS, TCBP, SMEMB>>>(tpptr, itptr, 0, h1a, s1a, h2a, s2a,
                                 nullptr, yhptr, ylptr);

    // conv1 on tensor cores (split-K) + attention
    dim3 g1(PPAD / 128, 4, NSPLIT);
    k_gemm1t<<<g1, 256, SMEMG>>>(cpptr);
    k_attn<<<32, 256>>>(conv1_b, conv2_w, conv2_b, img);

    // CBP layer B, per batch; fp32 output
    k_cbp<<<32, TCBP, SMEMB>>>(tpptr, rsptr, 1, h1b, s1b, h2b, s2b,
                               ybptr, nullptr, nullptr);

    // final linear
    dim3 gf(24, FSPLIT);
    k_final<<<gf, 256>>>(lin2_w);
    k_finred<<<(32 * 3000 + 255) / 256, 256>>>(lin2_b, out);
}

// round 11
// speedup vs baseline: 3.2255x; 1.0438x over previous
#include <cuda_runtime.h>
#include <cuda_bf16.h>
#include <math.h>
#include <stdint.h>

#define N_FFT 16000
#define PPOS  1568
#define PPAD  1664            // 13 * 128
#define NSPLIT 6
#define KCHUNK 2688           // divisible by 32; 5*2688 + 2560 = 16000
#define FSPLIT 8
#define TCBP   1024
#define SMT    10240          // bytes per smem tile array: 128 rows * 80B

// -------- device scratch (allocation-free rule: __device__ globals) --------
__device__ float g_txtp[32 * 2048];
__device__ __align__(16) float g_imgt[(size_t)PPOS * 2048];
__device__ __align__(16) __nv_bfloat16 g_Yh[(size_t)PPAD * N_FFT];
__device__ __align__(16) __nv_bfloat16 g_Yl[(size_t)PPAD * N_FFT];
__device__ __align__(16) __nv_bfloat16 g_Wh[(size_t)512 * N_FFT];
__device__ __align__(16) __nv_bfloat16 g_Wl[(size_t)512 * N_FFT];
__device__ float g_Cpart[(size_t)NSPLIT * PPOS * 512];
__device__ float g_res[32 * 2048];
__device__ __align__(16) float g_Yb[(size_t)32 * N_FFT];
__device__ float g_Fpart[(size_t)FSPLIT * 32 * 3000];

__constant__ float W5C[5] = {1.0f, 0.30901699437494742f, -0.80901699437494745f,
                             -0.80901699437494745f, 0.30901699437494742f};
__constant__ float W5S[5] = {0.0f, 0.95105651629515353f, 0.58778525229247314f,
                             -0.58778525229247314f, -0.95105651629515353f};
// W10^k = exp(-2*pi*i*k/10) = (W10C[k], -W10S[k])
__constant__ float W10C[5] = {1.0f, 0.80901699437494745f, 0.30901699437494742f,
                              -0.30901699437494742f, -0.80901699437494745f};
__constant__ float W10S[5] = {0.0f, 0.58778525229247314f, 0.95105651629515353f,
                              0.95105651629515353f, 0.58778525229247314f};

// -------- txt avgpool (3,3) s(100,1) p(1,1) count_include_pad -> (32,2048) ----
__global__ void k_txtp(const float* __restrict__ txt) {
    int b = blockIdx.x;
    const float* base = txt + (size_t)b * 50 * 2048;
    for (int j = threadIdx.x; j < 2048; j += blockDim.x) {
        float sum = 0.0f;
        #pragma unroll
        for (int r = 0; r < 2; r++)
            #pragma unroll
            for (int dj = -1; dj <= 1; dj++) {
                int jj = j + dj;
                if (jj >= 0 && jj < 2048) sum += base[r * 2048 + jj];
            }
        g_txtp[b * 2048 + j] = sum * (1.0f / 9.0f);
    }
}

// -------- tiled transpose img NCHW -> rows (b*49+q, c), both sides coalesced -
__global__ void k_imgt(const float* __restrict__ img) {
    __shared__ float tile[64][51];   // gcd(51,32)=1 -> conflict-free
    int b = blockIdx.y;
    int c0 = blockIdx.x * 64;
    int tid = threadIdx.x;
    const float* ib = img + (size_t)b * 2048 * 49;
    for (int idx = tid; idx < 64 * 49; idx += blockDim.x) {
        int cc = idx / 49, q = idx - cc * 49;
        tile[cc][q] = ib[(size_t)(c0 + cc) * 49 + q];
    }
    __syncthreads();
    for (int idx = tid; idx < 64 * 49; idx += blockDim.x) {
        int q = idx >> 6, cc = idx & 63;
        g_imgt[(size_t)(b * 49 + q) * 2048 + c0 + cc] = tile[cc][q];
    }
}

// -------- split conv1_w into bf16 hi/lo -------------------------------------
__global__ void k_wsplit(const float* __restrict__ W) {
    size_t i = (size_t)blockIdx.x * blockDim.x + threadIdx.x;
    if (i < (size_t)512 * N_FFT) {
        float w = W[i];
        __nv_bfloat16 h = __float2bfloat16(w);
        g_Wh[i] = h;
        g_Wl[i] = __float2bfloat16(w - __bfloat162float(h));
    }
}

// -------- one mixed-radix stage on smem, compile-time L/R/DIR ----------------
// DIR>0: DIF forward (butterfly then twiddle), scrambled output.
// DIR<0: transposed network (conj twiddle then inverse butterfly), reverse order.
// R==10 is only used at L==10 (m==1, j==0): twiddle-free DFT-10 via even/odd
// split into two DFT-5s + W10-constant combine (no sincosf).
template<int L, int R, int DIR>
__device__ __forceinline__ void fft_stage_t(float* re, float* im, int tid) {
    constexpr int m = L / R;
    constexpr int nb = N_FFT / R;
    const float invL = 1.0f / (float)L;
    for (int i = tid; i < nb; i += TCBP) {
        if (R == 10) {
            int base = i * 10;                       // m==1
            float xr[10], xi[10];
            #pragma unroll
            for (int q = 0; q < 10; q++) { xr[q] = re[base + q]; xi[q] = im[base + q]; }
            float Er[5], Ei[5], Or[5], Oi[5];
            #pragma unroll
            for (int k = 0; k < 5; k++) {
                float er = 0.0f, ei = 0.0f, og = 0.0f, oh = 0.0f;
                #pragma unroll
                for (int t = 0; t < 5; t++) {
                    int e = (k * t) % 5;
                    float C = W5C[e], S = W5S[e];
                    if (DIR > 0) {                   // * e^{-i th}
                        er += xr[2 * t] * C + xi[2 * t] * S;
                        ei += xi[2 * t] * C - xr[2 * t] * S;
                        og += xr[2 * t + 1] * C + xi[2 * t + 1] * S;
                        oh += xi[2 * t + 1] * C - xr[2 * t + 1] * S;
                    } else {                         // * e^{+i th}
                        er += xr[2 * t] * C - xi[2 * t] * S;
                        ei += xi[2 * t] * C + xr[2 * t] * S;
                        og += xr[2 * t + 1] * C - xi[2 * t + 1] * S;
                        oh += xi[2 * t + 1] * C + xr[2 * t + 1] * S;
                    }
                }
                Er[k] = er; Ei[k] = ei; Or[k] = og; Oi[k] = oh;
            }
            #pragma unroll
            for (int k = 0; k < 5; k++) {
                float C = W10C[k], S = W10S[k];
                float tr, ti;
                if (DIR > 0) { tr = Or[k] * C + Oi[k] * S; ti = Oi[k] * C - Or[k] * S; }
                else         { tr = Or[k] * C - Oi[k] * S; ti = Oi[k] * C + Or[k] * S; }
                re[base + k]     = Er[k] + tr;  im[base + k]     = Ei[k] + ti;
                re[base + k + 5] = Er[k] - tr;  im[base + k + 5] = Ei[k] - ti;
            }
            continue;
        }
        int blk = i / m, j = i - blk * m;            // const-divisor -> IMAD
        float f = (float)j * invL;
        if (f >= 0.5f) f -= 1.0f;
        if (R == 4) {
            int base = blk * L + j;
            float c1, s1;
            __sincosf(-6.28318530717958647692f * f, &s1, &c1);
            float c2 = c1 * c1 - s1 * s1, s2 = 2.0f * c1 * s1;
            float c3 = c2 * c1 - s2 * s1, s3 = c2 * s1 + s2 * c1;
            float u0r = re[base],         u0i = im[base];
            float u1r = re[base + m],     u1i = im[base + m];
            float u2r = re[base + 2 * m], u2i = im[base + 2 * m];
            float u3r = re[base + 3 * m], u3i = im[base + 3 * m];
            if (DIR > 0) {
                float t0r = u0r + u2r, t0i = u0i + u2i;
                float t1r = u0r - u2r, t1i = u0i - u2i;
                float t2r = u1r + u3r, t2i = u1i + u3i;
                float t3r = u1r - u3r, t3i = u1i - u3i;
                re[base] = t0r + t2r;  im[base] = t0i + t2i;
                float v1r = t1r + t3i, v1i = t1i - t3r;   // t1 - i t3
                float v2r = t0r - t2r, v2i = t0i - t2i;
                float v3r = t1r - t3i, v3i = t1i + t3r;   // t1 + i t3
                re[base + m]     = v1r * c1 - v1i * s1; im[base + m]     = v1r * s1 + v1i * c1;
                re[base + 2 * m] = v2r * c2 - v2i * s2; im[base + 2 * m] = v2r * s2 + v2i * c2;
                re[base + 3 * m] = v3r * c3 - v3i * s3; im[base + 3 * m] = v3r * s3 + v3i * c3;
            } else {
                float a1r = u1r * c1 + u1i * s1, a1i = u1i * c1 - u1r * s1;
                float a2r = u2r * c2 + u2i * s2, a2i = u2i * c2 - u2r * s2;
                float a3r = u3r * c3 + u3i * s3, a3i = u3i * c3 - u3r * s3;
                float t0r = u0r + a2r, t0i = u0i + a2i;
                float t1r = u0r - a2r, t1i = u0i - a2i;
                float t2r = a1r + a3r, t2i = a1i + a3i;
                float t3r = a1r - a3r, t3i = a1i - a3i;
                re[base] = t0r + t2r;  im[base] = t0i + t2i;
                re[base + m]     = t1r - t3i; im[base + m]     = t1i + t3r;  // t1 + i t3
                re[base + 2 * m] = t0r - t2r; im[base + 2 * m] = t0i - t2i;
                re[base + 3 * m] = t1r + t3i; im[base + 3 * m] = t1i - t3r;  // t1 - i t3
            }
        } else {  // R == 5
            int base = blk * L + j;
            float w1r, w1i;
            __sincosf(-6.28318530717958647692f * f, &w1i, &w1r);
            float ur[5], ui[5];
            if (DIR > 0) {
                #pragma unroll
                for (int q = 0; q < 5; q++) { ur[q] = re[base + q * m]; ui[q] = im[base + q * m]; }
                float cwr = 1.0f, cwi = 0.0f;   // running twiddle W^{jq}
                #pragma unroll
                for (int q = 0; q < 5; q++) {
                    float vr = 0.0f, vi = 0.0f;
                    #pragma unroll
                    for (int t = 0; t < 5; t++) {
                        int e = (q * t) % 5;
                        float C = W5C[e], S = W5S[e];       // * e^{-i th}
                        vr += ur[t] * C + ui[t] * S;
                        vi += ui[t] * C - ur[t] * S;
                    }
                    re[base + q * m] = vr * cwr - vi * cwi;
                    im[base + q * m] = vr * cwi + vi * cwr;
                    float nr = cwr * w1r - cwi * w1i;
                    cwi = cwr * w1i + cwi * w1r; cwr = nr;
                }
            } else {
                float cwr = 1.0f, cwi = 0.0f;
                #pragma unroll
                for (int q = 0; q < 5; q++) {
                    float a = re[base + q * m], b2 = im[base + q * m];
                    ur[q] = a * cwr + b2 * cwi;             // * conj(W^{jq})
                    ui[q] = b2 * cwr - a * cwi;
                    float nr = cwr * w1r - cwi * w1i;
                    cwi = cwr * w1i + cwi * w1r; cwr = nr;
                }
                #pragma unroll
                for (int t = 0; t < 5; t++) {
                    float vr = 0.0f, vi = 0.0f;
                    #pragma unroll
                    for (int q = 0; q < 5; q++) {
                        int e = (q * t) % 5;
                        float C = W5C[e], S = W5S[e];       // * e^{+i th}
                        vr += ur[q] * C - ui[q] * S;
                        vi += ui[q] * C + ur[q] * S;
                    }
                    re[base + t * m] = vr; im[base + t * m] = vi;
                }
            }
        }
    }
}

// plan {4,4,4,5,5,10}: 16000 -> 4000 -> 1000 -> 250 -> 50 -> 10 -> 1
__device__ __forceinline__ void fft_fwd(float* re, float* im, int tid) {
    fft_stage_t<16000, 4, 1>(re, im, tid); __syncthreads();
    fft_stage_t<4000, 4, 1>(re, im, tid);  __syncthreads();
    fft_stage_t<1000, 4, 1>(re, im, tid);  __syncthreads();
    fft_stage_t<250, 5, 1>(re, im, tid);   __syncthreads();
    fft_stage_t<50, 5, 1>(re, im, tid);    __syncthreads();
    fft_stage_t<10, 10, 1>(re, im, tid);   __syncthreads();
}
__device__ __forceinline__ void fft_inv(float* re, float* im, int tid) {
    fft_stage_t<10, 10, -1>(re, im, tid);   __syncthreads();
    fft_stage_t<50, 5, -1>(re, im, tid);    __syncthreads();
    fft_stage_t<250, 5, -1>(re, im, tid);   __syncthreads();
    fft_stage_t<1000, 4, -1>(re, im, tid);  __syncthreads();
    fft_stage_t<4000, 4, -1>(re, im, tid);  __syncthreads();
    fft_stage_t<16000, 4, -1>(re, im, tid); __syncthreads();
}

// -------- fused CBP: z = s1 + i*s2; FFT; Z^2; IFFT; Im/(2N); ssqrt; l2norm ---
// mode 0 (layer A): sketch1 from tiled txt_p, sketch2 from src2 rows;
//                   output split bf16 hi/lo (feeds tensor-core GEMM).
// mode 1 (layer B): both plain rows; output fp32 Yout.
__global__ __launch_bounds__(TCBP, 1) void k_cbp(
    const float* __restrict__ src1, const float* __restrict__ src2, int mode,
    const int* __restrict__ h1, const int* __restrict__ s1,
    const int* __restrict__ h2, const int* __restrict__ s2,
    float* __restrict__ Yout, __nv_bfloat16* __restrict__ YoutH,
    __nv_bfloat16* __restrict__ YoutL) {
    extern __shared__ float sm[];
    float* re = sm;
    float* im = sm + N_FFT;
    float* red = sm + 2 * N_FFT;
    int tid = threadIdx.x, p = blockIdx.x;
    for (int d = tid; d < N_FFT; d += TCBP) { re[d] = 0.0f; im[d] = 0.0f; }
    __syncthreads();
    if (mode == 0) {
        int b = p / 49, q = p - 49 * b;
        const float* tp = src1 + (size_t)b * 2048;
        const float* x2 = src2 + (size_t)p * 2048;
        for (int c = tid; c < 2048; c += TCBP) {
            float v = tp[(49 * c + q) & 2047];
            v = (s1[c] > 0) ? v : -v;
            atomicAdd(&re[h1[c]], v);
            float w = x2[c];
            w = (s2[c] > 0) ? w : -w;
            atomicAdd(&im[h2[c]], w);
        }
    } else {
        const float* x1 = src1 + (size_t)p * 2048;
        const float* x2 = src2 + (size_t)p * 2048;
        for (int c = tid; c < 2048; c += TCBP) {
            float v = x1[c];
            v = (s1[c] > 0) ? v : -v;
            atomicAdd(&re[h1[c]], v);
            float w = x2[c];
            w = (s2[c] > 0) ? w : -w;
            atomicAdd(&im[h2[c]], w);
        }
    }
    __syncthreads();
    fft_fwd(re, im, tid);              // scrambled Z
    for (int d = tid; d < N_FFT; d += TCBP) {
        float a = re[d], b2 = im[d];   // Z^2 (pointwise, order-agnostic)
        re[d] = a * a - b2 * b2;
        im[d] = 2.0f * a * b2;
    }
    __syncthreads();
    fft_inv(re, im, tid);              // natural-order unnormalized IDFT
    const float sc0 = 0.5f / (float)N_FFT;   // Im/(2N) = a (*) b
    float ss = 0.0f;
    for (int d = tid; d < N_FFT; d += TCBP) {
        float v = im[d] * sc0;
        float y = copysignf(sqrtf(fabsf(v)), v);
        im[d] = y;
        ss += y * y;
    }
    #pragma unroll
    for (int o = 16; o; o >>= 1) ss += __shfl_xor_sync(0xffffffffu, ss, o);
    if ((tid & 31) == 0) red[tid >> 5] = ss;
    __syncthreads();
    if (tid == 0) {
        float tot = 0.0f;
        for (int i = 0; i < TCBP / 32; i++) tot += red[i];
        red[0] = 1.0f / fmaxf(sqrtf(tot), 1e-12f);
    }
    __syncthreads();
    float sc = red[0];
    if (mode == 0) {
        __nv_bfloat16* yh = YoutH + (size_t)p * N_FFT;
        __nv_bfloat16* yl = YoutL + (size_t)p * N_FFT;
        for (int d = tid; d < N_FFT; d += TCBP) {
            float y = im[d] * sc;
            __nv_bfloat16 h = __float2bfloat16(y);
            yh[d] = h;
            yl[d] = __float2bfloat16(y - __bfloat162float(h));
        }
    } else {
        float* yo = Yout + (size_t)p * N_FFT;
        for (int d = tid; d < N_FFT; d += TCBP) yo[d] = im[d] * sc;
    }
}

// -------- conv1 GEMM on tensor cores, split-bf16 (hi*hi + hi*lo + lo*hi) -----
__device__ __forceinline__ void ldmx4(uint32_t* r, uint32_t a) {
    asm volatile("ldmatrix.sync.aligned.m8n8.x4.shared.b16 {%0,%1,%2,%3}, [%4];"
                 : "=r"(r[0]), "=r"(r[1]), "=r"(r[2]), "=r"(r[3]) : "r"(a));
}
__device__ __forceinline__ void ldmx2(uint32_t* r, uint32_t a) {
    asm volatile("ldmatrix.sync.aligned.m8n8.x2.shared.b16 {%0,%1}, [%2];"
                 : "=r"(r[0]), "=r"(r[1]) : "r"(a));
}
__device__ __forceinline__ void mma16816(float* d, const uint32_t* a, const uint32_t* b) {
    asm volatile("mma.sync.aligned.m16n8k16.row.col.f32.bf16.bf16.f32 "
                 "{%0,%1,%2,%3}, {%4,%5,%6,%7}, {%8,%9}, {%0,%1,%2,%3};"
                 : "+f"(d[0]), "+f"(d[1]), "+f"(d[2]), "+f"(d[3])
                 : "r"(a[0]), "r"(a[1]), "r"(a[2]), "r"(a[3]), "r"(b[0]), "r"(b[1]));
}

__global__ __launch_bounds__(256) void k_gemm1t(float* __restrict__ Cp) {
    extern __shared__ __align__(16) char smraw[];   // 2 bufs * 4 arrays * SMT = 80KB
    uint32_t sbase;
    asm("{ .reg .u64 t; cvta.to.shared.u64 t, %1; cvt.u32.u64 %0, t; }"
        : "=r"(sbase) : "l"(smraw));
    int tid = threadIdx.x;
    int p0 = blockIdx.x * 128, o0 = blockIdx.y * 128;
    int kbeg = blockIdx.z * KCHUNK;
    int kend = min(16000, kbeg + KCHUNK);
    int nk = (kend - kbeg) >> 5;
    int wid = tid >> 5, lane = tid & 31;
    int wm = wid >> 2, wn = wid & 3;                // warp tile: 64x32

    // stage loader: 4 arrays (Yh,Yl,Wh,Wl), 128 rows x 4 chunks of 16B each.
    // Y rows >= PPOS are zero-filled via cp.async src-size=0 (no pad kernel).
    auto load_stage = [&](int it, int buf) {
        int kpos = kbeg + it * 32;
        uint32_t bb = sbase + buf * (4 * SMT);
        #pragma unroll
        for (int x = 0; x < 8; x++) {
            const int arr = x >> 1;                 // compile-time per unrolled x
            int idx = tid + x * 256;
            int rem = idx & 511;
            int row = rem >> 2, ch = rem & 3;
            const __nv_bfloat16* g;
            int sz = 16;
            if (arr == 0)      { g = g_Yh + (size_t)(p0 + row) * 16000;
                                 if (p0 + row >= PPOS) sz = 0; }
            else if (arr == 1) { g = g_Yl + (size_t)(p0 + row) * 16000;
                                 if (p0 + row >= PPOS) sz = 0; }
            else if (arr == 2) g = g_Wh + (size_t)(o0 + row) * 16000;
            else               g = g_Wl + (size_t)(o0 + row) * 16000;
            const void* src = (const void*)(g + kpos + ch * 8);
            uint32_t dst = bb + arr * SMT + row * 80 + ch * 16;
            asm volatile("cp.async.cg.shared.global [%0], [%1], 16, %2;"
                         :: "r"(dst), "l"(src), "r"(sz));
        }
        asm volatile("cp.async.commit_group;");
    };

    float acc[4][4][4];
    #pragma unroll
    for (int i = 0; i < 4; i++)
        #pragma unroll
        for (int j = 0; j < 4; j++)
            #pragma unroll
            for (int k = 0; k < 4; k++) acc[i][j][k] = 0.0f;

    load_stage(0, 0);
    for (int it = 0; it < nk; it++) {
        bool more = (it + 1) < nk;
        if (more) {
            load_stage(it + 1, (it + 1) & 1);
            asm volatile("cp.async.wait_group 1;" ::: "memory");
        } else {
            asm volatile("cp.async.wait_group 0;" ::: "memory");
        }
        __syncthreads();
        uint32_t bb = sbase + (it & 1) * (4 * SMT);
        #pragma unroll
        for (int kk = 0; kk < 2; kk++) {           // two k16 halves of BK=32
            uint32_t ah[4][4], al[4][4], bh[4][2], bl[4][2];
            uint32_t chA = kk * 2 + (lane >> 4);
            #pragma unroll
            for (int mt = 0; mt < 4; mt++) {
                uint32_t r = wm * 64 + mt * 16 + (lane & 15);
                ldmx4(ah[mt], bb + 0 * SMT + r * 80 + chA * 16);
                ldmx4(al[mt], bb + 1 * SMT + r * 80 + chA * 16);
            }
            uint32_t chB = kk * 2 + ((lane >> 3) & 1);
            #pragma unroll
            for (int nt = 0; nt < 4; nt++) {
                uint32_t r = wn * 32 + nt * 8 + (lane & 7);
                ldmx2(bh[nt], bb + 2 * SMT + r * 80 + chB * 16);
                ldmx2(bl[nt], bb + 3 * SMT + r * 80 + chB * 16);
            }
            #pragma unroll
            for (int mt = 0; mt < 4; mt++)
                #pragma unroll
                for (int nt = 0; nt < 4; nt++) {
                    mma16816(acc[mt][nt], ah[mt], bh[nt]);
                    mma16816(acc[mt][nt], ah[mt], bl[nt]);
                    mma16816(acc[mt][nt], al[mt], bh[nt]);
                }
        }
        __syncthreads();
    }

    float* cp = Cp + (size_t)blockIdx.z * PPOS * 512;
    int tq = lane >> 2, t2 = (lane & 3) * 2;
    #pragma unroll
    for (int mt = 0; mt < 4; mt++)
        #pragma unroll
        for (int nt = 0; nt < 4; nt++) {
            int o = o0 + wn * 32 + nt * 8 + t2;
            int pA = p0 + wm * 64 + mt * 16 + tq;
            if (pA < PPOS) {
                float* d = cp + (size_t)pA * 512 + o;
                d[0] = acc[mt][nt][0]; d[1] = acc[mt][nt][1];
            }
            int pB = pA + 8;
            if (pB < PPOS) {
                float* d = cp + (size_t)pB * 512 + o;
                d[0] = acc[mt][nt][2]; d[1] = acc[mt][nt][3];
            }
        }
}

// -------- attention: sum partials + bias + relu, conv2, softmax(49), pooling -
__global__ void k_attn(const float* __restrict__ b1, const float* __restrict__ w2,
                       const float* __restrict__ b2, const float* __restrict__ img) {
    __shared__ float slog[49];
    __shared__ float sw[49];
    int b = blockIdx.x, tid = threadIdx.x;
    int warp = tid >> 5, lane = tid & 31;
    for (int q = warp; q < 49; q += 8) {
        float acc = 0.0f;
        const float* c0 = g_Cpart + (size_t)(b * 49 + q) * 512;
        for (int o = lane; o < 512; o += 32) {
            float z = b1[o];
            #pragma unroll
            for (int s = 0; s < NSPLIT; s++) z += c0[(size_t)s * PPOS * 512 + o];
            z = fmaxf(z, 0.0f);
            acc += z * w2[o];
        }
        #pragma unroll
        for (int o = 16; o; o >>= 1) acc += __shfl_xor_sync(0xffffffffu, acc, o);
        if (lane == 0) slog[q] = acc + b2[0];
    }
    __syncthreads();
    if (tid == 0) {
        float mx = -1e30f;
        for (int q = 0; q < 49; q++) mx = fmaxf(mx, slog[q]);
        float sum = 0.0f;
        for (int q = 0; q < 49; q++) { float e = expf(slog[q] - mx); sw[q] = e; sum += e; }
        float inv = 1.0f / sum;
        for (int q = 0; q < 49; q++) sw[q] *= inv;
    }
    __syncthreads();
    // faithful to torch .view(bs,49,-1) on NCHW-contiguous img: flat addressing
    const float* ib = img + (size_t)b * 100352;
    for (int c = tid; c < 2048; c += blockDim.x) {
        float acc = 0.0f;
        #pragma unroll
        for (int q = 0; q < 49; q++) acc += sw[q] * ib[q * 2048 + c];
        g_res[b * 2048 + c] = acc;
    }
}

// -------- final GEMM partials: Fp[z][b][o] = sum_{k-chunk} Yb[b,k]*W[o,k] -----
__global__ __launch_bounds__(256) void k_final(const float* __restrict__ W) {
    __shared__ __align__(16) float Ws[16][132];
    __shared__ __align__(16) float Ys[16][36];
    int tid = threadIdx.x;
    int o0 = blockIdx.x * 128;
    int z = blockIdx.y;
    int ty = tid >> 5, tx = tid & 31;
    float acc[4][4];
    #pragma unroll
    for (int i = 0; i < 4; i++)
        #pragma unroll
        for (int j = 0; j < 4; j++) acc[i][j] = 0.0f;

    int kq = (tid & 3) * 4;
    int orow = tid >> 2;
    int brow = tid >> 2;

    for (int it = 0; it < 125; it++) {
        int k0 = z * 2000 + it * 16;
        if (brow < 32) {
            float4 f = *(const float4*)(g_Yb + (size_t)brow * 16000 + k0 + kq);
            Ys[kq + 0][brow] = f.x; Ys[kq + 1][brow] = f.y;
            Ys[kq + 2][brow] = f.z; Ys[kq + 3][brow] = f.w;
        }
        #pragma unroll
        for (int rr = 0; rr < 2; rr++) {
            int o = o0 + orow + rr * 64;
            float4 f = (o < 3000) ? *(const float4*)(W + (size_t)o * 16000 + k0 + kq)
                                  : make_float4(0, 0, 0, 0);
            Ws[kq + 0][orow + rr * 64] = f.x; Ws[kq + 1][orow + rr * 64] = f.y;
            Ws[kq + 2][orow + rr * 64] = f.z; Ws[kq + 3][orow + rr * 64] = f.w;
        }
        __syncthreads();
        #pragma unroll
        for (int kk = 0; kk < 16; kk++) {
            float a[4], b[4];
            *(float4*)a = *(const float4*)&Ys[kk][ty * 4];
            *(float4*)b = *(const float4*)&Ws[kk][tx * 4];
            #pragma unroll
            for (int i = 0; i < 4; i++)
                #pragma unroll
                for (int j = 0; j < 4; j++) acc[i][j] += a[i] * b[j];
        }
        __syncthreads();
    }

    float* fp = g_Fpart + (size_t)z * 32 * 3000;
    #pragma unroll
    for (int i = 0; i < 4; i++) {
        int b = ty * 4 + i;
        #pragma unroll
        for (int j = 0; j < 4; j++) {
            int o = o0 + tx * 4 + j;
            if (o < 3000) fp[(size_t)b * 3000 + o] = acc[i][j];
        }
    }
}

// -------- reduce final partials + bias -> d_out ------------------------------
__global__ void k_finred(const float* __restrict__ bias, float* __restrict__ out) {
    int i = blockIdx.x * blockDim.x + threadIdx.x;
    if (i < 32 * 3000) {
        int o = i % 3000;
        float s = bias[o];
        #pragma unroll
        for (int zz = 0; zz < FSPLIT; zz++) s += g_Fpart[(size_t)zz * 32 * 3000 + i];
        out[i] = s;
    }
}

extern "C" void kernel_launch(void* const* d_in, const int* in_sizes, int n_in,
                              void* d_out, int out_size) {
    const float* txt     = (const float*)d_in[0];
    const float* img     = (const float*)d_in[1];
    const float* conv1_w = (const float*)d_in[2];
    const float* conv1_b = (const float*)d_in[3];
    const float* conv2_w = (const float*)d_in[4];
    const float* conv2_b = (const float*)d_in[5];
    const float* lin2_w  = (const float*)d_in[6];
    const float* lin2_b  = (const float*)d_in[7];
    const int* h1a = (const int*)d_in[8];
    const int* s1a = (const int*)d_in[9];
    const int* h2a = (const int*)d_in[10];
    const int* s2a = (const int*)d_in[11];
    const int* h1b = (const int*)d_in[12];
    const int* s1b = (const int*)d_in[13];
    const int* h2b = (const int*)d_in[14];
    const int* s2b = (const int*)d_in[15];
    float* out = (float*)d_out;

    const int SMEMB = (2 * N_FFT + 32) * sizeof(float);
    const int SMEMG = 2 * 4 * SMT;   // 80KB
    cudaFuncSetAttribute(k_cbp, cudaFuncAttributeMaxDynamicSharedMemorySize, SMEMB);
    cudaFuncSetAttribute(k_gemm1t, cudaFuncAttributeMaxDynamicSharedMemorySize, SMEMG);

    float* ybptr; cudaGetSymbolAddress((void**)&ybptr, g_Yb);
    float* cpptr; cudaGetSymbolAddress((void**)&cpptr, g_Cpart);
    float* tpptr; cudaGetSymbolAddress((void**)&tpptr, g_txtp);
    float* itptr; cudaGetSymbolAddress((void**)&itptr, g_imgt);
    float* rsptr; cudaGetSymbolAddress((void**)&rsptr, g_res);
    __nv_bfloat16* yhptr; cudaGetSymbolAddress((void**)&yhptr, g_Yh);
    __nv_bfloat16* ylptr; cudaGetSymbolAddress((void**)&ylptr, g_Yl);

    k_txtp<<<32, 256>>>(txt);
    dim3 gt(32, 32);
    k_imgt<<<gt, 256>>>(img);
    k_wsplit<<<(512 * N_FFT + 255) / 256, 256>>>(conv1_w);

    // CBP layer A: fused, per spatial position; writes split bf16 hi/lo
    k_cbp<<<PPOS, TCBP, SMEMB>>>(tpptr, itptr, 0, h1a, s1a, h2a, s2a,
                                 nullptr, yhptr, ylptr);

    // conv1 on tensor cores (split-K) + attention
    dim3 g1(PPAD / 128, 4, NSPLIT);
    k_gemm1t<<<g1, 256, SMEMG>>>(cpptr);
    k_attn<<<32, 256>>>(conv1_b, conv2_w, conv2_b, img);

    // CBP layer B, per batch; fp32 output
    k_cbp<<<32, TCBP, SMEMB>>>(tpptr, rsptr, 1, h1b, s1b, h2b, s2b,
                               ybptr, nullptr, nullptr);

    // final linear
    dim3 gf(24, FSPLIT);
    k_final<<<gf, 256>>>(lin2_w);
    k_finred<<<(32 * 3000 + 255) / 256, 256>>>(lin2_b, out);
}

// round 13
// speedup vs baseline: 3.4216x; 1.0608x over previous
#include <cuda_runtime.h>
#include <cuda_bf16.h>
#include <math.h>
#include <stdint.h>

#define N_FFT 16000
#define PPOS  1568
#define PPAD  1664            // 13 * 128
#define NSPLIT 6
#define KCHUNK 2688           // divisible by 32; 5*2688 + 2560 = 16000
#define FSPLIT 10
#define TCBP   1024
#define SMT    10240          // bytes per smem tile array: 128 rows * 80B

// -------- device scratch (allocation-free rule: __device__ globals) --------
__device__ float g_txtp[32 * 2048];
__device__ __align__(16) float g_imgt[(size_t)PPOS * 2048];
__device__ __align__(16) __nv_bfloat16 g_Yh[(size_t)PPAD * N_FFT];
__device__ __align__(16) __nv_bfloat16 g_Yl[(size_t)PPAD * N_FFT];
__device__ __align__(16) __nv_bfloat16 g_Wh[(size_t)512 * N_FFT];
__device__ __align__(16) __nv_bfloat16 g_Wl[(size_t)512 * N_FFT];
__device__ float g_Cpart[(size_t)NSPLIT * PPOS * 512];
__device__ float g_res[32 * 2048];
__device__ __align__(16) float g_Yb[(size_t)32 * N_FFT];
__device__ float g_Fpart[(size_t)FSPLIT * 32 * 3000];

__constant__ float W5C[5] = {1.0f, 0.30901699437494742f, -0.80901699437494745f,
                             -0.80901699437494745f, 0.30901699437494742f};
__constant__ float W5S[5] = {0.0f, 0.95105651629515353f, 0.58778525229247314f,
                             -0.58778525229247314f, -0.95105651629515353f};
// W10^k = exp(-2*pi*i*k/10) = (W10C[k], -W10S[k])
__constant__ float W10C[5] = {1.0f, 0.80901699437494745f, 0.30901699437494742f,
                              -0.30901699437494742f, -0.80901699437494745f};
__constant__ float W10S[5] = {0.0f, 0.58778525229247314f, 0.95105651629515353f,
                              0.95105651629515353f, 0.58778525229247314f};

// -------- txt avgpool (3,3) s(100,1) p(1,1) count_include_pad -> (32,2048) ----
__global__ void k_txtp(const float* __restrict__ txt) {
    int b = blockIdx.x;
    const float* base = txt + (size_t)b * 50 * 2048;
    for (int j = threadIdx.x; j < 2048; j += blockDim.x) {
        float sum = 0.0f;
        #pragma unroll
        for (int r = 0; r < 2; r++)
            #pragma unroll
            for (int dj = -1; dj <= 1; dj++) {
                int jj = j + dj;
                if (jj >= 0 && jj < 2048) sum += base[r * 2048 + jj];
            }
        g_txtp[b * 2048 + j] = sum * (1.0f / 9.0f);
    }
}

// -------- tiled transpose img NCHW -> rows (b*49+q, c), both sides coalesced -
__global__ void k_imgt(const float* __restrict__ img) {
    __shared__ float tile[64][51];   // gcd(51,32)=1 -> conflict-free
    int b = blockIdx.y;
    int c0 = blockIdx.x * 64;
    int tid = threadIdx.x;
    const float* ib = img + (size_t)b * 2048 * 49;
    for (int idx = tid; idx < 64 * 49; idx += blockDim.x) {
        int cc = idx / 49, q = idx - cc * 49;
        tile[cc][q] = ib[(size_t)(c0 + cc) * 49 + q];
    }
    __syncthreads();
    for (int idx = tid; idx < 64 * 49; idx += blockDim.x) {
        int q = idx >> 6, cc = idx & 63;
        g_imgt[(size_t)(b * 49 + q) * 2048 + c0 + cc] = tile[cc][q];
    }
}

// -------- split conv1_w into bf16 hi/lo -------------------------------------
__global__ void k_wsplit(const float* __restrict__ W) {
    size_t i = (size_t)blockIdx.x * blockDim.x + threadIdx.x;
    if (i < (size_t)512 * N_FFT) {
        float w = W[i];
        __nv_bfloat16 h = __float2bfloat16(w);
        g_Wh[i] = h;
        g_Wl[i] = __float2bfloat16(w - __bfloat162float(h));
    }
}

// -------- one mixed-radix stage on smem, compile-time L/R/DIR ----------------
// DIR>0: DIF forward (butterfly then twiddle), scrambled output.
// DIR<0: transposed network (conj twiddle then inverse butterfly), reverse order.
// R==10 only at L==10 (m==1): twiddle-free DFT-10 (even/odd DFT-5 + W10 combine).
template<int L, int R, int DIR>
__device__ __forceinline__ void fft_stage_t(float* re, float* im, int tid) {
    constexpr int m = L / R;
    constexpr int nb = N_FFT / R;
    const float invL = 1.0f / (float)L;
    for (int i = tid; i < nb; i += TCBP) {
        if (R == 10) {
            int base = i * 10;                       // m==1
            float xr[10], xi[10];
            #pragma unroll
            for (int q = 0; q < 10; q++) { xr[q] = re[base + q]; xi[q] = im[base + q]; }
            float Er[5], Ei[5], Or[5], Oi[5];
            #pragma unroll
            for (int k = 0; k < 5; k++) {
                float er = 0.0f, ei = 0.0f, og = 0.0f, oh = 0.0f;
                #pragma unroll
                for (int t = 0; t < 5; t++) {
                    int e = (k * t) % 5;
                    float C = W5C[e], S = W5S[e];
                    if (DIR > 0) {
                        er += xr[2 * t] * C + xi[2 * t] * S;
                        ei += xi[2 * t] * C - xr[2 * t] * S;
                        og += xr[2 * t + 1] * C + xi[2 * t + 1] * S;
                        oh += xi[2 * t + 1] * C - xr[2 * t + 1] * S;
                    } else {
                        er += xr[2 * t] * C - xi[2 * t] * S;
                        ei += xi[2 * t] * C + xr[2 * t] * S;
                        og += xr[2 * t + 1] * C - xi[2 * t + 1] * S;
                        oh += xi[2 * t + 1] * C + xr[2 * t + 1] * S;
                    }
                }
                Er[k] = er; Ei[k] = ei; Or[k] = og; Oi[k] = oh;
            }
            #pragma unroll
            for (int k = 0; k < 5; k++) {
                float C = W10C[k], S = W10S[k];
                float tr, ti;
                if (DIR > 0) { tr = Or[k] * C + Oi[k] * S; ti = Oi[k] * C - Or[k] * S; }
                else         { tr = Or[k] * C - Oi[k] * S; ti = Oi[k] * C + Or[k] * S; }
                re[base + k]     = Er[k] + tr;  im[base + k]     = Ei[k] + ti;
                re[base + k + 5] = Er[k] - tr;  im[base + k + 5] = Ei[k] - ti;
            }
            continue;
        }
        int blk = i / m, j = i - blk * m;            // const-divisor -> IMAD
        float f = (float)j * invL;
        if (f >= 0.5f) f -= 1.0f;
        if (R == 4) {
            int base = blk * L + j;
            float c1, s1;
            __sincosf(-6.28318530717958647692f * f, &s1, &c1);
            float c2 = c1 * c1 - s1 * s1, s2 = 2.0f * c1 * s1;
            float c3 = c2 * c1 - s2 * s1, s3 = c2 * s1 + s2 * c1;
            float u0r = re[base],         u0i = im[base];
            float u1r = re[base + m],     u1i = im[base + m];
            float u2r = re[base + 2 * m], u2i = im[base + 2 * m];
            float u3r = re[base + 3 * m], u3i = im[base + 3 * m];
            if (DIR > 0) {
                float t0r = u0r + u2r, t0i = u0i + u2i;
                float t1r = u0r - u2r, t1i = u0i - u2i;
                float t2r = u1r + u3r, t2i = u1i + u3i;
                float t3r = u1r - u3r, t3i = u1i - u3i;
                re[base] = t0r + t2r;  im[base] = t0i + t2i;
                float v1r = t1r + t3i, v1i = t1i - t3r;   // t1 - i t3
                float v2r = t0r - t2r, v2i = t0i - t2i;
                float v3r = t1r - t3i, v3i = t1i + t3r;   // t1 + i t3
                re[base + m]     = v1r * c1 - v1i * s1; im[base + m]     = v1r * s1 + v1i * c1;
                re[base + 2 * m] = v2r * c2 - v2i * s2; im[base + 2 * m] = v2r * s2 + v2i * c2;
                re[base + 3 * m] = v3r * c3 - v3i * s3; im[base + 3 * m] = v3r * s3 + v3i * c3;
            } else {
                float a1r = u1r * c1 + u1i * s1, a1i = u1i * c1 - u1r * s1;
                float a2r = u2r * c2 + u2i * s2, a2i = u2i * c2 - u2r * s2;
                float a3r = u3r * c3 + u3i * s3, a3i = u3i * c3 - u3r * s3;
                float t0r = u0r + a2r, t0i = u0i + a2i;
                float t1r = u0r - a2r, t1i = u0i - a2i;
                float t2r = a1r + a3r, t2i = a1i + a3i;
                float t3r = a1r - a3r, t3i = a1i - a3i;
                re[base] = t0r + t2r;  im[base] = t0i + t2i;
                re[base + m]     = t1r - t3i; im[base + m]     = t1i + t3r;  // t1 + i t3
                re[base + 2 * m] = t0r - t2r; im[base + 2 * m] = t0i - t2i;
                re[base + 3 * m] = t1r + t3i; im[base + 3 * m] = t1i - t3r;  // t1 - i t3
            }
        } else {  // R == 5
            int base = blk * L + j;
            float w1r, w1i;
            __sincosf(-6.28318530717958647692f * f, &w1i, &w1r);
            float ur[5], ui[5];
            if (DIR > 0) {
                #pragma unroll
                for (int q = 0; q < 5; q++) { ur[q] = re[base + q * m]; ui[q] = im[base + q * m]; }
                float cwr = 1.0f, cwi = 0.0f;   // running twiddle W^{jq}
                #pragma unroll
                for (int q = 0; q < 5; q++) {
                    float vr = 0.0f, vi = 0.0f;
                    #pragma unroll
                    for (int t = 0; t < 5; t++) {
                        int e = (q * t) % 5;
                        float C = W5C[e], S = W5S[e];       // * e^{-i th}
                        vr += ur[t] * C + ui[t] * S;
                        vi += ui[t] * C - ur[t] * S;
                    }
                    re[base + q * m] = vr * cwr - vi * cwi;
                    im[base + q * m] = vr * cwi + vi * cwr;
                    float nr = cwr * w1r - cwi * w1i;
                    cwi = cwr * w1i + cwi * w1r; cwr = nr;
                }
            } else {
                float cwr = 1.0f, cwi = 0.0f;
                #pragma unroll
                for (int q = 0; q < 5; q++) {
                    float a = re[base + q * m], b2 = im[base + q * m];
                    ur[q] = a * cwr + b2 * cwi;             // * conj(W^{jq})
                    ui[q] = b2 * cwr - a * cwi;
                    float nr = cwr * w1r - cwi * w1i;
                    cwi = cwr * w1i + cwi * w1r; cwr = nr;
                }
                #pragma unroll
                for (int t = 0; t < 5; t++) {
                    float vr = 0.0f, vi = 0.0f;
                    #pragma unroll
                    for (int q = 0; q < 5; q++) {
                        int e = (q * t) % 5;
                        float C = W5C[e], S = W5S[e];       // * e^{+i th}
                        vr += ur[q] * C - ui[q] * S;
                        vi += ui[q] * C + ur[q] * S;
                    }
                    re[base + t * m] = vr; im[base + t * m] = vi;
                }
            }
        }
    }
}

// plan {4,4,4,5,5,10}: 16000 -> 4000 -> 1000 -> 250 -> 50 -> 10 -> 1
__device__ __forceinline__ void fft_fwd(float* re, float* im, int tid) {
    fft_stage_t<16000, 4, 1>(re, im, tid); __syncthreads();
    fft_stage_t<4000, 4, 1>(re, im, tid);  __syncthreads();
    fft_stage_t<1000, 4, 1>(re, im, tid);  __syncthreads();
    fft_stage_t<250, 5, 1>(re, im, tid);   __syncthreads();
    fft_stage_t<50, 5, 1>(re, im, tid);    __syncthreads();
    fft_stage_t<10, 10, 1>(re, im, tid);   __syncthreads();
}
__device__ __forceinline__ void fft_inv(float* re, float* im, int tid) {
    fft_stage_t<10, 10, -1>(re, im, tid);   __syncthreads();
    fft_stage_t<50, 5, -1>(re, im, tid);    __syncthreads();
    fft_stage_t<250, 5, -1>(re, im, tid);   __syncthreads();
    fft_stage_t<1000, 4, -1>(re, im, tid);  __syncthreads();
    fft_stage_t<4000, 4, -1>(re, im, tid);  __syncthreads();
    fft_stage_t<16000, 4, -1>(re, im, tid); __syncthreads();
}

// -------- fused CBP: z = s1 + i*s2; FFT; Z^2; IFFT; Im/(2N); ssqrt; l2norm ---
// mode 0 (layer A): sketch1 from tiled txt_p, sketch2 from src2 rows;
//                   output split bf16 hi/lo (feeds tensor-core GEMM).
// mode 1 (layer B): both plain rows; output fp32 Yout.
__global__ __launch_bounds__(TCBP, 1) void k_cbp(
    const float* __restrict__ src1, const float* __restrict__ src2, int mode,
    const int* __restrict__ h1, const int* __restrict__ s1,
    const int* __restrict__ h2, const int* __restrict__ s2,
    float* __restrict__ Yout, __nv_bfloat16* __restrict__ YoutH,
    __nv_bfloat16* __restrict__ YoutL) {
    extern __shared__ float sm[];
    float* re = sm;
    float* im = sm + N_FFT;
    float* red = sm + 2 * N_FFT;
    int tid = threadIdx.x, p = blockIdx.x;
    for (int d = tid; d < N_FFT; d += TCBP) { re[d] = 0.0f; im[d] = 0.0f; }
    __syncthreads();
    if (mode == 0) {
        int b = p / 49, q = p - 49 * b;
        const float* tp = src1 + (size_t)b * 2048;
        const float* x2 = src2 + (size_t)p * 2048;
        for (int c = tid; c < 2048; c += TCBP) {
            float v = tp[(49 * c + q) & 2047];
            v = (s1[c] > 0) ? v : -v;
            atomicAdd(&re[h1[c]], v);
            float w = x2[c];
            w = (s2[c] > 0) ? w : -w;
            atomicAdd(&im[h2[c]], w);
        }
    } else {
        const float* x1 = src1 + (size_t)p * 2048;
        const float* x2 = src2 + (size_t)p * 2048;
        for (int c = tid; c < 2048; c += TCBP) {
            float v = x1[c];
            v = (s1[c] > 0) ? v : -v;
            atomicAdd(&re[h1[c]], v);
            float w = x2[c];
            w = (s2[c] > 0) ? w : -w;
            atomicAdd(&im[h2[c]], w);
        }
    }
    __syncthreads();
    fft_fwd(re, im, tid);              // scrambled Z
    for (int d = tid; d < N_FFT; d += TCBP) {
        float a = re[d], b2 = im[d];   // Z^2 (pointwise, order-agnostic)
        re[d] = a * a - b2 * b2;
        im[d] = 2.0f * a * b2;
    }
    __syncthreads();
    fft_inv(re, im, tid);              // natural-order unnormalized IDFT
    const float sc0 = 0.5f / (float)N_FFT;   // Im/(2N) = a (*) b
    float ss = 0.0f;
    for (int d = tid; d < N_FFT; d += TCBP) {
        float v = im[d] * sc0;
        float y = copysignf(sqrtf(fabsf(v)), v);
        im[d] = y;
        ss += y * y;
    }
    #pragma unroll
    for (int o = 16; o; o >>= 1) ss += __shfl_xor_sync(0xffffffffu, ss, o);
    if ((tid & 31) == 0) red[tid >> 5] = ss;
    __syncthreads();
    if (tid == 0) {
        float tot = 0.0f;
        for (int i = 0; i < TCBP / 32; i++) tot += red[i];
        red[0] = 1.0f / fmaxf(sqrtf(tot), 1e-12f);
    }
    __syncthreads();
    float sc = red[0];
    if (mode == 0) {
        __nv_bfloat16* yh = YoutH + (size_t)p * N_FFT;
        __nv_bfloat16* yl = YoutL + (size_t)p * N_FFT;
        for (int d = tid; d < N_FFT; d += TCBP) {
            float y = im[d] * sc;
            __nv_bfloat16 h = __float2bfloat16(y);
            yh[d] = h;
            yl[d] = __float2bfloat16(y - __bfloat162float(h));
        }
    } else {
        float* yo = Yout + (size_t)p * N_FFT;
        for (int d = tid; d < N_FFT; d += TCBP) yo[d] = im[d] * sc;
    }
}

// -------- conv1 GEMM on tensor cores (mma.sync), split-bf16 ------------------
__device__ __forceinline__ void ldmx4(uint32_t* r, uint32_t a) {
    asm volatile("ldmatrix.sync.aligned.m8n8.x4.shared.b16 {%0,%1,%2,%3}, [%4];"
                 : "=r"(r[0]), "=r"(r[1]), "=r"(r[2]), "=r"(r[3]) : "r"(a));
}
__device__ __forceinline__ void ldmx2(uint32_t* r, uint32_t a) {
    asm volatile("ldmatrix.sync.aligned.m8n8.x2.shared.b16 {%0,%1}, [%2];"
                 : "=r"(r[0]), "=r"(r[1]) : "r"(a));
}
__device__ __forceinline__ void mma16816(float* d, const uint32_t* a, const uint32_t* b) {
    asm volatile("mma.sync.aligned.m16n8k16.row.col.f32.bf16.bf16.f32 "
                 "{%0,%1,%2,%3}, {%4,%5,%6,%7}, {%8,%9}, {%0,%1,%2,%3};"
                 : "+f"(d[0]), "+f"(d[1]), "+f"(d[2]), "+f"(d[3])
                 : "r"(a[0]), "r"(a[1]), "r"(a[2]), "r"(a[3]), "r"(b[0]), "r"(b[1]));
}

__global__ __launch_bounds__(256, 2) void k_gemm1t(float* __restrict__ Cp) {
    extern __shared__ __align__(16) char smraw[];   // 2 bufs * 4 arrays * SMT = 80KB
    uint32_t sbase;
    asm("{ .reg .u64 t; cvta.to.shared.u64 t, %1; cvt.u32.u64 %0, t; }"
        : "=r"(sbase) : "l"(smraw));
    int tid = threadIdx.x;
    int p0 = blockIdx.x * 128, o0 = blockIdx.y * 128;
    int kbeg = blockIdx.z * KCHUNK;
    int kend = min(16000, kbeg + KCHUNK);
    int nk = (kend - kbeg) >> 5;
    int wid = tid >> 5, lane = tid & 31;
    int wm = wid >> 2, wn = wid & 3;                // warp tile: 64x32

    // stage loader: 4 arrays (Yh,Yl,Wh,Wl), 128 rows x 4 chunks of 16B each.
    // Y rows >= PPOS are zero-filled via cp.async src-size=0.
    auto load_stage = [&](int it, int buf) {
        int kpos = kbeg + it * 32;
        uint32_t bb = sbase + buf * (4 * SMT);
        #pragma unroll
        for (int x = 0; x < 8; x++) {
            const int arr = x >> 1;                 // compile-time per unrolled x
            int idx = tid + x * 256;
            int rem = idx & 511;
            int row = rem >> 2, ch = rem & 3;
            const __nv_bfloat16* g;
            int sz = 16;
            if (arr == 0)      { g = g_Yh + (size_t)(p0 + row) * 16000;
                                 if (p0 + row >= PPOS) sz = 0; }
            else if (arr == 1) { g = g_Yl + (size_t)(p0 + row) * 16000;
                                 if (p0 + row >= PPOS) sz = 0; }
            else if (arr == 2) g = g_Wh + (size_t)(o0 + row) * 16000;
            else               g = g_Wl + (size_t)(o0 + row) * 16000;
            const void* src = (const void*)(g + kpos + ch * 8);
            uint32_t dst = bb + arr * SMT + row * 80 + ch * 16;
            asm volatile("cp.async.cg.shared.global [%0], [%1], 16, %2;"
                         :: "r"(dst), "l"(src), "r"(sz));
        }
        asm volatile("cp.async.commit_group;");
    };

    float acc[4][4][4];
    #pragma unroll
    for (int i = 0; i < 4; i++)
        #pragma unroll
        for (int j = 0; j < 4; j++)
            #pragma unroll
            for (int k = 0; k < 4; k++) acc[i][j][k] = 0.0f;

    load_stage(0, 0);
    for (int it = 0; it < nk; it++) {
        bool more = (it + 1) < nk;
        if (more) {
            load_stage(it + 1, (it + 1) & 1);
            asm volatile("cp.async.wait_group 1;" ::: "memory");
        } else {
            asm volatile("cp.async.wait_group 0;" ::: "memory");
        }
        __syncthreads();
        uint32_t bb = sbase + (it & 1) * (4 * SMT);
        #pragma unroll
        for (int kk = 0; kk < 2; kk++) {           // two k16 halves of BK=32
            // register-lean order: B fragments first, then stream A per m-tile
            uint32_t bh[4][2], bl[4][2];
            uint32_t chB = kk * 2 + ((lane >> 3) & 1);
            #pragma unroll
            for (int nt = 0; nt < 4; nt++) {
                uint32_t r = wn * 32 + nt * 8 + (lane & 7);
                ldmx2(bh[nt], bb + 2 * SMT + r * 80 + chB * 16);
                ldmx2(bl[nt], bb + 3 * SMT + r * 80 + chB * 16);
            }
            uint32_t chA = kk * 2 + (lane >> 4);
            #pragma unroll
            for (int mt = 0; mt < 4; mt++) {
                uint32_t ah[4], al[4];
                uint32_t r = wm * 64 + mt * 16 + (lane & 15);
                ldmx4(ah, bb + 0 * SMT + r * 80 + chA * 16);
                ldmx4(al, bb + 1 * SMT + r * 80 + chA * 16);
                #pragma unroll
                for (int nt = 0; nt < 4; nt++) {
                    mma16816(acc[mt][nt], ah, bh[nt]);
                    mma16816(acc[mt][nt], ah, bl[nt]);
                    mma16816(acc[mt][nt], al, bh[nt]);
                }
            }
        }
        __syncthreads();
    }

    float* cp = Cp + (size_t)blockIdx.z * PPOS * 512;
    int tq = lane >> 2, t2 = (lane & 3) * 2;
    #pragma unroll
    for (int mt = 0; mt < 4; mt++)
        #pragma unroll
        for (int nt = 0; nt < 4; nt++) {
            int o = o0 + wn * 32 + nt * 8 + t2;
            int pA = p0 + wm * 64 + mt * 16 + tq;
            if (pA < PPOS) {
                float* d = cp + (size_t)pA * 512 + o;
                d[0] = acc[mt][nt][0]; d[1] = acc[mt][nt][1];
            }
            int pB = pA + 8;
            if (pB < PPOS) {
                float* d = cp + (size_t)pB * 512 + o;
                d[0] = acc[mt][nt][2]; d[1] = acc[mt][nt][3];
            }
        }
}

// -------- attention: sum partials + bias + relu, conv2, softmax(49), pooling -
__global__ void k_attn(const float* __restrict__ b1, const float* __restrict__ w2,
                       const float* __restrict__ b2, const float* __restrict__ img) {
    __shared__ float slog[49];
    __shared__ float sw[49];
    int b = blockIdx.x, tid = threadIdx.x;
    int warp = tid >> 5, lane = tid & 31;
    for (int q = warp; q < 49; q += 8) {
        float acc = 0.0f;
        const float* c0 = g_Cpart + (size_t)(b * 49 + q) * 512;
        for (int o = lane; o < 512; o += 32) {
            float z = b1[o];
            #pragma unroll
            for (int s = 0; s < NSPLIT; s++) z += c0[(size_t)s * PPOS * 512 + o];
            z = fmaxf(z, 0.0f);
            acc += z * w2[o];
        }
        #pragma unroll
        for (int o = 16; o; o >>= 1) acc += __shfl_xor_sync(0xffffffffu, acc, o);
        if (lane == 0) slog[q] = acc + b2[0];
    }
    __syncthreads();
    if (tid == 0) {
        float mx = -1e30f;
        for (int q = 0; q < 49; q++) mx = fmaxf(mx, slog[q]);
        float sum = 0.0f;
        for (int q = 0; q < 49; q++) { float e = expf(slog[q] - mx); sw[q] = e; sum += e; }
        float inv = 1.0f / sum;
        for (int q = 0; q < 49; q++) sw[q] *= inv;
    }
    __syncthreads();
    // faithful to torch .view(bs,49,-1) on NCHW-contiguous img: flat addressing
    const float* ib = img + (size_t)b * 100352;
    for (int c = tid; c < 2048; c += blockDim.x) {
        float acc = 0.0f;
        #pragma unroll
        for (int q = 0; q < 49; q++) acc += sw[q] * ib[q * 2048 + c];
        g_res[b * 2048 + c] = acc;
    }
}

// -------- final GEMM partials: Fp[z][b][o] = sum_{k-chunk} Yb[b,k]*W[o,k] -----
// FSPLIT=10 chunks of 1600 k each (100 iters of 16).
__global__ __launch_bounds__(256) void k_final(const float* __restrict__ W) {
    __shared__ __align__(16) float Ws[16][132];
    __shared__ __align__(16) float Ys[16][36];
    int tid = threadIdx.x;
    int o0 = blockIdx.x * 128;
    int z = blockIdx.y;
    int ty = tid >> 5, tx = tid & 31;
    float acc[4][4];
    #pragma unroll
    for (int i = 0; i < 4; i++)
        #pragma unroll
        for (int j = 0; j < 4; j++) acc[i][j] = 0.0f;

    int kq = (tid & 3) * 4;
    int orow = tid >> 2;
    int brow = tid >> 2;

    for (int it = 0; it < 100; it++) {
        int k0 = z * 1600 + it * 16;
        if (brow < 32) {
            float4 f = *(const float4*)(g_Yb + (size_t)brow * 16000 + k0 + kq);
            Ys[kq + 0][brow] = f.x; Ys[kq + 1][brow] = f.y;
            Ys[kq + 2][brow] = f.z; Ys[kq + 3][brow] = f.w;
        }
        #pragma unroll
        for (int rr = 0; rr < 2; rr++) {
            int o = o0 + orow + rr * 64;
            float4 f = (o < 3000) ? *(const float4*)(W + (size_t)o * 16000 + k0 + kq)
                                  : make_float4(0, 0, 0, 0);
            Ws[kq + 0][orow + rr * 64] = f.x; Ws[kq + 1][orow + rr * 64] = f.y;
            Ws[kq + 2][orow + rr * 64] = f.z; Ws[kq + 3][orow + rr * 64] = f.w;
        }
        __syncthreads();
        #pragma unroll
        for (int kk = 0; kk < 16; kk++) {
            float a[4], b[4];
            *(float4*)a = *(const float4*)&Ys[kk][ty * 4];
            *(float4*)b = *(const float4*)&Ws[kk][tx * 4];
            #pragma unroll
            for (int i = 0; i < 4; i++)
                #pragma unroll
                for (int j = 0; j < 4; j++) acc[i][j] += a[i] * b[j];
        }
        __syncthreads();
    }

    float* fp = g_Fpart + (size_t)z * 32 * 3000;
    #pragma unroll
    for (int i = 0; i < 4; i++) {
        int b = ty * 4 + i;
        #pragma unroll
        for (int j = 0; j < 4; j++) {
            int o = o0 + tx * 4 + j;
            if (o < 3000) fp[(size_t)b * 3000 + o] = acc[i][j];
        }
    }
}

// -------- reduce final partials + bias -> d_out ------------------------------
__global__ void k_finred(const float* __restrict__ bias, float* __restrict__ out) {
    int i = blockIdx.x * blockDim.x + threadIdx.x;
    if (i < 32 * 3000) {
        int o = i % 3000;
        float s = bias[o];
        #pragma unroll
        for (int zz = 0; zz < FSPLIT; zz++) s += g_Fpart[(size_t)zz * 32 * 3000 + i];
        out[i] = s;
    }
}

extern "C" void kernel_launch(void* const* d_in, const int* in_sizes, int n_in,
                              void* d_out, int out_size) {
    const float* txt     = (const float*)d_in[0];
    const float* img     = (const float*)d_in[1];
    const float* conv1_w = (const float*)d_in[2];
    const float* conv1_b = (const float*)d_in[3];
    const float* conv2_w = (const float*)d_in[4];
    const float* conv2_b = (const float*)d_in[5];
    const float* lin2_w  = (const float*)d_in[6];
    const float* lin2_b  = (const float*)d_in[7];
    const int* h1a = (const int*)d_in[8];
    const int* s1a = (const int*)d_in[9];
    const int* h2a = (const int*)d_in[10];
    const int* s2a = (const int*)d_in[11];
    const int* h1b = (const int*)d_in[12];
    const int* s1b = (const int*)d_in[13];
    const int* h2b = (const int*)d_in[14];
    const int* s2b = (const int*)d_in[15];
    float* out = (float*)d_out;

    const int SMEMB = (2 * N_FFT + 32) * sizeof(float);
    const int SMEMG = 2 * 4 * SMT;   // 80KB
    cudaFuncSetAttribute(k_cbp, cudaFuncAttributeMaxDynamicSharedMemorySize, SMEMB);
    cudaFuncSetAttribute(k_gemm1t, cudaFuncAttributeMaxDynamicSharedMemorySize, SMEMG);

    float* ybptr; cudaGetSymbolAddress((void**)&ybptr, g_Yb);
    float* cpptr; cudaGetSymbolAddress((void**)&cpptr, g_Cpart);
    float* tpptr; cudaGetSymbolAddress((void**)&tpptr, g_txtp);
    float* itptr; cudaGetSymbolAddress((void**)&itptr, g_imgt);
    float* rsptr; cudaGetSymbolAddress((void**)&rsptr, g_res);
    __nv_bfloat16* yhptr; cudaGetSymbolAddress((void**)&yhptr, g_Yh);
    __nv_bfloat16* ylptr; cudaGetSymbolAddress((void**)&ylptr, g_Yl);

    k_txtp<<<32, 256>>>(txt);
    dim3 gt(32, 32);
    k_imgt<<<gt, 256>>>(img);
    k_wsplit<<<(512 * N_FFT + 255) / 256, 256>>>(conv1_w);

    // CBP layer A: fused, per spatial position; writes split bf16 hi/lo
    k_cbp<<<PPOS, TCBP, SMEMB>>>(tpptr, itptr, 0, h1a, s1a, h2a, s2a,
                                 nullptr, yhptr, ylptr);

    // conv1 on tensor cores (split-K) + attention
    dim3 g1(PPAD / 128, 4, NSPLIT);
    k_gemm1t<<<g1, 256, SMEMG>>>(cpptr);
    k_attn<<<32, 256>>>(conv1_b, conv2_w, conv2_b, img);

    // CBP layer B, per batch; fp32 output
    k_cbp<<<32, TCBP, SMEMB>>>(tpptr, rsptr, 1, h1b, s1b, h2b, s2b,
                               ybptr, nullptr, nullptr);

    // final linear
    dim3 gf(24, FSPLIT);
    k_final<<<gf, 256>>>(lin2_w);
    k_finred<<<(32 * 3000 + 255) / 256, 256>>>(lin2_b, out);
}

// round 15
// speedup vs baseline: 3.5096x; 1.0257x over previous
#include <cuda_runtime.h>
#include <cuda_bf16.h>
#include <math.h>
#include <stdint.h>

#define N_FFT 16000
#define PPOS  1568
#define PPAD  1664            // 13 * 128
#define NSPLIT 6
#define KCHUNK 2688           // divisible by 32; 5*2688 + 2560 = 16000
#define FSPLIT 10
#define TCBP   1024
#define SMT    10240          // bytes per smem tile array: 128 rows * 80B

// -------- device scratch (allocation-free rule: __device__ globals) --------
__device__ float g_txtp[32 * 2048];
__device__ __align__(16) float g_imgt[(size_t)PPOS * 2048];
__device__ __align__(16) __nv_bfloat16 g_Yh[(size_t)PPAD * N_FFT];
__device__ __align__(16) __nv_bfloat16 g_Yl[(size_t)PPAD * N_FFT];
__device__ __align__(16) __nv_bfloat16 g_Wh[(size_t)512 * N_FFT];
__device__ __align__(16) __nv_bfloat16 g_Wl[(size_t)512 * N_FFT];
__device__ float g_Cpart[(size_t)NSPLIT * PPOS * 512];
__device__ float g_res[32 * 2048];
__device__ __align__(16) float g_Yb[(size_t)32 * N_FFT];
__device__ float g_Fpart[(size_t)FSPLIT * 32 * 3000];

__constant__ float W5C[5] = {1.0f, 0.30901699437494742f, -0.80901699437494745f,
                             -0.80901699437494745f, 0.30901699437494742f};
__constant__ float W5S[5] = {0.0f, 0.95105651629515353f, 0.58778525229247314f,
                             -0.58778525229247314f, -0.95105651629515353f};
// W10^k = exp(-2*pi*i*k/10) = (W10C[k], -W10S[k])
__constant__ float W10C[5] = {1.0f, 0.80901699437494745f, 0.30901699437494742f,
                              -0.30901699437494742f, -0.80901699437494745f};
__constant__ float W10S[5] = {0.0f, 0.58778525229247314f, 0.95105651629515353f,
                              0.95105651629515353f, 0.58778525229247314f};

// -------- txt avgpool (3,3) s(100,1) p(1,1) count_include_pad -> (32,2048) ----
__global__ void k_txtp(const float* __restrict__ txt) {
    int b = blockIdx.x;
    const float* base = txt + (size_t)b * 50 * 2048;
    for (int j = threadIdx.x; j < 2048; j += blockDim.x) {
        float sum = 0.0f;
        #pragma unroll
        for (int r = 0; r < 2; r++)
            #pragma unroll
            for (int dj = -1; dj <= 1; dj++) {
                int jj = j + dj;
                if (jj >= 0 && jj < 2048) sum += base[r * 2048 + jj];
            }
        g_txtp[b * 2048 + j] = sum * (1.0f / 9.0f);
    }
}

// -------- tiled transpose img NCHW -> rows (b*49+q, c), both sides coalesced -
__global__ void k_imgt(const float* __restrict__ img) {
    __shared__ float tile[64][51];   // gcd(51,32)=1 -> conflict-free
    int b = blockIdx.y;
    int c0 = blockIdx.x * 64;
    int tid = threadIdx.x;
    const float* ib = img + (size_t)b * 2048 * 49;
    for (int idx = tid; idx < 64 * 49; idx += blockDim.x) {
        int cc = idx / 49, q = idx - cc * 49;
        tile[cc][q] = ib[(size_t)(c0 + cc) * 49 + q];
    }
    __syncthreads();
    for (int idx = tid; idx < 64 * 49; idx += blockDim.x) {
        int q = idx >> 6, cc = idx & 63;
        g_imgt[(size_t)(b * 49 + q) * 2048 + c0 + cc] = tile[cc][q];
    }
}

// -------- split conv1_w into bf16 hi/lo -------------------------------------
__global__ void k_wsplit(const float* __restrict__ W) {
    size_t i = (size_t)blockIdx.x * blockDim.x + threadIdx.x;
    if (i < (size_t)512 * N_FFT) {
        float w = W[i];
        __nv_bfloat16 h = __float2bfloat16(w);
        g_Wh[i] = h;
        g_Wl[i] = __float2bfloat16(w - __bfloat162float(h));
    }
}

// -------- one mixed-radix stage on smem, compile-time L/R/DIR ----------------
// DIR>0: DIF forward (butterfly then twiddle), scrambled output.
// DIR<0: transposed network (conj twiddle then inverse butterfly), reverse order.
template<int L, int R, int DIR>
__device__ __forceinline__ void fft_stage_t(float* re, float* im, int tid) {
    constexpr int m = L / R;
    constexpr int nb = N_FFT / R;
    const float invL = 1.0f / (float)L;
    for (int i = tid; i < nb; i += TCBP) {
        int blk = i / m, j = i - blk * m;            // const-divisor -> IMAD
        float f = (float)j * invL;
        if (f >= 0.5f) f -= 1.0f;
        if (R == 4) {
            int base = blk * L + j;
            float c1, s1;
            __sincosf(-6.28318530717958647692f * f, &s1, &c1);
            float c2 = c1 * c1 - s1 * s1, s2 = 2.0f * c1 * s1;
            float c3 = c2 * c1 - s2 * s1, s3 = c2 * s1 + s2 * c1;
            float u0r = re[base],         u0i = im[base];
            float u1r = re[base + m],     u1i = im[base + m];
            float u2r = re[base + 2 * m], u2i = im[base + 2 * m];
            float u3r = re[base + 3 * m], u3i = im[base + 3 * m];
            if (DIR > 0) {
                float t0r = u0r + u2r, t0i = u0i + u2i;
                float t1r = u0r - u2r, t1i = u0i - u2i;
                float t2r = u1r + u3r, t2i = u1i + u3i;
                float t3r = u1r - u3r, t3i = u1i - u3i;
                re[base] = t0r + t2r;  im[base] = t0i + t2i;
                float v1r = t1r + t3i, v1i = t1i - t3r;   // t1 - i t3
                float v2r = t0r - t2r, v2i = t0i - t2i;
                float v3r = t1r - t3i, v3i = t1i + t3r;   // t1 + i t3
                re[base + m]     = v1r * c1 - v1i * s1; im[base + m]     = v1r * s1 + v1i * c1;
                re[base + 2 * m] = v2r * c2 - v2i * s2; im[base + 2 * m] = v2r * s2 + v2i * c2;
                re[base + 3 * m] = v3r * c3 - v3i * s3; im[base + 3 * m] = v3r * s3 + v3i * c3;
            } else {
                float a1r = u1r * c1 + u1i * s1, a1i = u1i * c1 - u1r * s1;
                float a2r = u2r * c2 + u2i * s2, a2i = u2i * c2 - u2r * s2;
                float a3r = u3r * c3 + u3i * s3, a3i = u3i * c3 - u3r * s3;
                float t0r = u0r + a2r, t0i = u0i + a2i;
                float t1r = u0r - a2r, t1i = u0i - a2i;
                float t2r = a1r + a3r, t2i = a1i + a3i;
                float t3r = a1r - a3r, t3i = a1i - a3i;
                re[base] = t0r + t2r;  im[base] = t0i + t2i;
                re[base + m]     = t1r - t3i; im[base + m]     = t1i + t3r;  // t1 + i t3
                re[base + 2 * m] = t0r - t2r; im[base + 2 * m] = t0i - t2i;
                re[base + 3 * m] = t1r + t3i; im[base + 3 * m] = t1i - t3r;  // t1 - i t3
            }
        } else {  // R == 5
            int base = blk * L + j;
            float w1r, w1i;
            __sincosf(-6.28318530717958647692f * f, &w1i, &w1r);
            float ur[5], ui[5];
            if (DIR > 0) {
                #pragma unroll
                for (int q = 0; q < 5; q++) { ur[q] = re[base + q * m]; ui[q] = im[base + q * m]; }
                float cwr = 1.0f, cwi = 0.0f;   // running twiddle W^{jq}
                #pragma unroll
                for (int q = 0; q < 5; q++) {
                    float vr = 0.0f, vi = 0.0f;
                    #pragma unroll
                    for (int t = 0; t < 5; t++) {
                        int e = (q * t) % 5;
                        float C = W5C[e], S = W5S[e];       // * e^{-i th}
                        vr += ur[t] * C + ui[t] * S;
                        vi += ui[t] * C - ur[t] * S;
                    }
                    re[base + q * m] = vr * cwr - vi * cwi;
                    im[base + q * m] = vr * cwi + vi * cwr;
                    float nr = cwr * w1r - cwi * w1i;
                    cwi = cwr * w1i + cwi * w1r; cwr = nr;
                }
            } else {
                float cwr = 1.0f, cwi = 0.0f;
                #pragma unroll
                for (int q = 0; q < 5; q++) {
                    float a = re[base + q * m], b2 = im[base + q * m];
                    ur[q] = a * cwr + b2 * cwi;             // * conj(W^{jq})
                    ui[q] = b2 * cwr - a * cwi;
                    float nr = cwr * w1r - cwi * w1i;
                    cwi = cwr * w1i + cwi * w1r; cwr = nr;
                }
                #pragma unroll
                for (int t = 0; t < 5; t++) {
                    float vr = 0.0f, vi = 0.0f;
                    #pragma unroll
                    for (int q = 0; q < 5; q++) {
                        int e = (q * t) % 5;
                        float C = W5C[e], S = W5S[e];       // * e^{+i th}
                        vr += ur[q] * C - ui[q] * S;
                        vi += ui[q] * C + ur[q] * S;
                    }
                    re[base + t * m] = vr; im[base + t * m] = vi;
                }
            }
        }
    }
}

// -------- fused middle: DFT10 fwd -> Z^2 -> DFT10 inv, all in registers -------
// The L=10 (m=1) stage is twiddle-free and its inverse is applied immediately
// after the pointwise square, on the SAME 10 elements per thread: no smem
// round-trip, no separate Z^2 pass, no extra syncs.
__device__ __forceinline__ void cbp_mid(float* re, float* im, int tid) {
    for (int i = tid; i < 1600; i += TCBP) {
        int base = i * 10;
        float xr[10], xi[10];
        #pragma unroll
        for (int q = 0; q < 10; q++) { xr[q] = re[base + q]; xi[q] = im[base + q]; }
        // forward DFT10 (e^{-i}): E/O DFT5 then W10 combine
        float er[5], ei[5], orr[5], oi[5];
        #pragma unroll
        for (int k = 0; k < 5; k++) {
            float a = 0.0f, b = 0.0f, c = 0.0f, d = 0.0f;
            #pragma unroll
            for (int t = 0; t < 5; t++) {
                int e = (k * t) % 5;
                float C = W5C[e], S = W5S[e];
                a += xr[2 * t] * C + xi[2 * t] * S;
                b += xi[2 * t] * C - xr[2 * t] * S;
                c += xr[2 * t + 1] * C + xi[2 * t + 1] * S;
                d += xi[2 * t + 1] * C - xr[2 * t + 1] * S;
            }
            er[k] = a; ei[k] = b; orr[k] = c; oi[k] = d;
        }
        #pragma unroll
        for (int k = 0; k < 5; k++) {
            float C = W10C[k], S = W10S[k];
            float tr = orr[k] * C + oi[k] * S;
            float ti = oi[k] * C - orr[k] * S;
            xr[k]     = er[k] + tr;  xi[k]     = ei[k] + ti;
            xr[k + 5] = er[k] - tr;  xi[k + 5] = ei[k] - ti;
        }
        // Z^2 (pointwise, order-agnostic)
        #pragma unroll
        for (int q = 0; q < 10; q++) {
            float a = xr[q], b = xi[q];
            xr[q] = a * a - b * b;
            xi[q] = 2.0f * a * b;
        }
        // inverse DFT10 (e^{+i}): E/O DFT5 then conj(W10) combine
        #pragma unroll
        for (int k = 0; k < 5; k++) {
            float a = 0.0f, b = 0.0f, c = 0.0f, d = 0.0f;
            #pragma unroll
            for (int t = 0; t < 5; t++) {
                int e = (k * t) % 5;
                float C = W5C[e], S = W5S[e];
                a += xr[2 * t] * C - xi[2 * t] * S;
                b += xi[2 * t] * C + xr[2 * t] * S;
                c += xr[2 * t + 1] * C - xi[2 * t + 1] * S;
                d += xi[2 * t + 1] * C + xr[2 * t + 1] * S;
            }
            er[k] = a; ei[k] = b; orr[k] = c; oi[k] = d;
        }
        #pragma unroll
        for (int k = 0; k < 5; k++) {
            float C = W10C[k], S = W10S[k];
            float tr = orr[k] * C - oi[k] * S;
            float ti = oi[k] * C + orr[k] * S;
            re[base + k]     = er[k] + tr;  im[base + k]     = ei[k] + ti;
            re[base + k + 5] = er[k] - tr;  im[base + k + 5] = ei[k] - ti;
        }
    }
}

// -------- fused last inverse stage (L=16000, R=4): only imag outputs needed.
// Applies 1/(2N) scale + signed-sqrt in registers, accumulates l2 partials;
// skips all real-part math/stores and the separate epilogue pass.
__device__ __forceinline__ void fft_last_fused(float* re, float* im, int tid, float& ss) {
    constexpr int m = 4000;
    const float invL = 1.0f / 16000.0f;
    const float sc0 = 0.5f / (float)N_FFT;
    for (int j = tid; j < 4000; j += TCBP) {
        float f = (float)j * invL;
        if (f >= 0.5f) f -= 1.0f;
        float c1, s1;
        __sincosf(-6.28318530717958647692f * f, &s1, &c1);
        float c2 = c1 * c1 - s1 * s1, s2 = 2.0f * c1 * s1;
        float c3 = c2 * c1 - s2 * s1, s3 = c2 * s1 + s2 * c1;
        float u0i = im[j];
        float u1r = re[j + m],     u1i = im[j + m];
        float u2r = re[j + 2 * m], u2i = im[j + 2 * m];
        float u3r = re[j + 3 * m], u3i = im[j + 3 * m];
        float a1r = u1r * c1 + u1i * s1, a1i = u1i * c1 - u1r * s1;
        float a2i = u2i * c2 - u2r * s2;
        float a3r = u3r * c3 + u3i * s3, a3i = u3i * c3 - u3r * s3;
        float t0i = u0i + a2i;
        float t1i = u0i - a2i;
        float t2i = a1i + a3i;
        float t3r = a1r - a3r;
        float v0 = (t0i + t2i) * sc0; float y0 = copysignf(sqrtf(fabsf(v0)), v0);
        float v1 = (t1i + t3r) * sc0; float y1 = copysignf(sqrtf(fabsf(v1)), v1);
        float v2 = (t0i - t2i) * sc0; float y2 = copysignf(sqrtf(fabsf(v2)), v2);
        float v3 = (t1i - t3r) * sc0; float y3 = copysignf(sqrtf(fabsf(v3)), v3);
        im[j] = y0; im[j + m] = y1; im[j + 2 * m] = y2; im[j + 3 * m] = y3;
        ss += y0 * y0 + y1 * y1 + y2 * y2 + y3 * y3;
    }
}

// -------- fused CBP: z = s1 + i*s2; FFT; Z^2; IFFT; Im/(2N); ssqrt; l2norm ---
// mode 0 (layer A): sketch1 from tiled txt_p, sketch2 from src2 rows;
//                   output split bf16 hi/lo (feeds tensor-core GEMM).
// mode 1 (layer B): both plain rows; output fp32 Yout.
__global__ __launch_bounds__(TCBP, 1) void k_cbp(
    const float* __restrict__ src1, const float* __restrict__ src2, int mode,
    const int* __restrict__ h1, const int* __restrict__ s1,
    const int* __restrict__ h2, const int* __restrict__ s2,
    float* __restrict__ Yout, __nv_bfloat16* __restrict__ YoutH,
    __nv_bfloat16* __restrict__ YoutL) {
    extern __shared__ float sm[];
    float* re = sm;
    float* im = sm + N_FFT;
    float* red = sm + 2 * N_FFT;
    int tid = threadIdx.x, p = blockIdx.x;
    for (int d = tid; d < N_FFT; d += TCBP) { re[d] = 0.0f; im[d] = 0.0f; }
    __syncthreads();
    if (mode == 0) {
        int b = p / 49, q = p - 49 * b;
        const float* tp = src1 + (size_t)b * 2048;
        const float* x2 = src2 + (size_t)p * 2048;
        for (int c = tid; c < 2048; c += TCBP) {
            float v = tp[(49 * c + q) & 2047];
            v = (s1[c] > 0) ? v : -v;
            atomicAdd(&re[h1[c]], v);
            float w = x2[c];
            w = (s2[c] > 0) ? w : -w;
            atomicAdd(&im[h2[c]], w);
        }
    } else {
        const float* x1 = src1 + (size_t)p * 2048;
        const float* x2 = src2 + (size_t)p * 2048;
        for (int c = tid; c < 2048; c += TCBP) {
            float v = x1[c];
            v = (s1[c] > 0) ? v : -v;
            atomicAdd(&re[h1[c]], v);
            float w = x2[c];
            w = (s2[c] > 0) ? w : -w;
            atomicAdd(&im[h2[c]], w);
        }
    }
    __syncthreads();
    // forward stages {4,4,4,5,5}, fused mid (DFT10+Z^2+invDFT10), inverse
    // stages {5,5,4,4}, fused last stage with ssqrt epilogue.
    fft_stage_t<16000, 4, 1>(re, im, tid); __syncthreads();
    fft_stage_t<4000, 4, 1>(re, im, tid);  __syncthreads();
    fft_stage_t<1000, 4, 1>(re, im, tid);  __syncthreads();
    fft_stage_t<250, 5, 1>(re, im, tid);   __syncthreads();
    fft_stage_t<50, 5, 1>(re, im, tid);    __syncthreads();
    cbp_mid(re, im, tid);                  __syncthreads();
    fft_stage_t<50, 5, -1>(re, im, tid);   __syncthreads();
    fft_stage_t<250, 5, -1>(re, im, tid);  __syncthreads();
    fft_stage_t<1000, 4, -1>(re, im, tid); __syncthreads();
    fft_stage_t<4000, 4, -1>(re, im, tid); __syncthreads();
    float ss = 0.0f;
    fft_last_fused(re, im, tid, ss);
    #pragma unroll
    for (int o = 16; o; o >>= 1) ss += __shfl_xor_sync(0xffffffffu, ss, o);
    if ((tid & 31) == 0) red[tid >> 5] = ss;
    __syncthreads();
    if (tid == 0) {
        float tot = 0.0f;
        for (int i = 0; i < TCBP / 32; i++) tot += red[i];
        red[0] = 1.0f / fmaxf(sqrtf(tot), 1e-12f);
    }
    __syncthreads();
    float sc = red[0];
    if (mode == 0) {
        __nv_bfloat16* yh = YoutH + (size_t)p * N_FFT;
        __nv_bfloat16* yl = YoutL + (size_t)p * N_FFT;
        for (int d = tid; d < N_FFT; d += TCBP) {
            float y = im[d] * sc;
            __nv_bfloat16 h = __float2bfloat16(y);
            yh[d] = h;
            yl[d] = __float2bfloat16(y - __bfloat162float(h));
        }
    } else {
        float* yo = Yout + (size_t)p * N_FFT;
        for (int d = tid; d < N_FFT; d += TCBP) yo[d] = im[d] * sc;
    }
}

// -------- conv1 GEMM on tensor cores (mma.sync), split-bf16 ------------------
__device__ __forceinline__ void ldmx4(uint32_t* r, uint32_t a) {
    asm volatile("ldmatrix.sync.aligned.m8n8.x4.shared.b16 {%0,%1,%2,%3}, [%4];"
                 : "=r"(r[0]), "=r"(r[1]), "=r"(r[2]), "=r"(r[3]) : "r"(a));
}
__device__ __forceinline__ void ldmx2(uint32_t* r, uint32_t a) {
    asm volatile("ldmatrix.sync.aligned.m8n8.x2.shared.b16 {%0,%1}, [%2];"
                 : "=r"(r[0]), "=r"(r[1]) : "r"(a));
}
__device__ __forceinline__ void mma16816(float* d, const uint32_t* a, const uint32_t* b) {
    asm volatile("mma.sync.aligned.m16n8k16.row.col.f32.bf16.bf16.f32 "
                 "{%0,%1,%2,%3}, {%4,%5,%6,%7}, {%8,%9}, {%0,%1,%2,%3};"
                 : "+f"(d[0]), "+f"(d[1]), "+f"(d[2]), "+f"(d[3])
                 : "r"(a[0]), "r"(a[1]), "r"(a[2]), "r"(a[3]), "r"(b[0]), "r"(b[1]));
}

__global__ __launch_bounds__(256, 2) void k_gemm1t(float* __restrict__ Cp) {
    extern __shared__ __align__(16) char smraw[];   // 2 bufs * 4 arrays * SMT = 80KB
    uint32_t sbase;
    asm("{ .reg .u64 t; cvta.to.shared.u64 t, %1; cvt.u32.u64 %0, t; }"
        : "=r"(sbase) : "l"(smraw));
    int tid = threadIdx.x;
    int p0 = blockIdx.x * 128, o0 = blockIdx.y * 128;
    int kbeg = blockIdx.z * KCHUNK;
    int kend = min(16000, kbeg + KCHUNK);
    int nk = (kend - kbeg) >> 5;
    int wid = tid >> 5, lane = tid & 31;
    int wm = wid >> 2, wn = wid & 3;                // warp tile: 64x32

    auto load_stage = [&](int it, int buf) {
        int kpos = kbeg + it * 32;
        uint32_t bb = sbase + buf * (4 * SMT);
        #pragma unroll
        for (int x = 0; x < 8; x++) {
            const int arr = x >> 1;
            int idx = tid + x * 256;
            int rem = idx & 511;
            int row = rem >> 2, ch = rem & 3;
            const __nv_bfloat16* g;
            int sz = 16;
            if (arr == 0)      { g = g_Yh + (size_t)(p0 + row) * 16000;
                                 if (p0 + row >= PPOS) sz = 0; }
            else if (arr == 1) { g = g_Yl + (size_t)(p0 + row) * 16000;
                                 if (p0 + row >= PPOS) sz = 0; }
            else if (arr == 2) g = g_Wh + (size_t)(o0 + row) * 16000;
            else               g = g_Wl + (size_t)(o0 + row) * 16000;
            const void* src = (const void*)(g + kpos + ch * 8);
            uint32_t dst = bb + arr * SMT + row * 80 + ch * 16;
            asm volatile("cp.async.cg.shared.global [%0], [%1], 16, %2;"
                         :: "r"(dst), "l"(src), "r"(sz));
        }
        asm volatile("cp.async.commit_group;");
    };

    float acc[4][4][4];
    #pragma unroll
    for (int i = 0; i < 4; i++)
        #pragma unroll
        for (int j = 0; j < 4; j++)
            #pragma unroll
            for (int k = 0; k < 4; k++) acc[i][j][k] = 0.0f;

    load_stage(0, 0);
    for (int it = 0; it < nk; it++) {
        bool more = (it + 1) < nk;
        if (more) {
            load_stage(it + 1, (it + 1) & 1);
            asm volatile("cp.async.wait_group 1;" ::: "memory");
        } else {
            asm volatile("cp.async.wait_group 0;" ::: "memory");
        }
        __syncthreads();
        uint32_t bb = sbase + (it & 1) * (4 * SMT);
        #pragma unroll
        for (int kk = 0; kk < 2; kk++) {
            uint32_t bh[4][2], bl[4][2];
            uint32_t chB = kk * 2 + ((lane >> 3) & 1);
            #pragma unroll
            for (int nt = 0; nt < 4; nt++) {
                uint32_t r = wn * 32 + nt * 8 + (lane & 7);
                ldmx2(bh[nt], bb + 2 * SMT + r * 80 + chB * 16);
                ldmx2(bl[nt], bb + 3 * SMT + r * 80 + chB * 16);
            }
            uint32_t chA = kk * 2 + (lane >> 4);
            #pragma unroll
            for (int mt = 0; mt < 4; mt++) {
                uint32_t ah[4], al[4];
                uint32_t r = wm * 64 + mt * 16 + (lane & 15);
                ldmx4(ah, bb + 0 * SMT + r * 80 + chA * 16);
                ldmx4(al, bb + 1 * SMT + r * 80 + chA * 16);
                #pragma unroll
                for (int nt = 0; nt < 4; nt++) {
                    mma16816(acc[mt][nt], ah, bh[nt]);
                    mma16816(acc[mt][nt], ah, bl[nt]);
                    mma16816(acc[mt][nt], al, bh[nt]);
                }
            }
        }
        __syncthreads();
    }

    float* cp = Cp + (size_t)blockIdx.z * PPOS * 512;
    int tq = lane >> 2, t2 = (lane & 3) * 2;
    #pragma unroll
    for (int mt = 0; mt < 4; mt++)
        #pragma unroll
        for (int nt = 0; nt < 4; nt++) {
            int o = o0 + wn * 32 + nt * 8 + t2;
            int pA = p0 + wm * 64 + mt * 16 + tq;
            if (pA < PPOS) {
                float* d = cp + (size_t)pA * 512 + o;
                d[0] = acc[mt][nt][0]; d[1] = acc[mt][nt][1];
            }
            int pB = pA + 8;
            if (pB < PPOS) {
                float* d = cp + (size_t)pB * 512 + o;
                d[0] = acc[mt][nt][2]; d[1] = acc[mt][nt][3];
            }
        }
}

// -------- attention: sum partials + bias + relu, conv2, softmax(49), pooling -
__global__ void k_attn(const float* __restrict__ b1, const float* __restrict__ w2,
                       const float* __restrict__ b2, const float* __restrict__ img) {
    __shared__ float slog[49];
    __shared__ float sw[49];
    int b = blockIdx.x, tid = threadIdx.x;
    int warp = tid >> 5, lane = tid & 31;
    for (int q = warp; q < 49; q += 8) {
        float acc = 0.0f;
        const float* c0 = g_Cpart + (size_t)(b * 49 + q) * 512;
        for (int o = lane; o < 512; o += 32) {
            float z = b1[o];
            #pragma unroll
            for (int s = 0; s < NSPLIT; s++) z += c0[(size_t)s * PPOS * 512 + o];
            z = fmaxf(z, 0.0f);
            acc += z * w2[o];
        }
        #pragma unroll
        for (int o = 16; o; o >>= 1) acc += __shfl_xor_sync(0xffffffffu, acc, o);
        if (lane == 0) slog[q] = acc + b2[0];
    }
    __syncthreads();
    if (tid == 0) {
        float mx = -1e30f;
        for (int q = 0; q < 49; q++) mx = fmaxf(mx, slog[q]);
        float sum = 0.0f;
        for (int q = 0; q < 49; q++) { float e = expf(slog[q] - mx); sw[q] = e; sum += e; }
        float inv = 1.0f / sum;
        for (int q = 0; q < 49; q++) sw[q] *= inv;
    }
    __syncthreads();
    // faithful to torch .view(bs,49,-1) on NCHW-contiguous img: flat addressing
    const float* ib = img + (size_t)b * 100352;
    for (int c = tid; c < 2048; c += blockDim.x) {
        float acc = 0.0f;
        #pragma unroll
        for (int q = 0; q < 49; q++) acc += sw[q] * ib[q * 2048 + c];
        g_res[b * 2048 + c] = acc;
    }
}

// -------- final GEMM partials: Fp[z][b][o] = sum_{k-chunk} Yb[b,k]*W[o,k] -----
// FSPLIT=10 chunks of 1600 k each (100 iters of 16).
__global__ __launch_bounds__(256) void k_final(const float* __restrict__ W) {
    __shared__ __align__(16) float Ws[16][132];
    __shared__ __align__(16) float Ys[16][36];
    int tid = threadIdx.x;
    int o0 = blockIdx.x * 128;
    int z = blockIdx.y;
    int ty = tid >> 5, tx = tid & 31;
    float acc[4][4];
    #pragma unroll
    for (int i = 0; i < 4; i++)
        #pragma unroll
        for (int j = 0; j < 4; j++) acc[i][j] = 0.0f;

    int kq = (tid & 3) * 4;
    int orow = tid >> 2;
    int brow = tid >> 2;

    for (int it = 0; it < 100; it++) {
        int k0 = z * 1600 + it * 16;
        if (brow < 32) {
            float4 f = *(const float4*)(g_Yb + (size_t)brow * 16000 + k0 + kq);
            Ys[kq + 0][brow] = f.x; Ys[kq + 1][brow] = f.y;
            Ys[kq + 2][brow] = f.z; Ys[kq + 3][brow] = f.w;
        }
        #pragma unroll
        for (int rr = 0; rr < 2; rr++) {
            int o = o0 + orow + rr * 64;
            float4 f = (o < 3000) ? *(const float4*)(W + (size_t)o * 16000 + k0 + kq)
                                  : make_float4(0, 0, 0, 0);
            Ws[kq + 0][orow + rr * 64] = f.x; Ws[kq + 1][orow + rr * 64] = f.y;
            Ws[kq + 2][orow + rr * 64] = f.z; Ws[kq + 3][orow + rr * 64] = f.w;
        }
        __syncthreads();
        #pragma unroll
        for (int kk = 0; kk < 16; kk++) {
            float a[4], b[4];
            *(float4*)a = *(const float4*)&Ys[kk][ty * 4];
            *(float4*)b = *(const float4*)&Ws[kk][tx * 4];
            #pragma unroll
            for (int i = 0; i < 4; i++)
                #pragma unroll
                for (int j = 0; j < 4; j++) acc[i][j] += a[i] * b[j];
        }
        __syncthreads();
    }

    float* fp = g_Fpart + (size_t)z * 32 * 3000;
    #pragma unroll
    for (int i = 0; i < 4; i++) {
        int b = ty * 4 + i;
        #pragma unroll
        for (int j = 0; j < 4; j++) {
            int o = o0 + tx * 4 + j;
            if (o < 3000) fp[(size_t)b * 3000 + o] = acc[i][j];
        }
    }
}

// -------- reduce final partials + bias -> d_out ------------------------------
__global__ void k_finred(const float* __restrict__ bias, float* __restrict__ out) {
    int i = blockIdx.x * blockDim.x + threadIdx.x;
    if (i < 32 * 3000) {
        int o = i % 3000;
        float s = bias[o];
        #pragma unroll
        for (int zz = 0; zz < FSPLIT; zz++) s += g_Fpart[(size_t)zz * 32 * 3000 + i];
        out[i] = s;
    }
}

extern "C" void kernel_launch(void* const* d_in, const int* in_sizes, int n_in,
                              void* d_out, int out_size) {
    const float* txt     = (const float*)d_in[0];
    const float* img     = (const float*)d_in[1];
    const float* conv1_w = (const float*)d_in[2];
    const float* conv1_b = (const float*)d_in[3];
    const float* conv2_w = (const float*)d_in[4];
    const float* conv2_b = (const float*)d_in[5];
    const float* lin2_w  = (const float*)d_in[6];
    const float* lin2_b  = (const float*)d_in[7];
    const int* h1a = (const int*)d_in[8];
    const int* s1a = (const int*)d_in[9];
    const int* h2a = (const int*)d_in[10];
    const int* s2a = (const int*)d_in[11];
    const int* h1b = (const int*)d_in[12];
    const int* s1b = (const int*)d_in[13];
    const int* h2b = (const int*)d_in[14];
    const int* s2b = (const int*)d_in[15];
    float* out = (float*)d_out;

    const int SMEMB = (2 * N_FFT + 32) * sizeof(float);
    const int SMEMG = 2 * 4 * SMT;   // 80KB
    cudaFuncSetAttribute(k_cbp, cudaFuncAttributeMaxDynamicSharedMemorySize, SMEMB);
    cudaFuncSetAttribute(k_gemm1t, cudaFuncAttributeMaxDynamicSharedMemorySize, SMEMG);

    float* ybptr; cudaGetSymbolAddress((void**)&ybptr, g_Yb);
    float* cpptr; cudaGetSymbolAddress((void**)&cpptr, g_Cpart);
    float* tpptr; cudaGetSymbolAddress((void**)&tpptr, g_txtp);
    float* itptr; cudaGetSymbolAddress((void**)&itptr, g_imgt);
    float* rsptr; cudaGetSymbolAddress((void**)&rsptr, g_res);
    __nv_bfloat16* yhptr; cudaGetSymbolAddress((void**)&yhptr, g_Yh);
    __nv_bfloat16* ylptr; cudaGetSymbolAddress((void**)&ylptr, g_Yl);

    k_txtp<<<32, 256>>>(txt);
    dim3 gt(32, 32);
    k_imgt<<<gt, 256>>>(img);
    k_wsplit<<<(512 * N_FFT + 255) / 256, 256>>>(conv1_w);

    // CBP layer A: fused, per spatial position; writes split bf16 hi/lo
    k_cbp<<<PPOS, TCBP, SMEMB>>>(tpptr, itptr, 0, h1a, s1a, h2a, s2a,
                                 nullptr, yhptr, ylptr);

    // conv1 on tensor cores (split-K) + attention
    dim3 g1(PPAD / 128, 4, NSPLIT);
    k_gemm1t<<<g1, 256, SMEMG>>>(cpptr);
    k_attn<<<32, 256>>>(conv1_b, conv2_w, conv2_b, img);

    // CBP layer B, per batch; fp32 output
    k_cbp<<<32, TCBP, SMEMB>>>(tpptr, rsptr, 1, h1b, s1b, h2b, s2b,
                               ybptr, nullptr, nullptr);

    // final linear
    dim3 gf(24, FSPLIT);
    k_final<<<gf, 256>>>(lin2_w);
    k_finred<<<(32 * 3000 + 255) / 256, 256>>>(lin2_b, out);
}

// round 17
// speedup vs baseline: 3.7365x; 1.0647x over previous
#include <cuda_runtime.h>
#include <cuda_bf16.h>
#include <math.h>
#include <stdint.h>

#define N_FFT 16000
#define PPOS  1568
#define PPAD  1664            // 13 * 128
#define NSPLIT 6
#define KCHUNK 2688           // divisible by 32; 5*2688 + 2560 = 16000
#define FSPLIT 10
#define TCBP   1024
#define SMT    10240          // bytes per smem tile array: 128 rows * 80B

// -------- device scratch (allocation-free rule: __device__ globals) --------
__device__ float g_txtp[32 * 2048];
__device__ __align__(16) float g_imgt[(size_t)PPOS * 2048];
__device__ __align__(16) __nv_bfloat16 g_Yh[(size_t)PPAD * N_FFT];
__device__ __align__(16) __nv_bfloat16 g_Yl[(size_t)PPAD * N_FFT];
__device__ __align__(16) __nv_bfloat16 g_Wh[(size_t)512 * N_FFT];
__device__ __align__(16) __nv_bfloat16 g_Wl[(size_t)512 * N_FFT];
__device__ float g_Cpart[(size_t)NSPLIT * PPOS * 512];
__device__ float g_res[32 * 2048];
__device__ __align__(16) float g_Yb[(size_t)32 * N_FFT];
__device__ float g_Fpart[(size_t)FSPLIT * 32 * 3000];

__constant__ float W5C[5] = {1.0f, 0.30901699437494742f, -0.80901699437494745f,
                             -0.80901699437494745f, 0.30901699437494742f};
__constant__ float W5S[5] = {0.0f, 0.95105651629515353f, 0.58778525229247314f,
                             -0.58778525229247314f, -0.95105651629515353f};
// W10^k = exp(-2*pi*i*k/10) = (W10C[k], -W10S[k])
__constant__ float W10C[5] = {1.0f, 0.80901699437494745f, 0.30901699437494742f,
                              -0.30901699437494742f, -0.80901699437494745f};
__constant__ float W10S[5] = {0.0f, 0.58778525229247314f, 0.95105651629515353f,
                              0.95105651629515353f, 0.58778525229247314f};

// -------- txt avgpool (3,3) s(100,1) p(1,1) count_include_pad -> (32,2048) ----
__global__ void k_txtp(const float* __restrict__ txt) {
    int b = blockIdx.x;
    const float* base = txt + (size_t)b * 50 * 2048;
    for (int j = threadIdx.x; j < 2048; j += blockDim.x) {
        float sum = 0.0f;
        #pragma unroll
        for (int r = 0; r < 2; r++)
            #pragma unroll
            for (int dj = -1; dj <= 1; dj++) {
                int jj = j + dj;
                if (jj >= 0 && jj < 2048) sum += base[r * 2048 + jj];
            }
        g_txtp[b * 2048 + j] = sum * (1.0f / 9.0f);
    }
}

// -------- tiled transpose img NCHW -> rows (b*49+q, c), both sides coalesced -
__global__ void k_imgt(const float* __restrict__ img) {
    __shared__ float tile[64][51];   // gcd(51,32)=1 -> conflict-free
    int b = blockIdx.y;
    int c0 = blockIdx.x * 64;
    int tid = threadIdx.x;
    const float* ib = img + (size_t)b * 2048 * 49;
    for (int idx = tid; idx < 64 * 49; idx += blockDim.x) {
        int cc = idx / 49, q = idx - cc * 49;
        tile[cc][q] = ib[(size_t)(c0 + cc) * 49 + q];
    }
    __syncthreads();
    for (int idx = tid; idx < 64 * 49; idx += blockDim.x) {
        int q = idx >> 6, cc = idx & 63;
        g_imgt[(size_t)(b * 49 + q) * 2048 + c0 + cc] = tile[cc][q];
    }
}

// -------- split conv1_w into bf16 hi/lo (vectorized: float4 -> 2x bf16x2) ----
__global__ void k_wsplit(const float* __restrict__ W) {
    size_t i = ((size_t)blockIdx.x * blockDim.x + threadIdx.x) * 4;
    if (i < (size_t)512 * N_FFT) {
        float4 w = *(const float4*)(W + i);
        __nv_bfloat16 h0 = __float2bfloat16(w.x), h1 = __float2bfloat16(w.y);
        __nv_bfloat16 h2 = __float2bfloat16(w.z), h3 = __float2bfloat16(w.w);
        __nv_bfloat162* ph = (__nv_bfloat162*)(g_Wh + i);
        ph[0] = __nv_bfloat162(h0, h1);
        ph[1] = __nv_bfloat162(h2, h3);
        __nv_bfloat162* pl = (__nv_bfloat162*)(g_Wl + i);
        pl[0] = __nv_bfloat162(__float2bfloat16(w.x - __bfloat162float(h0)),
                               __float2bfloat16(w.y - __bfloat162float(h1)));
        pl[1] = __nv_bfloat162(__float2bfloat16(w.z - __bfloat162float(h2)),
                               __float2bfloat16(w.w - __bfloat162float(h3)));
    }
}

// -------- one mixed-radix stage on smem, compile-time L/R/DIR ----------------
// DIR>0: DIF forward (butterfly then twiddle), scrambled output.
// DIR<0: transposed network (conj twiddle then inverse butterfly), reverse order.
template<int L, int R, int DIR>
__device__ __forceinline__ void fft_stage_t(float* re, float* im, int tid) {
    constexpr int m = L / R;
    constexpr int nb = N_FFT / R;
    const float invL = 1.0f / (float)L;
    for (int i = tid; i < nb; i += TCBP) {
        int blk = i / m, j = i - blk * m;            // const-divisor -> IMAD
        float f = (float)j * invL;
        if (f >= 0.5f) f -= 1.0f;
        if (R == 4) {
            int base = blk * L + j;
            float c1, s1;
            __sincosf(-6.28318530717958647692f * f, &s1, &c1);
            float c2 = c1 * c1 - s1 * s1, s2 = 2.0f * c1 * s1;
            float c3 = c2 * c1 - s2 * s1, s3 = c2 * s1 + s2 * c1;
            float u0r = re[base],         u0i = im[base];
            float u1r = re[base + m],     u1i = im[base + m];
            float u2r = re[base + 2 * m], u2i = im[base + 2 * m];
            float u3r = re[base + 3 * m], u3i = im[base + 3 * m];
            if (DIR > 0) {
                float t0r = u0r + u2r, t0i = u0i + u2i;
                float t1r = u0r - u2r, t1i = u0i - u2i;
                float t2r = u1r + u3r, t2i = u1i + u3i;
                float t3r = u1r - u3r, t3i = u1i - u3i;
                re[base] = t0r + t2r;  im[base] = t0i + t2i;
                float v1r = t1r + t3i, v1i = t1i - t3r;   // t1 - i t3
                float v2r = t0r - t2r, v2i = t0i - t2i;
                float v3r = t1r - t3i, v3i = t1i + t3r;   // t1 + i t3
                re[base + m]     = v1r * c1 - v1i * s1; im[base + m]     = v1r * s1 + v1i * c1;
                re[base + 2 * m] = v2r * c2 - v2i * s2; im[base + 2 * m] = v2r * s2 + v2i * c2;
                re[base + 3 * m] = v3r * c3 - v3i * s3; im[base + 3 * m] = v3r * s3 + v3i * c3;
            } else {
                float a1r = u1r * c1 + u1i * s1, a1i = u1i * c1 - u1r * s1;
                float a2r = u2r * c2 + u2i * s2, a2i = u2i * c2 - u2r * s2;
                float a3r = u3r * c3 + u3i * s3, a3i = u3i * c3 - u3r * s3;
                float t0r = u0r + a2r, t0i = u0i + a2i;
                float t1r = u0r - a2r, t1i = u0i - a2i;
                float t2r = a1r + a3r, t2i = a1i + a3i;
                float t3r = a1r - a3r, t3i = a1i - a3i;
                re[base] = t0r + t2r;  im[base] = t0i + t2i;
                re[base + m]     = t1r - t3i; im[base + m]     = t1i + t3r;  // t1 + i t3
                re[base + 2 * m] = t0r - t2r; im[base + 2 * m] = t0i - t2i;
                re[base + 3 * m] = t1r + t3i; im[base + 3 * m] = t1i - t3r;  // t1 - i t3
            }
        } else {  // R == 5
            int base = blk * L + j;
            float w1r, w1i;
            __sincosf(-6.28318530717958647692f * f, &w1i, &w1r);
            float ur[5], ui[5];
            if (DIR > 0) {
                #pragma unroll
                for (int q = 0; q < 5; q++) { ur[q] = re[base + q * m]; ui[q] = im[base + q * m]; }
                float cwr = 1.0f, cwi = 0.0f;   // running twiddle W^{jq}
                #pragma unroll
                for (int q = 0; q < 5; q++) {
                    float vr = 0.0f, vi = 0.0f;
                    #pragma unroll
                    for (int t = 0; t < 5; t++) {
                        int e = (q * t) % 5;
                        float C = W5C[e], S = W5S[e];       // * e^{-i th}
                        vr += ur[t] * C + ui[t] * S;
                        vi += ui[t] * C - ur[t] * S;
                    }
                    re[base + q * m] = vr * cwr - vi * cwi;
                    im[base + q * m] = vr * cwi + vi * cwr;
                    float nr = cwr * w1r - cwi * w1i;
                    cwi = cwr * w1i + cwi * w1r; cwr = nr;
                }
            } else {
                float cwr = 1.0f, cwi = 0.0f;
                #pragma unroll
                for (int q = 0; q < 5; q++) {
                    float a = re[base + q * m], b2 = im[base + q * m];
                    ur[q] = a * cwr + b2 * cwi;             // * conj(W^{jq})
                    ui[q] = b2 * cwr - a * cwi;
                    float nr = cwr * w1r - cwi * w1i;
                    cwi = cwr * w1i + cwi * w1r; cwr = nr;
                }
                #pragma unroll
                for (int t = 0; t < 5; t++) {
                    float vr = 0.0f, vi = 0.0f;
                    #pragma unroll
                    for (int q = 0; q < 5; q++) {
                        int e = (q * t) % 5;
                        float C = W5C[e], S = W5S[e];       // * e^{+i th}
                        vr += ur[q] * C - ui[q] * S;
                        vi += ui[q] * C + ur[q] * S;
                    }
                    re[base + t * m] = vr; im[base + t * m] = vi;
                }
            }
        }
    }
}

// -------- fused middle: DFT10 fwd -> Z^2 -> DFT10 inv, all in registers -------
__device__ __forceinline__ void cbp_mid(float* re, float* im, int tid) {
    for (int i = tid; i < 1600; i += TCBP) {
        int base = i * 10;
        float xr[10], xi[10];
        #pragma unroll
        for (int q = 0; q < 10; q++) { xr[q] = re[base + q]; xi[q] = im[base + q]; }
        float er[5], ei[5], orr[5], oi[5];
        #pragma unroll
        for (int k = 0; k < 5; k++) {
            float a = 0.0f, b = 0.0f, c = 0.0f, d = 0.0f;
            #pragma unroll
            for (int t = 0; t < 5; t++) {
                int e = (k * t) % 5;
                float C = W5C[e], S = W5S[e];
                a += xr[2 * t] * C + xi[2 * t] * S;
                b += xi[2 * t] * C - xr[2 * t] * S;
                c += xr[2 * t + 1] * C + xi[2 * t + 1] * S;
                d += xi[2 * t + 1] * C - xr[2 * t + 1] * S;
            }
            er[k] = a; ei[k] = b; orr[k] = c; oi[k] = d;
        }
        #pragma unroll
        for (int k = 0; k < 5; k++) {
            float C = W10C[k], S = W10S[k];
            float tr = orr[k] * C + oi[k] * S;
            float ti = oi[k] * C - orr[k] * S;
            xr[k]     = er[k] + tr;  xi[k]     = ei[k] + ti;
            xr[k + 5] = er[k] - tr;  xi[k + 5] = ei[k] - ti;
        }
        #pragma unroll
        for (int q = 0; q < 10; q++) {
            float a = xr[q], b = xi[q];
            xr[q] = a * a - b * b;
            xi[q] = 2.0f * a * b;
        }
        #pragma unroll
        for (int k = 0; k < 5; k++) {
            float a = 0.0f, b = 0.0f, c = 0.0f, d = 0.0f;
            #pragma unroll
            for (int t = 0; t < 5; t++) {
                int e = (k * t) % 5;
                float C = W5C[e], S = W5S[e];
                a += xr[2 * t] * C - xi[2 * t] * S;
                b += xi[2 * t] * C + xr[2 * t] * S;
                c += xr[2 * t + 1] * C - xi[2 * t + 1] * S;
                d += xi[2 * t + 1] * C + xr[2 * t + 1] * S;
            }
            er[k] = a; ei[k] = b; orr[k] = c; oi[k] = d;
        }
        #pragma unroll
        for (int k = 0; k < 5; k++) {
            float C = W10C[k], S = W10S[k];
            float tr = orr[k] * C - oi[k] * S;
            float ti = oi[k] * C + orr[k] * S;
            re[base + k]     = er[k] + tr;  im[base + k]     = ei[k] + ti;
            re[base + k + 5] = er[k] - tr;  im[base + k + 5] = ei[k] - ti;
        }
    }
}

// -------- fused last inverse stage (L=16000, R=4): only imag outputs needed.
__device__ __forceinline__ void fft_last_fused(float* re, float* im, int tid, float& ss) {
    constexpr int m = 4000;
    const float invL = 1.0f / 16000.0f;
    const float sc0 = 0.5f / (float)N_FFT;
    for (int j = tid; j < 4000; j += TCBP) {
        float f = (float)j * invL;
        if (f >= 0.5f) f -= 1.0f;
        float c1, s1;
        __sincosf(-6.28318530717958647692f * f, &s1, &c1);
        float c2 = c1 * c1 - s1 * s1, s2 = 2.0f * c1 * s1;
        float c3 = c2 * c1 - s2 * s1, s3 = c2 * s1 + s2 * c1;
        float u0i = im[j];
        float u1r = re[j + m],     u1i = im[j + m];
        float u2r = re[j + 2 * m], u2i = im[j + 2 * m];
        float u3r = re[j + 3 * m], u3i = im[j + 3 * m];
        float a1r = u1r * c1 + u1i * s1, a1i = u1i * c1 - u1r * s1;
        float a2i = u2i * c2 - u2r * s2;
        float a3r = u3r * c3 + u3i * s3, a3i = u3i * c3 - u3r * s3;
        float t0i = u0i + a2i;
        float t1i = u0i - a2i;
        float t2i = a1i + a3i;
        float t3r = a1r - a3r;
        float v0 = (t0i + t2i) * sc0; float y0 = copysignf(sqrtf(fabsf(v0)), v0);
        float v1 = (t1i + t3r) * sc0; float y1 = copysignf(sqrtf(fabsf(v1)), v1);
        float v2 = (t0i - t2i) * sc0; float y2 = copysignf(sqrtf(fabsf(v2)), v2);
        float v3 = (t1i - t3r) * sc0; float y3 = copysignf(sqrtf(fabsf(v3)), v3);
        im[j] = y0; im[j + m] = y1; im[j + 2 * m] = y2; im[j + 3 * m] = y3;
        ss += y0 * y0 + y1 * y1 + y2 * y2 + y3 * y3;
    }
}

// -------- fused CBP: z = s1 + i*s2; FFT; Z^2; IFFT; Im/(2N); ssqrt; l2norm ---
__global__ __launch_bounds__(TCBP, 1) void k_cbp(
    const float* __restrict__ src1, const float* __restrict__ src2, int mode,
    const int* __restrict__ h1, const int* __restrict__ s1,
    const int* __restrict__ h2, const int* __restrict__ s2,
    float* __restrict__ Yout, __nv_bfloat16* __restrict__ YoutH,
    __nv_bfloat16* __restrict__ YoutL) {
    extern __shared__ float sm[];
    float* re = sm;
    float* im = sm + N_FFT;
    float* red = sm + 2 * N_FFT;
    int tid = threadIdx.x, p = blockIdx.x;
    for (int d = tid; d < N_FFT; d += TCBP) { re[d] = 0.0f; im[d] = 0.0f; }
    __syncthreads();
    if (mode == 0) {
        int b = p / 49, q = p - 49 * b;
        const float* tp = src1 + (size_t)b * 2048;
        const float* x2 = src2 + (size_t)p * 2048;
        for (int c = tid; c < 2048; c += TCBP) {
            float v = tp[(49 * c + q) & 2047];
            v = (s1[c] > 0) ? v : -v;
            atomicAdd(&re[h1[c]], v);
            float w = x2[c];
            w = (s2[c] > 0) ? w : -w;
            atomicAdd(&im[h2[c]], w);
        }
    } else {
        const float* x1 = src1 + (size_t)p * 2048;
        const float* x2 = src2 + (size_t)p * 2048;
        for (int c = tid; c < 2048; c += TCBP) {
            float v = x1[c];
            v = (s1[c] > 0) ? v : -v;
            atomicAdd(&re[h1[c]], v);
            float w = x2[c];
            w = (s2[c] > 0) ? w : -w;
            atomicAdd(&im[h2[c]], w);
        }
    }
    __syncthreads();
    fft_stage_t<16000, 4, 1>(re, im, tid); __syncthreads();
    fft_stage_t<4000, 4, 1>(re, im, tid);  __syncthreads();
    fft_stage_t<1000, 4, 1>(re, im, tid);  __syncthreads();
    fft_stage_t<250, 5, 1>(re, im, tid);   __syncthreads();
    fft_stage_t<50, 5, 1>(re, im, tid);    __syncthreads();
    cbp_mid(re, im, tid);                  __syncthreads();
    fft_stage_t<50, 5, -1>(re, im, tid);   __syncthreads();
    fft_stage_t<250, 5, -1>(re, im, tid);  __syncthreads();
    fft_stage_t<1000, 4, -1>(re, im, tid); __syncthreads();
    fft_stage_t<4000, 4, -1>(re, im, tid); __syncthreads();
    float ss = 0.0f;
    fft_last_fused(re, im, tid, ss);
    #pragma unroll
    for (int o = 16; o; o >>= 1) ss += __shfl_xor_sync(0xffffffffu, ss, o);
    if ((tid & 31) == 0) red[tid >> 5] = ss;
    __syncthreads();
    if (tid == 0) {
        float tot = 0.0f;
        for (int i = 0; i < TCBP / 32; i++) tot += red[i];
        red[0] = 1.0f / fmaxf(sqrtf(tot), 1e-12f);
    }
    __syncthreads();
    float sc = red[0];
    if (mode == 0) {
        __nv_bfloat16* yh = YoutH + (size_t)p * N_FFT;
        __nv_bfloat16* yl = YoutL + (size_t)p * N_FFT;
        for (int d = tid * 2; d < N_FFT; d += 2 * TCBP) {
            float2 v = *(const float2*)(im + d);
            float y0 = v.x * sc, y1 = v.y * sc;
            __nv_bfloat16 h0 = __float2bfloat16(y0);
            __nv_bfloat16 h1 = __float2bfloat16(y1);
            *(__nv_bfloat162*)(yh + d) = __nv_bfloat162(h0, h1);
            *(__nv_bfloat162*)(yl + d) =
                __nv_bfloat162(__float2bfloat16(y0 - __bfloat162float(h0)),
                               __float2bfloat16(y1 - __bfloat162float(h1)));
        }
    } else {
        float* yo = Yout + (size_t)p * N_FFT;
        for (int d = tid; d < N_FFT; d += TCBP) yo[d] = im[d] * sc;
    }
}

// -------- conv1 GEMM on tensor cores (mma.sync), split-bf16 ------------------
__device__ __forceinline__ void ldmx4(uint32_t* r, uint32_t a) {
    asm volatile("ldmatrix.sync.aligned.m8n8.x4.shared.b16 {%0,%1,%2,%3}, [%4];"
                 : "=r"(r[0]), "=r"(r[1]), "=r"(r[2]), "=r"(r[3]) : "r"(a));
}
__device__ __forceinline__ void ldmx2(uint32_t* r, uint32_t a) {
    asm volatile("ldmatrix.sync.aligned.m8n8.x2.shared.b16 {%0,%1}, [%2];"
                 : "=r"(r[0]), "=r"(r[1]) : "r"(a));
}
__device__ __forceinline__ void mma16816(float* d, const uint32_t* a, const uint32_t* b) {
    asm volatile("mma.sync.aligned.m16n8k16.row.col.f32.bf16.bf16.f32 "
                 "{%0,%1,%2,%3}, {%4,%5,%6,%7}, {%8,%9}, {%0,%1,%2,%3};"
                 : "+f"(d[0]), "+f"(d[1]), "+f"(d[2]), "+f"(d[3])
                 : "r"(a[0]), "r"(a[1]), "r"(a[2]), "r"(a[3]), "r"(b[0]), "r"(b[1]));
}

__global__ __launch_bounds__(256, 2) void k_gemm1t(float* __restrict__ Cp) {
    extern __shared__ __align__(16) char smraw[];   // 2 bufs * 4 arrays * SMT = 80KB
    uint32_t sbase;
    asm("{ .reg .u64 t; cvta.to.shared.u64 t, %1; cvt.u32.u64 %0, t; }"
        : "=r"(sbase) : "l"(smraw));
    int tid = threadIdx.x;
    int p0 = blockIdx.x * 128, o0 = blockIdx.y * 128;
    int kbeg = blockIdx.z * KCHUNK;
    int kend = min(16000, kbeg + KCHUNK);
    int nk = (kend - kbeg) >> 5;
    int wid = tid >> 5, lane = tid & 31;
    int wm = wid >> 2, wn = wid & 3;                // warp tile: 64x32

    auto load_stage = [&](int it, int buf) {
        int kpos = kbeg + it * 32;
        uint32_t bb = sbase + buf * (4 * SMT);
        #pragma unroll
        for (int x = 0; x < 8; x++) {
            const int arr = x >> 1;
            int idx = tid + x * 256;
            int rem = idx & 511;
            int row = rem >> 2, ch = rem & 3;
            const __nv_bfloat16* g;
            int sz = 16;
            if (arr == 0)      { g = g_Yh + (size_t)(p0 + row) * 16000;
                                 if (p0 + row >= PPOS) sz = 0; }
            else if (arr == 1) { g = g_Yl + (size_t)(p0 + row) * 16000;
                                 if (p0 + row >= PPOS) sz = 0; }
            else if (arr == 2) g = g_Wh + (size_t)(o0 + row) * 16000;
            else               g = g_Wl + (size_t)(o0 + row) * 16000;
            const void* src = (const void*)(g + kpos + ch * 8);
            uint32_t dst = bb + arr * SMT + row * 80 + ch * 16;
            asm volatile("cp.async.cg.shared.global [%0], [%1], 16, %2;"
                         :: "r"(dst), "l"(src), "r"(sz));
        }
        asm volatile("cp.async.commit_group;");
    };

    float acc[4][4][4];
    #pragma unroll
    for (int i = 0; i < 4; i++)
        #pragma unroll
        for (int j = 0; j < 4; j++)
            #pragma unroll
            for (int k = 0; k < 4; k++) acc[i][j][k] = 0.0f;

    load_stage(0, 0);
    for (int it = 0; it < nk; it++) {
        bool more = (it + 1) < nk;
        if (more) {
            load_stage(it + 1, (it + 1) & 1);
            asm volatile("cp.async.wait_group 1;" ::: "memory");
        } else {
            asm volatile("cp.async.wait_group 0;" ::: "memory");
        }
        __syncthreads();
        uint32_t bb = sbase + (it & 1) * (4 * SMT);
        #pragma unroll
        for (int kk = 0; kk < 2; kk++) {
            uint32_t bh[4][2], bl[4][2];
            uint32_t chB = kk * 2 + ((lane >> 3) & 1);
            #pragma unroll
            for (int nt = 0; nt < 4; nt++) {
                uint32_t r = wn * 32 + nt * 8 + (lane & 7);
                ldmx2(bh[nt], bb + 2 * SMT + r * 80 + chB * 16);
                ldmx2(bl[nt], bb + 3 * SMT + r * 80 + chB * 16);
            }
            uint32_t chA = kk * 2 + (lane >> 4);
            #pragma unroll
            for (int mt = 0; mt < 4; mt++) {
                uint32_t ah[4], al[4];
                uint32_t r = wm * 64 + mt * 16 + (lane & 15);
                ldmx4(ah, bb + 0 * SMT + r * 80 + chA * 16);
                ldmx4(al, bb + 1 * SMT + r * 80 + chA * 16);
                #pragma unroll
                for (int nt = 0; nt < 4; nt++) {
                    mma16816(acc[mt][nt], ah, bh[nt]);
                    mma16816(acc[mt][nt], ah, bl[nt]);
                    mma16816(acc[mt][nt], al, bh[nt]);
                }
            }
        }
        __syncthreads();
    }

    float* cp = Cp + (size_t)blockIdx.z * PPOS * 512;
    int tq = lane >> 2, t2 = (lane & 3) * 2;
    #pragma unroll
    for (int mt = 0; mt < 4; mt++)
        #pragma unroll
        for (int nt = 0; nt < 4; nt++) {
            int o = o0 + wn * 32 + nt * 8 + t2;
            int pA = p0 + wm * 64 + mt * 16 + tq;
            if (pA < PPOS) {
                float* d = cp + (size_t)pA * 512 + o;
                d[0] = acc[mt][nt][0]; d[1] = acc[mt][nt][1];
            }
            int pB = pA + 8;
            if (pB < PPOS) {
                float* d = cp + (size_t)pB * 512 + o;
                d[0] = acc[mt][nt][2]; d[1] = acc[mt][nt][3];
            }
        }
}

// -------- attention: sum partials + bias + relu, conv2, softmax(49), pooling -
__global__ void k_attn(const float* __restrict__ b1, const float* __restrict__ w2,
                       const float* __restrict__ b2, const float* __restrict__ img) {
    __shared__ float slog[49];
    __shared__ float sw[49];
    int b = blockIdx.x, tid = threadIdx.x;
    int warp = tid >> 5, lane = tid & 31;
    for (int q = warp; q < 49; q += 8) {
        float acc = 0.0f;
        const float* c0 = g_Cpart + (size_t)(b * 49 + q) * 512;
        for (int o = lane; o < 512; o += 32) {
            float z = b1[o];
            #pragma unroll
            for (int s = 0; s < NSPLIT; s++) z += c0[(size_t)s * PPOS * 512 + o];
            z = fmaxf(z, 0.0f);
            acc += z * w2[o];
        }
        #pragma unroll
        for (int o = 16; o; o >>= 1) acc += __shfl_xor_sync(0xffffffffu, acc, o);
        if (lane == 0) slog[q] = acc + b2[0];
    }
    __syncthreads();
    if (tid == 0) {
        float mx = -1e30f;
        for (int q = 0; q < 49; q++) mx = fmaxf(mx, slog[q]);
        float sum = 0.0f;
        for (int q = 0; q < 49; q++) { float e = expf(slog[q] - mx); sw[q] = e; sum += e; }
        float inv = 1.0f / sum;
        for (int q = 0; q < 49; q++) sw[q] *= inv;
    }
    __syncthreads();
    // faithful to torch .view(bs,49,-1) on NCHW-contiguous img: flat addressing
    const float* ib = img + (size_t)b * 100352;
    for (int c = tid; c < 2048; c += blockDim.x) {
        float acc = 0.0f;
        #pragma unroll
        for (int q = 0; q < 49; q++) acc += sw[q] * ib[q * 2048 + c];
        g_res[b * 2048 + c] = acc;
    }
}

// -------- final GEMM partials, register-prefetch double-buffered -------------
// Fp[z][b][o] = sum_{k in chunk z} Yb[b,k]*W[o,k]; FSPLIT=10 chunks of 1600,
// 50 iterations of 32 k each.
__global__ __launch_bounds__(256) void k_final(const float* __restrict__ W) {
    __shared__ __align__(16) float Ws[2][32][132];
    __shared__ __align__(16) float Ys[2][32][36];
    int tid = threadIdx.x;
    int o0 = blockIdx.x * 128;
    int z = blockIdx.y;
    int ty = tid >> 5, tx = tid & 31;
    float acc[4][4];
    #pragma unroll
    for (int i = 0; i < 4; i++)
        #pragma unroll
        for (int j = 0; j < 4; j++) acc[i][j] = 0.0f;

    // loader mapping: W rows one-per-thread (tid&127), k-half by tid>>7;
    // Y: b = tid&31, k quad by tid>>5.
    int lo_row = tid & 127;
    int lo_k = (tid >> 7) * 16;        // 0 or 16
    int ly_b = tid & 31;
    int ly_k = (tid >> 5) * 4;         // 0..28
    int oW = o0 + lo_row;
    const float* wrow = W + (size_t)oW * 16000;
    const float* yrow = g_Yb + (size_t)ly_b * 16000;
    bool wok = (oW < 3000);

    float4 pw[4], py;
    auto ldg = [&](int it) {
        int k0 = z * 1600 + it * 32;
        #pragma unroll
        for (int i = 0; i < 4; i++)
            pw[i] = wok ? *(const float4*)(wrow + k0 + lo_k + i * 4)
                        : make_float4(0, 0, 0, 0);
        py = *(const float4*)(yrow + k0 + ly_k);
    };
    auto sts = [&](int buf) {
        #pragma unroll
        for (int i = 0; i < 4; i++) {
            int kr = lo_k + i * 4;
            Ws[buf][kr + 0][lo_row] = pw[i].x;
            Ws[buf][kr + 1][lo_row] = pw[i].y;
            Ws[buf][kr + 2][lo_row] = pw[i].z;
            Ws[buf][kr + 3][lo_row] = pw[i].w;
        }
        Ys[buf][ly_k + 0][ly_b] = py.x;
        Ys[buf][ly_k + 1][ly_b] = py.y;
        Ys[buf][ly_k + 2][ly_b] = py.z;
        Ys[buf][ly_k + 3][ly_b] = py.w;
    };

    ldg(0); sts(0);
    __syncthreads();
    for (int it = 0; it < 50; it++) {
        int cur = it & 1;
        bool more = (it + 1) < 50;
        if (more) ldg(it + 1);
        #pragma unroll
        for (int kk = 0; kk < 32; kk++) {
            float a[4], b[4];
            *(float4*)a = *(const float4*)&Ys[cur][kk][ty * 4];
            *(float4*)b = *(const float4*)&Ws[cur][kk][tx * 4];
            #pragma unroll
            for (int i = 0; i < 4; i++)
                #pragma unroll
                for (int j = 0; j < 4; j++) acc[i][j] += a[i] * b[j];
        }
        if (more) sts(cur ^ 1);
        __syncthreads();
    }

    float* fp = g_Fpart + (size_t)z * 32 * 3000;
    #pragma unroll
    for (int i = 0; i < 4; i++) {
        int b = ty * 4 + i;
        #pragma unroll
        for (int j = 0; j < 4; j++) {
            int o = o0 + tx * 4 + j;
            if (o < 3000) fp[(size_t)b * 3000 + o] = acc[i][j];
        }
    }
}

// -------- reduce final partials + bias -> d_out ------------------------------
__global__ void k_finred(const float* __restrict__ bias, float* __restrict__ out) {
    int i = blockIdx.x * blockDim.x + threadIdx.x;
    if (i < 32 * 3000) {
        int o = i % 3000;
        float s = bias[o];
        #pragma unroll
        for (int zz = 0; zz < FSPLIT; zz++) s += g_Fpart[(size_t)zz * 32 * 3000 + i];
        out[i] = s;
    }
}

extern "C" void kernel_launch(void* const* d_in, const int* in_sizes, int n_in,
                              void* d_out, int out_size) {
    const float* txt     = (const float*)d_in[0];
    const float* img     = (const float*)d_in[1];
    const float* conv1_w = (const float*)d_in[2];
    const float* conv1_b = (const float*)d_in[3];
    const float* conv2_w = (const float*)d_in[4];
    const float* conv2_b = (const float*)d_in[5];
    const float* lin2_w  = (const float*)d_in[6];
    const float* lin2_b  = (const float*)d_in[7];
    const int* h1a = (const int*)d_in[8];
    const int* s1a = (const int*)d_in[9];
    const int* h2a = (const int*)d_in[10];
    const int* s2a = (const int*)d_in[11];
    const int* h1b = (const int*)d_in[12];
    const int* s1b = (const int*)d_in[13];
    const int* h2b = (const int*)d_in[14];
    const int* s2b = (const int*)d_in[15];
    float* out = (float*)d_out;

    const int SMEMB = (2 * N_FFT + 32) * sizeof(float);
    const int SMEMG = 2 * 4 * SMT;   // 80KB
    cudaFuncSetAttribute(k_cbp, cudaFuncAttributeMaxDynamicSharedMemorySize, SMEMB);
    cudaFuncSetAttribute(k_gemm1t, cudaFuncAttributeMaxDynamicSharedMemorySize, SMEMG);

    float* ybptr; cudaGetSymbolAddress((void**)&ybptr, g_Yb);
    float* cpptr; cudaGetSymbolAddress((void**)&cpptr, g_Cpart);
    float* tpptr; cudaGetSymbolAddress((void**)&tpptr, g_txtp);
    float* itptr; cudaGetSymbolAddress((void**)&itptr, g_imgt);
    float* rsptr; cudaGetSymbolAddress((void**)&rsptr, g_res);
    __nv_bfloat16* yhptr; cudaGetSymbolAddress((void**)&yhptr, g_Yh);
    __nv_bfloat16* ylptr; cudaGetSymbolAddress((void**)&ylptr, g_Yl);

    k_txtp<<<32, 256>>>(txt);
    dim3 gt(32, 32);
    k_imgt<<<gt, 256>>>(img);
    k_wsplit<<<(512 * N_FFT / 4 + 255) / 256, 256>>>(conv1_w);

    // CBP layer A: fused, per spatial position; writes split bf16 hi/lo
    k_cbp<<<PPOS, TCBP, SMEMB>>>(tpptr, itptr, 0, h1a, s1a, h2a, s2a,
                                 nullptr, yhptr, ylptr);

    // conv1 on tensor cores (split-K) + attention
    dim3 g1(PPAD / 128, 4, NSPLIT);
    k_gemm1t<<<g1, 256, SMEMG>>>(cpptr);
    k_attn<<<32, 256>>>(conv1_b, conv2_w, conv2_b, img);

    // CBP layer B, per batch; fp32 output
    k_cbp<<<32, TCBP, SMEMB>>>(tpptr, rsptr, 1, h1b, s1b, h2b, s2b,
                               ybptr, nullptr, nullptr);

    // final linear
    dim3 gf(24, FSPLIT);
    k_final<<<gf, 256>>>(lin2_w);
    k_finred<<<(32 * 3000 + 255) / 256, 256>>>(lin2_b, out);
}